// round 3
// baseline (speedup 1.0000x reference)
#include <cuda_runtime.h>

// Problem constants
#define NN   8192
#define DD   512
#define NCLS 10
#define REG_E 0.05f
#define NIT  20

static constexpr size_t NN2 = (size_t)NN * (size_t)NN;

// ---------------- scratch (device globals; no allocation) ----------------
static __device__ float g_C[NN2];           // 256 MiB: CX -> C
static __device__ float g_P[NN2];           // 256 MiB: exp(-C/(reg*cmax))
static __device__ float g_xp2[NN], g_xq2[NN], g_yp2[NN], g_yq2[NN];
static __device__ float g_z[NN], g_w[NN];
static __device__ float g_part[128 * NN];   // column-pass partials (4 MB)
static __device__ float g_bpart[4096];      // final reduction partials
static __device__ unsigned g_max_cx, g_max_cy, g_max_c;

// ---------------- helpers ----------------
__device__ __forceinline__ float blockReduceSum(float v) {
    __shared__ float red[32];
    unsigned lane = threadIdx.x & 31u, wid = threadIdx.x >> 5;
#pragma unroll
    for (int o = 16; o > 0; o >>= 1) v += __shfl_down_sync(0xffffffffu, v, o);
    if (lane == 0) red[wid] = v;
    __syncthreads();
    int nw = (blockDim.x + 31) >> 5;
    v = (threadIdx.x < (unsigned)nw) ? red[threadIdx.x] : 0.f;
    if (wid == 0) {
#pragma unroll
        for (int o = 16; o > 0; o >>= 1) v += __shfl_down_sync(0xffffffffu, v, o);
    }
    return v;  // valid in thread 0
}

__device__ __forceinline__ double blockReduceSumD(double v) {
    __shared__ double redd[32];
    unsigned lane = threadIdx.x & 31u, wid = threadIdx.x >> 5;
#pragma unroll
    for (int o = 16; o > 0; o >>= 1) v += __shfl_down_sync(0xffffffffu, v, o);
    if (lane == 0) redd[wid] = v;
    __syncthreads();
    int nw = (blockDim.x + 31) >> 5;
    v = (threadIdx.x < (unsigned)nw) ? redd[threadIdx.x] : 0.0;
    if (wid == 0) {
#pragma unroll
        for (int o = 16; o > 0; o >>= 1) v += __shfl_down_sync(0xffffffffu, v, o);
    }
    return v;
}

// fast exp2 for y in [-30, 0]; FMA-only (no MUFU). rel err ~1e-7.
__device__ __forceinline__ float fexp2(float y) {
    float fk = y + 12582912.0f;                 // round-to-nearest integer
    int   k  = __float_as_int(fk) - 0x4B400000; // extract k (negative ok)
    float r  = y - (fk - 12582912.0f);          // r in [-0.5, 0.5], exact
    float p  = 1.5403530e-4f;                   // ln2^6/720
    p = fmaf(p, r, 1.3333558e-3f);
    p = fmaf(p, r, 9.6181291e-3f);
    p = fmaf(p, r, 5.5504109e-2f);
    p = fmaf(p, r, 2.4022651e-1f);
    p = fmaf(p, r, 6.9314718e-1f);
    p = fmaf(p, r, 1.0f);
    return p * __int_as_float((k + 127) << 23);
}

// ---------------- kernels ----------------
__global__ void k_init() {
    int t = blockIdx.x * blockDim.x + threadIdx.x;
    if (t == 0) { g_max_cx = 0u; g_max_cy = 0u; g_max_c = 0u; }
    if (t < NN) g_w[t] = 1.0f;
}

__global__ void k_norm512(const float* __restrict__ X, int which) {
    int i = blockIdx.x;
    float4 v = reinterpret_cast<const float4*>(X)[(size_t)i * (DD / 4) + threadIdx.x];
    float s = v.x * v.x + v.y * v.y + v.z * v.z + v.w * v.w;
    s = blockReduceSum(s);
    if (threadIdx.x == 0) (which ? g_xq2 : g_xp2)[i] = s;
}

__global__ void k_norm10(const float* __restrict__ Y, int which) {
    int i = blockIdx.x * blockDim.x + threadIdx.x;
    if (i < NN) {
        float s = 0.f;
#pragma unroll
        for (int c = 0; c < NCLS; c++) { float t = Y[(size_t)i * NCLS + c]; s += t * t; }
        (which ? g_yq2 : g_yp2)[i] = s;
    }
}

#define BM 128
#define BN 128
#define BK 16

// CX = relu(xp2 + xq2 - 2*XP@XQ^T) -> g_C; track max(CX) and max(CY).
__global__ void __launch_bounds__(256) k_gemm(const float* __restrict__ XP, const float* __restrict__ XQ,
                                              const float* __restrict__ YP, const float* __restrict__ YQ) {
    __shared__ float As2[BK][2 * BM];   // A duplicated: As2[k][2m]=As2[k][2m+1]=A[m]
    __shared__ float Bs[BK][BN];
    __shared__ float YPs[BM][NCLS];
    __shared__ float YQs[BN][NCLS];

    const int tid = threadIdx.x;
    const int tx = tid & 15;
    const int ty = tid >> 4;
    const int row0 = blockIdx.y * BM;
    const int col0 = blockIdx.x * BN;

    for (int idx = tid; idx < BM * NCLS; idx += 256) {
        int r = idx / NCLS, c = idx - r * NCLS;
        YPs[r][c] = YP[(size_t)(row0 + r) * NCLS + c];
        YQs[r][c] = YQ[(size_t)(col0 + r) * NCLS + c];
    }

    unsigned long long acc[8][4];
#pragma unroll
    for (int i = 0; i < 8; i++)
#pragma unroll
        for (int j = 0; j < 4; j++) acc[i][j] = 0ull;

    for (int k0 = 0; k0 < DD; k0 += BK) {
#pragma unroll
        for (int l = 0; l < 2; l++) {
            int idx = tid + l * 256;
            int r = idx >> 2;
            int kq = (idx & 3) << 2;
            float4 va = *reinterpret_cast<const float4*>(XP + (size_t)(row0 + r) * DD + k0 + kq);
            As2[kq + 0][2 * r] = va.x; As2[kq + 0][2 * r + 1] = va.x;
            As2[kq + 1][2 * r] = va.y; As2[kq + 1][2 * r + 1] = va.y;
            As2[kq + 2][2 * r] = va.z; As2[kq + 2][2 * r + 1] = va.z;
            As2[kq + 3][2 * r] = va.w; As2[kq + 3][2 * r + 1] = va.w;
            float4 vb = *reinterpret_cast<const float4*>(XQ + (size_t)(col0 + r) * DD + k0 + kq);
            Bs[kq + 0][r] = vb.x; Bs[kq + 1][r] = vb.y; Bs[kq + 2][r] = vb.z; Bs[kq + 3][r] = vb.w;
        }
        __syncthreads();
#pragma unroll
        for (int kk = 0; kk < BK; kk++) {
            unsigned long long a2[8], b2[4];
#pragma unroll
            for (int s = 0; s < 4; s++) {
                float4 v = *reinterpret_cast<const float4*>(&As2[kk][16 * ty + 4 * s]);
                asm("mov.b64 %0, {%1,%2};" : "=l"(a2[2 * s])     : "f"(v.x), "f"(v.y));
                asm("mov.b64 %0, {%1,%2};" : "=l"(a2[2 * s + 1]) : "f"(v.z), "f"(v.w));
            }
#pragma unroll
            for (int s = 0; s < 2; s++) {
                float4 v = *reinterpret_cast<const float4*>(&Bs[kk][8 * tx + 4 * s]);
                asm("mov.b64 %0, {%1,%2};" : "=l"(b2[2 * s])     : "f"(v.x), "f"(v.y));
                asm("mov.b64 %0, {%1,%2};" : "=l"(b2[2 * s + 1]) : "f"(v.z), "f"(v.w));
            }
#pragma unroll
            for (int i = 0; i < 8; i++)
#pragma unroll
                for (int j = 0; j < 4; j++)
                    asm("fma.rn.f32x2 %0, %1, %2, %0;" : "+l"(acc[i][j]) : "l"(a2[i]), "l"(b2[j]));
        }
        __syncthreads();
    }

    float maxcx = 0.f, maxcy = 0.f;
#pragma unroll
    for (int i = 0; i < 8; i++) {
        int gi = row0 + ty * 8 + i;
        float xp2i = g_xp2[gi];
        float yp2i = g_yp2[gi];
        float outv[8];
#pragma unroll
        for (int j2 = 0; j2 < 4; j2++) {
            float lo, hi;
            asm("mov.b64 {%0,%1}, %2;" : "=f"(lo), "=f"(hi) : "l"(acc[i][j2]));
            int gj0 = col0 + tx * 8 + 2 * j2;
            float cx0 = fmaxf(xp2i + g_xq2[gj0]     - 2.f * lo, 0.f);
            float cx1 = fmaxf(xp2i + g_xq2[gj0 + 1] - 2.f * hi, 0.f);
            outv[2 * j2] = cx0; outv[2 * j2 + 1] = cx1;
            maxcx = fmaxf(maxcx, fmaxf(cx0, cx1));
        }
        float4* dst = reinterpret_cast<float4*>(g_C + (size_t)gi * NN + col0 + tx * 8);
        dst[0] = make_float4(outv[0], outv[1], outv[2], outv[3]);
        dst[1] = make_float4(outv[4], outv[5], outv[6], outv[7]);
#pragma unroll
        for (int j = 0; j < 8; j++) {
            int lj = tx * 8 + j;
            float dot = 0.f;
#pragma unroll
            for (int c = 0; c < NCLS; c++) dot = fmaf(YPs[ty * 8 + i][c], YQs[lj][c], dot);
            float cy = fmaxf(yp2i + g_yq2[col0 + lj] - 2.f * dot, 0.f);
            maxcy = fmaxf(maxcy, cy);
        }
    }
#pragma unroll
    for (int o = 16; o > 0; o >>= 1) {
        maxcx = fmaxf(maxcx, __shfl_xor_sync(0xffffffffu, maxcx, o));
        maxcy = fmaxf(maxcy, __shfl_xor_sync(0xffffffffu, maxcy, o));
    }
    if ((tid & 31) == 0) {
        atomicMax(&g_max_cx, __float_as_uint(maxcx));   // values >= 0: uint compare == float compare
        atomicMax(&g_max_cy, __float_as_uint(maxcy));
    }
}

// C = CX + w*CY (CY recomputed, K=10); track max(C).
__global__ void __launch_bounds__(256) k_combine(const float* __restrict__ YP, const float* __restrict__ YQ) {
    __shared__ float YPs[8][NCLS];
    __shared__ float yp2s[8];
    int i0 = blockIdx.x * 8;
    int tid = threadIdx.x;
    if (tid < 8 * NCLS) { int r = tid / NCLS, c = tid - r * NCLS; YPs[r][c] = YP[(size_t)(i0 + r) * NCLS + c]; }
    if (tid < 8) yp2s[tid] = g_yp2[i0 + tid];
    __syncthreads();
    float cxm = __uint_as_float(g_max_cx);
    float cym = __uint_as_float(g_max_cy);
    float lw = (cym == 0.f) ? 0.f : cxm / cym;
    float localmax = 0.f;
    for (int j = tid; j < NN; j += 256) {
        float yq[NCLS];
#pragma unroll
        for (int c = 0; c < NCLS; c++) yq[c] = __ldg(&YQ[(size_t)j * NCLS + c]);
        float yq2j = g_yq2[j];
#pragma unroll
        for (int r = 0; r < 8; r++) {
            float dot = 0.f;
#pragma unroll
            for (int c = 0; c < NCLS; c++) dot = fmaf(YPs[r][c], yq[c], dot);
            float cy = fmaxf(yp2s[r] + yq2j - 2.f * dot, 0.f);
            size_t idx = (size_t)(i0 + r) * NN + j;
            float cv = g_C[idx] + lw * cy;
            g_C[idx] = cv;
            localmax = fmaxf(localmax, cv);
        }
    }
#pragma unroll
    for (int o = 16; o > 0; o >>= 1)
        localmax = fmaxf(localmax, __shfl_xor_sync(0xffffffffu, localmax, o));
    if ((tid & 31) == 0) atomicMax(&g_max_c, __float_as_uint(localmax));
}

// P = exp(-C/(reg*cmax))   (FMA-only exp2)
__global__ void __launch_bounds__(256) k_exp() {
    float cmax = __uint_as_float(g_max_c);
    float s = 1.4426950408889634f / (REG_E * cmax);   // log2(e)/(reg*cmax)
    const float4* C4 = reinterpret_cast<const float4*>(g_C);
    float4* P4 = reinterpret_cast<float4*>(g_P);
    size_t n4 = NN2 / 4;
    for (size_t idx = (size_t)blockIdx.x * blockDim.x + threadIdx.x; idx < n4;
         idx += (size_t)gridDim.x * blockDim.x) {
        float4 c = C4[idx];
        float4 p;
        p.x = fexp2(-c.x * s);
        p.y = fexp2(-c.y * s);
        p.z = fexp2(-c.z * s);
        p.w = fexp2(-c.w * s);
        P4[idx] = p;
    }
}

// z = (1/N) / (P @ w)   -- one block per row
__global__ void __launch_bounds__(256) k_row() {
    int i = blockIdx.x;
    const float4* Pr = reinterpret_cast<const float4*>(g_P + (size_t)i * NN);
    const float4* W4 = reinterpret_cast<const float4*>(g_w);
    float s0 = 0.f, s1 = 0.f;
#pragma unroll
    for (int it = 0; it < 8; it += 2) {
        int t0 = threadIdx.x + it * 256;
        int t1 = t0 + 256;
        float4 p0 = Pr[t0], w0 = W4[t0];
        float4 p1 = Pr[t1], w1 = W4[t1];
        s0 += p0.x * w0.x + p0.y * w0.y + p0.z * w0.z + p0.w * w0.w;
        s1 += p1.x * w1.x + p1.y * w1.y + p1.z * w1.z + p1.w * w1.w;
    }
    float s = blockReduceSum(s0 + s1);
    if (threadIdx.x == 0) g_z[i] = (1.0f / NN) / s;
}

// partial column sums of P^T @ z : grid (8, 128)
__global__ void __launch_bounds__(256) k_colpart() {
    int c4 = blockIdx.x * 256 + threadIdx.x;   // float4 column index (0..2047)
    int r0 = blockIdx.y * 64;
    const float4* P4 = reinterpret_cast<const float4*>(g_P);
    float ax = 0.f, ay = 0.f, az = 0.f, aw = 0.f;
#pragma unroll 4
    for (int r = 0; r < 64; r++) {
        float zz = g_z[r0 + r];
        float4 p = P4[(size_t)(r0 + r) * (NN / 4) + c4];
        ax = fmaf(p.x, zz, ax);
        ay = fmaf(p.y, zz, ay);
        az = fmaf(p.z, zz, az);
        aw = fmaf(p.w, zz, aw);
    }
    reinterpret_cast<float4*>(g_part)[(size_t)blockIdx.y * (NN / 4) + c4] = make_float4(ax, ay, az, aw);
}

// w = (1/M) / colsum  -- deterministic chunk-ordered reduce
__global__ void __launch_bounds__(256) k_colred() {
    int c4 = blockIdx.x * 256 + threadIdx.x;   // grid 8
    const float4* G = reinterpret_cast<const float4*>(g_part);
    float ax = 0.f, ay = 0.f, az = 0.f, aw = 0.f;
    for (int ch = 0; ch < 128; ch++) {
        float4 p = G[(size_t)ch * (NN / 4) + c4];
        ax += p.x; ay += p.y; az += p.z; aw += p.w;
    }
    float4 w;
    w.x = (1.0f / NN) / ax;
    w.y = (1.0f / NN) / ay;
    w.z = (1.0f / NN) / az;
    w.w = (1.0f / NN) / aw;
    reinterpret_cast<float4*>(g_w)[c4] = w;
}

// sum_ij C_ij * P_ij * z_i * w_j  -> block partials
__global__ void __launch_bounds__(256) k_final() {
    const float4* C4 = reinterpret_cast<const float4*>(g_C);
    const float4* P4 = reinterpret_cast<const float4*>(g_P);
    const float4* W4 = reinterpret_cast<const float4*>(g_w);
    float acc = 0.f;
    size_t base = (size_t)blockIdx.x * 4096;   // 4096 blocks x 4096 float4
#pragma unroll 4
    for (int it = 0; it < 16; it++) {
        size_t idx = base + (size_t)it * 256 + threadIdx.x;
        int i = (int)(idx >> 11);               // 2048 float4 per row
        int j4 = (int)(idx & 2047);
        float4 c = C4[idx];
        float4 p = P4[idx];
        float4 w = W4[j4];
        float zi = g_z[i];
        acc += zi * (c.x * p.x * w.x + c.y * p.y * w.y + c.z * p.z * w.z + c.w * p.w * w.w);
    }
    acc = blockReduceSum(acc);
    if (threadIdx.x == 0) g_bpart[blockIdx.x] = acc;
}

__global__ void __launch_bounds__(256) k_finalred(float* out) {
    double s = 0.0;
    for (int t = threadIdx.x; t < 4096; t += 256) s += (double)g_bpart[t];
    s = blockReduceSumD(s);
    if (threadIdx.x == 0) out[0] = (float)s;
}

// ---------------- launch ----------------
extern "C" void kernel_launch(void* const* d_in, const int* in_sizes, int n_in,
                              void* d_out, int out_size) {
    const float* XQ = (const float*)d_in[0];   // (8192, 512)
    const float* YQ = (const float*)d_in[1];   // (8192, 10)
    const float* XP = (const float*)d_in[2];   // (8192, 512)
    const float* YP = (const float*)d_in[3];   // (8192, 10)
    float* out = (float*)d_out;

    k_init<<<32, 256>>>();
    k_norm512<<<NN, 128>>>(XP, 0);
    k_norm512<<<NN, 128>>>(XQ, 1);
    k_norm10<<<NN / 256, 256>>>(YP, 0);
    k_norm10<<<NN / 256, 256>>>(YQ, 1);

    k_gemm<<<dim3(NN / BN, NN / BM), 256>>>(XP, XQ, YP, YQ);
    k_combine<<<NN / 8, 256>>>(YP, YQ);
    k_exp<<<4096, 256>>>();

    for (int it = 0; it < NIT; it++) {
        k_row<<<NN, 256>>>();
        k_colpart<<<dim3(8, 128), 256>>>();
        k_colred<<<8, 256>>>();
    }

    k_final<<<4096, 256>>>();
    k_finalred<<<1, 256>>>(out);
}

// round 4
// speedup vs baseline: 1.1190x; 1.1190x over previous
#include <cuda_runtime.h>
#include <cuda_fp16.h>

// Problem constants
#define NN   8192
#define DD   512
#define NCLS 10
#define REG_E 0.05f
#define NIT  20
#define SHIFT 15.0f          // exp2 shift for fp16 P storage
#define SHIFT_MUL 32768.0f   // 2^15

static constexpr size_t NN2 = (size_t)NN * (size_t)NN;

// ---------------- scratch (device globals; no allocation) ----------------
static __device__ float  g_C[NN2];            // 256 MiB: CX only
static __device__ __half g_Ph[NN2];           // 128 MiB: P' = 2^15 * exp(-C/(reg*cmax))
static __device__ float g_xp2[NN], g_xq2[NN], g_yp2[NN], g_yq2[NN];
static __device__ float g_z[NN], g_w[NN];
static __device__ float g_part[128 * NN];     // column-pass partials (4 MB)
static __device__ float g_bpart[512];         // final reduction partials
static __device__ unsigned g_max_cx, g_max_cy, g_max_c;

// ---------------- helpers ----------------
__device__ __forceinline__ float blockReduceSum(float v) {
    __shared__ float red[32];
    unsigned lane = threadIdx.x & 31u, wid = threadIdx.x >> 5;
#pragma unroll
    for (int o = 16; o > 0; o >>= 1) v += __shfl_down_sync(0xffffffffu, v, o);
    if (lane == 0) red[wid] = v;
    __syncthreads();
    int nw = (blockDim.x + 31) >> 5;
    v = (threadIdx.x < (unsigned)nw) ? red[threadIdx.x] : 0.f;
    if (wid == 0) {
#pragma unroll
        for (int o = 16; o > 0; o >>= 1) v += __shfl_down_sync(0xffffffffu, v, o);
    }
    return v;  // valid in thread 0
}

__device__ __forceinline__ double blockReduceSumD(double v) {
    __shared__ double redd[32];
    unsigned lane = threadIdx.x & 31u, wid = threadIdx.x >> 5;
#pragma unroll
    for (int o = 16; o > 0; o >>= 1) v += __shfl_down_sync(0xffffffffu, v, o);
    if (lane == 0) redd[wid] = v;
    __syncthreads();
    int nw = (blockDim.x + 31) >> 5;
    v = (threadIdx.x < (unsigned)nw) ? redd[threadIdx.x] : 0.0;
    if (wid == 0) {
#pragma unroll
        for (int o = 16; o > 0; o >>= 1) v += __shfl_down_sync(0xffffffffu, v, o);
    }
    return v;
}

// fast exp2 for y in [-30, 16]; FMA-only (no MUFU). rel err ~1e-7.
__device__ __forceinline__ float fexp2(float y) {
    float fk = y + 12582912.0f;                 // round-to-nearest integer
    int   k  = __float_as_int(fk) - 0x4B400000; // extract k (negative ok)
    float r  = y - (fk - 12582912.0f);          // r in [-0.5, 0.5], exact
    float p  = 1.5403530e-4f;
    p = fmaf(p, r, 1.3333558e-3f);
    p = fmaf(p, r, 9.6181291e-3f);
    p = fmaf(p, r, 5.5504109e-2f);
    p = fmaf(p, r, 2.4022651e-1f);
    p = fmaf(p, r, 6.9314718e-1f);
    p = fmaf(p, r, 1.0f);
    return p * __int_as_float((k + 127) << 23);
}

// ---------------- kernels ----------------
__global__ void k_init() {
    int t = blockIdx.x * blockDim.x + threadIdx.x;
    if (t == 0) { g_max_cx = 0u; g_max_cy = 0u; g_max_c = 0u; }
    if (t < NN) g_w[t] = 1.0f;
}

// grid (NN, 2): y=0 -> XP->g_xp2, y=1 -> XQ->g_xq2
__global__ void k_norm512(const float* __restrict__ XP, const float* __restrict__ XQ) {
    int i = blockIdx.x;
    const float* X = blockIdx.y ? XQ : XP;
    float4 v = reinterpret_cast<const float4*>(X)[(size_t)i * (DD / 4) + threadIdx.x];
    float s = v.x * v.x + v.y * v.y + v.z * v.z + v.w * v.w;
    s = blockReduceSum(s);
    if (threadIdx.x == 0) (blockIdx.y ? g_xq2 : g_xp2)[i] = s;
}

__global__ void k_norm10(const float* __restrict__ YP, const float* __restrict__ YQ) {
    int i = blockIdx.x * blockDim.x + threadIdx.x;
    if (i < NN) {
        float sp = 0.f, sq = 0.f;
#pragma unroll
        for (int c = 0; c < NCLS; c++) {
            float tp = YP[(size_t)i * NCLS + c];
            float tq = YQ[(size_t)i * NCLS + c];
            sp += tp * tp; sq += tq * tq;
        }
        g_yp2[i] = sp; g_yq2[i] = sq;
    }
}

#define BM 128
#define BN 128
#define BK 16

// CX = relu(xp2 + xq2 - 2*XP@XQ^T) -> g_C; track max(CX) and max(CY).
__global__ void __launch_bounds__(256) k_gemm(const float* __restrict__ XP, const float* __restrict__ XQ,
                                              const float* __restrict__ YP, const float* __restrict__ YQ) {
    __shared__ float As2[BK][2 * BM];   // A duplicated: As2[k][2m]=As2[k][2m+1]=A[m]
    __shared__ float Bs[BK][BN];
    __shared__ float YPs[BM][NCLS];
    __shared__ float YQs[BN][NCLS];

    const int tid = threadIdx.x;
    const int tx = tid & 15;
    const int ty = tid >> 4;
    const int row0 = blockIdx.y * BM;
    const int col0 = blockIdx.x * BN;

    for (int idx = tid; idx < BM * NCLS; idx += 256) {
        int r = idx / NCLS, c = idx - r * NCLS;
        YPs[r][c] = YP[(size_t)(row0 + r) * NCLS + c];
        YQs[r][c] = YQ[(size_t)(col0 + r) * NCLS + c];
    }

    unsigned long long acc[8][4];
#pragma unroll
    for (int i = 0; i < 8; i++)
#pragma unroll
        for (int j = 0; j < 4; j++) acc[i][j] = 0ull;

    for (int k0 = 0; k0 < DD; k0 += BK) {
#pragma unroll
        for (int l = 0; l < 2; l++) {
            int idx = tid + l * 256;
            int r = idx >> 2;
            int kq = (idx & 3) << 2;
            float4 va = *reinterpret_cast<const float4*>(XP + (size_t)(row0 + r) * DD + k0 + kq);
            As2[kq + 0][2 * r] = va.x; As2[kq + 0][2 * r + 1] = va.x;
            As2[kq + 1][2 * r] = va.y; As2[kq + 1][2 * r + 1] = va.y;
            As2[kq + 2][2 * r] = va.z; As2[kq + 2][2 * r + 1] = va.z;
            As2[kq + 3][2 * r] = va.w; As2[kq + 3][2 * r + 1] = va.w;
            float4 vb = *reinterpret_cast<const float4*>(XQ + (size_t)(col0 + r) * DD + k0 + kq);
            Bs[kq + 0][r] = vb.x; Bs[kq + 1][r] = vb.y; Bs[kq + 2][r] = vb.z; Bs[kq + 3][r] = vb.w;
        }
        __syncthreads();
#pragma unroll
        for (int kk = 0; kk < BK; kk++) {
            unsigned long long a2[8], b2[4];
#pragma unroll
            for (int s = 0; s < 4; s++) {
                float4 v = *reinterpret_cast<const float4*>(&As2[kk][16 * ty + 4 * s]);
                asm("mov.b64 %0, {%1,%2};" : "=l"(a2[2 * s])     : "f"(v.x), "f"(v.y));
                asm("mov.b64 %0, {%1,%2};" : "=l"(a2[2 * s + 1]) : "f"(v.z), "f"(v.w));
            }
#pragma unroll
            for (int s = 0; s < 2; s++) {
                float4 v = *reinterpret_cast<const float4*>(&Bs[kk][8 * tx + 4 * s]);
                asm("mov.b64 %0, {%1,%2};" : "=l"(b2[2 * s])     : "f"(v.x), "f"(v.y));
                asm("mov.b64 %0, {%1,%2};" : "=l"(b2[2 * s + 1]) : "f"(v.z), "f"(v.w));
            }
#pragma unroll
            for (int i = 0; i < 8; i++)
#pragma unroll
                for (int j = 0; j < 4; j++)
                    asm("fma.rn.f32x2 %0, %1, %2, %0;" : "+l"(acc[i][j]) : "l"(a2[i]), "l"(b2[j]));
        }
        __syncthreads();
    }

    float maxcx = 0.f, maxcy = 0.f;
#pragma unroll
    for (int i = 0; i < 8; i++) {
        int gi = row0 + ty * 8 + i;
        float xp2i = g_xp2[gi];
        float yp2i = g_yp2[gi];
        float outv[8];
#pragma unroll
        for (int j2 = 0; j2 < 4; j2++) {
            float lo, hi;
            asm("mov.b64 {%0,%1}, %2;" : "=f"(lo), "=f"(hi) : "l"(acc[i][j2]));
            int gj0 = col0 + tx * 8 + 2 * j2;
            float cx0 = fmaxf(xp2i + g_xq2[gj0]     - 2.f * lo, 0.f);
            float cx1 = fmaxf(xp2i + g_xq2[gj0 + 1] - 2.f * hi, 0.f);
            outv[2 * j2] = cx0; outv[2 * j2 + 1] = cx1;
            maxcx = fmaxf(maxcx, fmaxf(cx0, cx1));
        }
        float4* dst = reinterpret_cast<float4*>(g_C + (size_t)gi * NN + col0 + tx * 8);
        dst[0] = make_float4(outv[0], outv[1], outv[2], outv[3]);
        dst[1] = make_float4(outv[4], outv[5], outv[6], outv[7]);
#pragma unroll
        for (int j = 0; j < 8; j++) {
            int lj = tx * 8 + j;
            float dot = 0.f;
#pragma unroll
            for (int c = 0; c < NCLS; c++) dot = fmaf(YPs[ty * 8 + i][c], YQs[lj][c], dot);
            float cy = fmaxf(yp2i + g_yq2[col0 + lj] - 2.f * dot, 0.f);
            maxcy = fmaxf(maxcy, cy);
        }
    }
#pragma unroll
    for (int o = 16; o > 0; o >>= 1) {
        maxcx = fmaxf(maxcx, __shfl_xor_sync(0xffffffffu, maxcx, o));
        maxcy = fmaxf(maxcy, __shfl_xor_sync(0xffffffffu, maxcy, o));
    }
    if ((tid & 31) == 0) {
        atomicMax(&g_max_cx, __float_as_uint(maxcx));   // values >= 0: uint compare == float compare
        atomicMax(&g_max_cy, __float_as_uint(maxcy));
    }
}

// ---- shared pattern: 16 rows per block, 4 cols per thread, CY recomputed ----

// max(C) over all elements; C = CX + lw*CY on the fly.
__global__ void __launch_bounds__(256) k_maxc(const float* __restrict__ YP, const float* __restrict__ YQ) {
    __shared__ float YPs[16][NCLS];
    __shared__ float yp2s[16];
    const int i0 = blockIdx.x * 16;
    const int tid = threadIdx.x;
    if (tid < 16 * NCLS) { int r = tid / NCLS, c = tid - r * NCLS; YPs[r][c] = YP[(size_t)(i0 + r) * NCLS + c]; }
    if (tid < 16) yp2s[tid] = g_yp2[i0 + tid];
    __syncthreads();
    float cxm = __uint_as_float(g_max_cx);
    float cym = __uint_as_float(g_max_cy);
    float lw = (cym == 0.f) ? 0.f : cxm / cym;
    float localmax = 0.f;
    for (int j0 = tid * 4; j0 < NN; j0 += 1024) {
        float yq[4][NCLS], yq2[4];
#pragma unroll
        for (int c = 0; c < 4; c++) {
#pragma unroll
            for (int d = 0; d < NCLS; d += 2) {
                float2 t = __ldg(reinterpret_cast<const float2*>(&YQ[(size_t)(j0 + c) * NCLS + d]));
                yq[c][d] = t.x; yq[c][d + 1] = t.y;
            }
            yq2[c] = g_yq2[j0 + c];
        }
#pragma unroll
        for (int r = 0; r < 16; r++) {
            float4 cx = *reinterpret_cast<const float4*>(&g_C[(size_t)(i0 + r) * NN + j0]);
            float cxa[4] = {cx.x, cx.y, cx.z, cx.w};
#pragma unroll
            for (int c = 0; c < 4; c++) {
                float dot = 0.f;
#pragma unroll
                for (int d = 0; d < NCLS; d++) dot = fmaf(YPs[r][d], yq[c][d], dot);
                float cy = fmaxf(yp2s[r] + yq2[c] - 2.f * dot, 0.f);
                localmax = fmaxf(localmax, cxa[c] + lw * cy);
            }
        }
    }
#pragma unroll
    for (int o = 16; o > 0; o >>= 1)
        localmax = fmaxf(localmax, __shfl_xor_sync(0xffffffffu, localmax, o));
    if ((tid & 31) == 0) atomicMax(&g_max_c, __float_as_uint(localmax));
}

// P' = 2^SHIFT * exp(-C/(reg*cmax)) stored as fp16
__global__ void __launch_bounds__(256) k_exp(const float* __restrict__ YP, const float* __restrict__ YQ) {
    __shared__ float YPs[16][NCLS];
    __shared__ float yp2s[16];
    const int i0 = blockIdx.x * 16;
    const int tid = threadIdx.x;
    if (tid < 16 * NCLS) { int r = tid / NCLS, c = tid - r * NCLS; YPs[r][c] = YP[(size_t)(i0 + r) * NCLS + c]; }
    if (tid < 16) yp2s[tid] = g_yp2[i0 + tid];
    __syncthreads();
    float cxm = __uint_as_float(g_max_cx);
    float cym = __uint_as_float(g_max_cy);
    float lw = (cym == 0.f) ? 0.f : cxm / cym;
    float cmax = __uint_as_float(g_max_c);
    float sc = 1.4426950408889634f / (REG_E * cmax);
    for (int j0 = tid * 4; j0 < NN; j0 += 1024) {
        float yq[4][NCLS], yq2[4];
#pragma unroll
        for (int c = 0; c < 4; c++) {
#pragma unroll
            for (int d = 0; d < NCLS; d += 2) {
                float2 t = __ldg(reinterpret_cast<const float2*>(&YQ[(size_t)(j0 + c) * NCLS + d]));
                yq[c][d] = t.x; yq[c][d + 1] = t.y;
            }
            yq2[c] = g_yq2[j0 + c];
        }
#pragma unroll
        for (int r = 0; r < 16; r++) {
            float4 cx = *reinterpret_cast<const float4*>(&g_C[(size_t)(i0 + r) * NN + j0]);
            float cxa[4] = {cx.x, cx.y, cx.z, cx.w};
            float pv[4];
#pragma unroll
            for (int c = 0; c < 4; c++) {
                float dot = 0.f;
#pragma unroll
                for (int d = 0; d < NCLS; d++) dot = fmaf(YPs[r][d], yq[c][d], dot);
                float cy = fmaxf(yp2s[r] + yq2[c] - 2.f * dot, 0.f);
                float v = cxa[c] + lw * cy;
                pv[c] = fexp2(fmaf(-v, sc, SHIFT));
            }
            union { __half2 h[2]; uint2 u; } pk;
            pk.h[0] = __floats2half2_rn(pv[0], pv[1]);
            pk.h[1] = __floats2half2_rn(pv[2], pv[3]);
            *reinterpret_cast<uint2*>(&g_Ph[(size_t)(i0 + r) * NN + j0]) = pk.u;
        }
    }
}

// z' = (1/N) / (P' @ w)  -- 8 rows per block, one warp per row, w staged in smem
__global__ void __launch_bounds__(256) k_row() {
    __shared__ float ws[NN];
    const int tid = threadIdx.x;
    const int i0 = blockIdx.x * 8;
    const int wid = tid >> 5, lane = tid & 31;
    // cooperative load of w (32 KB)
    {
        const float4* W4 = reinterpret_cast<const float4*>(g_w);
        float4* S4 = reinterpret_cast<float4*>(ws);
#pragma unroll
        for (int k = 0; k < 8; k++) S4[tid + k * 256] = W4[tid + k * 256];
    }
    __syncthreads();
    const uint4* Pr = reinterpret_cast<const uint4*>(g_Ph + (size_t)(i0 + wid) * NN);
    float acc = 0.f;
#pragma unroll 4
    for (int c = lane; c < 1024; c += 32) {
        uint4 pv = Pr[c];
        float2 f0 = __half22float2(*reinterpret_cast<__half2*>(&pv.x));
        float2 f1 = __half22float2(*reinterpret_cast<__half2*>(&pv.y));
        float2 f2 = __half22float2(*reinterpret_cast<__half2*>(&pv.z));
        float2 f3 = __half22float2(*reinterpret_cast<__half2*>(&pv.w));
        float4 w0 = *reinterpret_cast<const float4*>(&ws[c * 8]);
        float4 w1 = *reinterpret_cast<const float4*>(&ws[c * 8 + 4]);
        acc = fmaf(f0.x, w0.x, acc); acc = fmaf(f0.y, w0.y, acc);
        acc = fmaf(f1.x, w0.z, acc); acc = fmaf(f1.y, w0.w, acc);
        acc = fmaf(f2.x, w1.x, acc); acc = fmaf(f2.y, w1.y, acc);
        acc = fmaf(f3.x, w1.z, acc); acc = fmaf(f3.y, w1.w, acc);
    }
#pragma unroll
    for (int o = 16; o > 0; o >>= 1) acc += __shfl_down_sync(0xffffffffu, acc, o);
    if (lane == 0) g_z[i0 + wid] = (1.0f / NN) / acc;
}

// partial column sums of P'^T @ z' : grid (4, 128), 64 rows per y-block
__global__ void __launch_bounds__(256) k_colpart() {
    __shared__ float zs[64];
    const int tid = threadIdx.x;
    const int c8 = blockIdx.x * 256 + tid;      // uint4 (8-col) chunk index 0..1023
    const int r0 = blockIdx.y * 64;
    if (tid < 64) zs[tid] = g_z[r0 + tid];
    __syncthreads();
    const uint4* P4 = reinterpret_cast<const uint4*>(g_Ph);
    float a0 = 0.f, a1 = 0.f, a2 = 0.f, a3 = 0.f, a4 = 0.f, a5 = 0.f, a6 = 0.f, a7 = 0.f;
#pragma unroll 4
    for (int r = 0; r < 64; r++) {
        float zz = zs[r];
        uint4 pv = P4[(size_t)(r0 + r) * 1024 + c8];
        float2 f0 = __half22float2(*reinterpret_cast<__half2*>(&pv.x));
        float2 f1 = __half22float2(*reinterpret_cast<__half2*>(&pv.y));
        float2 f2 = __half22float2(*reinterpret_cast<__half2*>(&pv.z));
        float2 f3 = __half22float2(*reinterpret_cast<__half2*>(&pv.w));
        a0 = fmaf(f0.x, zz, a0); a1 = fmaf(f0.y, zz, a1);
        a2 = fmaf(f1.x, zz, a2); a3 = fmaf(f1.y, zz, a3);
        a4 = fmaf(f2.x, zz, a4); a5 = fmaf(f2.y, zz, a5);
        a6 = fmaf(f3.x, zz, a6); a7 = fmaf(f3.y, zz, a7);
    }
    float4* G = reinterpret_cast<float4*>(g_part);
    G[(size_t)blockIdx.y * 2048 + c8 * 2]     = make_float4(a0, a1, a2, a3);
    G[(size_t)blockIdx.y * 2048 + c8 * 2 + 1] = make_float4(a4, a5, a6, a7);
}

// w = (1/M) / colsum  -- deterministic chunk-ordered reduce
__global__ void __launch_bounds__(256) k_colred() {
    int c4 = blockIdx.x * 256 + threadIdx.x;   // grid 8
    const float4* G = reinterpret_cast<const float4*>(g_part);
    float ax = 0.f, ay = 0.f, az = 0.f, aw = 0.f;
    for (int ch = 0; ch < 128; ch++) {
        float4 p = G[(size_t)ch * 2048 + c4];
        ax += p.x; ay += p.y; az += p.z; aw += p.w;
    }
    float4 w;
    w.x = (1.0f / NN) / ax;
    w.y = (1.0f / NN) / ay;
    w.z = (1.0f / NN) / az;
    w.w = (1.0f / NN) / aw;
    reinterpret_cast<float4*>(g_w)[c4] = w;
}

// sum_ij C_ij * plan_ij; C and plan (fp32) recomputed from CX + CY
__global__ void __launch_bounds__(256) k_final(const float* __restrict__ YP, const float* __restrict__ YQ) {
    __shared__ float YPs[16][NCLS];
    __shared__ float yp2s[16];
    __shared__ float zs[16];
    const int i0 = blockIdx.x * 16;
    const int tid = threadIdx.x;
    if (tid < 16 * NCLS) { int r = tid / NCLS, c = tid - r * NCLS; YPs[r][c] = YP[(size_t)(i0 + r) * NCLS + c]; }
    if (tid < 16) { yp2s[tid] = g_yp2[i0 + tid]; zs[tid] = g_z[i0 + tid] * SHIFT_MUL; }
    __syncthreads();
    float cxm = __uint_as_float(g_max_cx);
    float cym = __uint_as_float(g_max_cy);
    float lw = (cym == 0.f) ? 0.f : cxm / cym;
    float cmax = __uint_as_float(g_max_c);
    float sc = 1.4426950408889634f / (REG_E * cmax);
    float acc = 0.f;
    for (int j0 = tid * 4; j0 < NN; j0 += 1024) {
        float yq[4][NCLS], yq2[4];
#pragma unroll
        for (int c = 0; c < 4; c++) {
#pragma unroll
            for (int d = 0; d < NCLS; d += 2) {
                float2 t = __ldg(reinterpret_cast<const float2*>(&YQ[(size_t)(j0 + c) * NCLS + d]));
                yq[c][d] = t.x; yq[c][d + 1] = t.y;
            }
            yq2[c] = g_yq2[j0 + c];
        }
        float4 wv = *reinterpret_cast<const float4*>(&g_w[j0]);
        float wa[4] = {wv.x, wv.y, wv.z, wv.w};
#pragma unroll
        for (int r = 0; r < 16; r++) {
            float4 cx = *reinterpret_cast<const float4*>(&g_C[(size_t)(i0 + r) * NN + j0]);
            float cxa[4] = {cx.x, cx.y, cx.z, cx.w};
            float zi = zs[r];
#pragma unroll
            for (int c = 0; c < 4; c++) {
                float dot = 0.f;
#pragma unroll
                for (int d = 0; d < NCLS; d++) dot = fmaf(YPs[r][d], yq[c][d], dot);
                float cy = fmaxf(yp2s[r] + yq2[c] - 2.f * dot, 0.f);
                float v = cxa[c] + lw * cy;
                float p = fexp2(-v * sc);            // fp32 plan kernel
                acc = fmaf(v * p, zi * wa[c], acc);  // C * plan
            }
        }
    }
    acc = blockReduceSum(acc);
    if (tid == 0) g_bpart[blockIdx.x] = acc;
}

__global__ void __launch_bounds__(256) k_finalred(float* out) {
    double s = 0.0;
    for (int t = threadIdx.x; t < 512; t += 256) s += (double)g_bpart[t];
    s = blockReduceSumD(s);
    if (threadIdx.x == 0) out[0] = (float)s;
}

// ---------------- launch ----------------
extern "C" void kernel_launch(void* const* d_in, const int* in_sizes, int n_in,
                              void* d_out, int out_size) {
    const float* XQ = (const float*)d_in[0];   // (8192, 512)
    const float* YQ = (const float*)d_in[1];   // (8192, 10)
    const float* XP = (const float*)d_in[2];   // (8192, 512)
    const float* YP = (const float*)d_in[3];   // (8192, 10)
    float* out = (float*)d_out;

    k_init<<<32, 256>>>();
    k_norm512<<<dim3(NN, 2), 128>>>(XP, XQ);
    k_norm10<<<32, 256>>>(YP, YQ);

    k_gemm<<<dim3(NN / BN, NN / BM), 256>>>(XP, XQ, YP, YQ);   // launch #4: target for ncu capture
    k_maxc<<<NN / 16, 256>>>(YP, YQ);
    k_exp<<<NN / 16, 256>>>(YP, YQ);

    for (int it = 0; it < NIT; it++) {
        k_row<<<NN / 8, 256>>>();
        k_colpart<<<dim3(4, 128), 256>>>();
        k_colred<<<8, 256>>>();
    }

    k_final<<<NN / 16, 256>>>(YP, YQ);
    k_finalred<<<1, 256>>>(out);
}

// round 6
// speedup vs baseline: 1.3719x; 1.2260x over previous
#include <cuda_runtime.h>
#include <cuda_fp16.h>
#include <cstdint>

// Problem constants
#define NN   8192
#define DD   512
#define NCLS 10
#define REG_E 0.05f
#define NIT  20
#define SHIFT 15.0f          // exp2 shift for fp16 P storage
#define SHIFT_MUL 32768.0f   // 2^15

static constexpr size_t NN2 = (size_t)NN * (size_t)NN;

// ---------------- scratch (device globals; no allocation) ----------------
static __device__ float  g_C[NN2];            // 256 MiB: CX only
static __device__ __half g_Ph[NN2];           // 128 MiB: P' = 2^15 * exp(-C/(reg*cmax))
static __device__ float g_xp2[NN], g_xq2[NN], g_yp2[NN], g_yq2[NN];
static __device__ float g_z[NN], g_w[NN];
static __device__ float g_part[64 * NN];      // column-pass partials (2 MB)
static __device__ float g_bpart[512];         // final reduction partials
static __device__ unsigned g_max_cx, g_max_cy, g_max_c;

// ---------------- generic helpers ----------------
__device__ __forceinline__ float blockReduceSum(float v) {
    __shared__ float red[32];
    unsigned lane = threadIdx.x & 31u, wid = threadIdx.x >> 5;
#pragma unroll
    for (int o = 16; o > 0; o >>= 1) v += __shfl_down_sync(0xffffffffu, v, o);
    if (lane == 0) red[wid] = v;
    __syncthreads();
    int nw = (blockDim.x + 31) >> 5;
    v = (threadIdx.x < (unsigned)nw) ? red[threadIdx.x] : 0.f;
    if (wid == 0) {
#pragma unroll
        for (int o = 16; o > 0; o >>= 1) v += __shfl_down_sync(0xffffffffu, v, o);
    }
    return v;  // valid in thread 0
}

__device__ __forceinline__ double blockReduceSumD(double v) {
    __shared__ double redd[32];
    unsigned lane = threadIdx.x & 31u, wid = threadIdx.x >> 5;
#pragma unroll
    for (int o = 16; o > 0; o >>= 1) v += __shfl_down_sync(0xffffffffu, v, o);
    if (lane == 0) redd[wid] = v;
    __syncthreads();
    int nw = (blockDim.x + 31) >> 5;
    v = (threadIdx.x < (unsigned)nw) ? redd[threadIdx.x] : 0.0;
    if (wid == 0) {
#pragma unroll
        for (int o = 16; o > 0; o >>= 1) v += __shfl_down_sync(0xffffffffu, v, o);
    }
    return v;
}

// fast exp2 for y in [-30, 16]; FMA-only (no MUFU). rel err ~1e-7.
__device__ __forceinline__ float fexp2(float y) {
    float fk = y + 12582912.0f;
    int   k  = __float_as_int(fk) - 0x4B400000;
    float r  = y - (fk - 12582912.0f);
    float p  = 1.5403530e-4f;
    p = fmaf(p, r, 1.3333558e-3f);
    p = fmaf(p, r, 9.6181291e-3f);
    p = fmaf(p, r, 5.5504109e-2f);
    p = fmaf(p, r, 2.4022651e-1f);
    p = fmaf(p, r, 6.9314718e-1f);
    p = fmaf(p, r, 1.0f);
    return p * __int_as_float((k + 127) << 23);
}

// ---------------- mma / cp.async helpers (sm_80+ PTX, works on plain sm_100) ----
__device__ __forceinline__ void mma_tf32(float* d, const uint32_t* a, const uint32_t* b) {
    asm volatile(
        "mma.sync.aligned.m16n8k8.row.col.f32.tf32.tf32.f32 "
        "{%0,%1,%2,%3}, {%4,%5,%6,%7}, {%8,%9}, {%0,%1,%2,%3};"
        : "+f"(d[0]), "+f"(d[1]), "+f"(d[2]), "+f"(d[3])
        : "r"(a[0]), "r"(a[1]), "r"(a[2]), "r"(a[3]), "r"(b[0]), "r"(b[1]));
}
__device__ __forceinline__ void split_tf32(float f, uint32_t& hi, uint32_t& lo) {
    asm("cvt.rna.tf32.f32 %0, %1;" : "=r"(hi) : "f"(f));
    float l = f - __uint_as_float(hi);
    asm("cvt.rna.tf32.f32 %0, %1;" : "=r"(lo) : "f"(l));
}
__device__ __forceinline__ uint32_t smem_u32(const void* p) {
    uint32_t a;
    asm("{ .reg .u64 t; cvta.to.shared.u64 t, %1; cvt.u32.u64 %0, t; }" : "=r"(a) : "l"(p));
    return a;
}
#define CP_ASYNC16(dst, src) \
    asm volatile("cp.async.cg.shared.global [%0], [%1], 16;" :: "r"(dst), "l"(src) : "memory")
#define CP_COMMIT() asm volatile("cp.async.commit_group;" ::: "memory")
#define CP_WAIT0()  asm volatile("cp.async.wait_group 0;" ::: "memory")

// ---------------- small kernels ----------------
__global__ void k_init() {
    int t = blockIdx.x * blockDim.x + threadIdx.x;
    if (t == 0) { g_max_cx = 0u; g_max_cy = 0u; g_max_c = 0u; }
    if (t < NN) g_w[t] = 1.0f;
}

__global__ void k_norm512(const float* __restrict__ XP, const float* __restrict__ XQ) {
    int i = blockIdx.x;
    const float* X = blockIdx.y ? XQ : XP;
    float4 v = reinterpret_cast<const float4*>(X)[(size_t)i * (DD / 4) + threadIdx.x];
    float s = v.x * v.x + v.y * v.y + v.z * v.z + v.w * v.w;
    s = blockReduceSum(s);
    if (threadIdx.x == 0) (blockIdx.y ? g_xq2 : g_xp2)[i] = s;
}

__global__ void k_norm10(const float* __restrict__ YP, const float* __restrict__ YQ) {
    int i = blockIdx.x * blockDim.x + threadIdx.x;
    if (i < NN) {
        float sp = 0.f, sq = 0.f;
#pragma unroll
        for (int c = 0; c < NCLS; c++) {
            float tp = YP[(size_t)i * NCLS + c];
            float tq = YQ[(size_t)i * NCLS + c];
            sp += tp * tp; sq += tq * tq;
        }
        g_yp2[i] = sp; g_yq2[i] = sq;
    }
}

// ---------------- 3xTF32 mma.sync GEMM: CX tile + maxCX/maxCY ----------------
// CTA tile 128x128, 8 warps (2x4), warp tile 64x32 (4x4 m16n8k8 tiles).
// BK=32, cp.async double-buffered raw fp32 smem with PAD=36-float rows.
#define PAD 36
#define BUF_F (2 * 128 * PAD)            // floats per buffer (A then B)
#define SMEM_GEMM (2 * BUF_F * 4)        // bytes: 73728

__global__ void __launch_bounds__(256, 1)
k_gemm_mma(const float* __restrict__ XP, const float* __restrict__ XQ,
           const float* __restrict__ YP, const float* __restrict__ YQ) {
    extern __shared__ float sm[];
    const int tid = threadIdx.x;
    const int wid = tid >> 5, lane = tid & 31;
    const int warp_m = wid >> 2, warp_n = wid & 3;
    const int g = lane >> 2, t4 = lane & 3;
    const int row0 = blockIdx.y * 128;
    const int col0 = blockIdx.x * 128;

    const uint32_t smb = smem_u32(sm);

    float acc[4][4][4];
#pragma unroll
    for (int mt = 0; mt < 4; mt++)
#pragma unroll
        for (int nt = 0; nt < 4; nt++)
#pragma unroll
            for (int q = 0; q < 4; q++) acc[mt][nt][q] = 0.f;

    // cp.async issue of chunk ch into buffer buf
    auto issue = [&](int ch, int buf) {
        const uint32_t abase = smb + (uint32_t)buf * (BUF_F * 4);
        const uint32_t bbase = abase + 128 * PAD * 4;
#pragma unroll
        for (int q = 0; q < 4; q++) {
            int f = tid + q * 256;          // float4 index 0..1023
            int r = f >> 3;
            int c4 = f & 7;
            uint32_t doff = (uint32_t)(r * PAD + c4 * 4) * 4;
            const float* srcA = XP + (size_t)(row0 + r) * DD + ch * 32 + c4 * 4;
            const float* srcB = XQ + (size_t)(col0 + r) * DD + ch * 32 + c4 * 4;
            CP_ASYNC16(abase + doff, srcA);
            CP_ASYNC16(bbase + doff, srcB);
        }
        CP_COMMIT();
    };

    issue(0, 0);
    for (int ch = 0; ch < 16; ch++) {
        const int buf = ch & 1;
        CP_WAIT0();
        __syncthreads();
        if (ch < 15) issue(ch + 1, buf ^ 1);
        const float* As = sm + buf * BUF_F;
        const float* Bs = As + 128 * PAD;
#pragma unroll
        for (int k8 = 0; k8 < 4; k8++) {
            const int kb = k8 * 8;
            uint32_t ahi[4][4], alo[4][4];
#pragma unroll
            for (int mt = 0; mt < 4; mt++) {
                const float* ap = As + (warp_m * 64 + mt * 16 + g) * PAD + kb;
                split_tf32(ap[t4],            ahi[mt][0], alo[mt][0]);
                split_tf32(ap[8 * PAD + t4],  ahi[mt][1], alo[mt][1]);
                split_tf32(ap[t4 + 4],        ahi[mt][2], alo[mt][2]);
                split_tf32(ap[8 * PAD + t4 + 4], ahi[mt][3], alo[mt][3]);
            }
            uint32_t bhi[4][2], blo[4][2];
#pragma unroll
            for (int nt = 0; nt < 4; nt++) {
                const float* bp = Bs + (warp_n * 32 + nt * 8 + g) * PAD + kb;
                split_tf32(bp[t4],     bhi[nt][0], blo[nt][0]);
                split_tf32(bp[t4 + 4], bhi[nt][1], blo[nt][1]);
            }
#pragma unroll
            for (int mt = 0; mt < 4; mt++)
#pragma unroll
                for (int nt = 0; nt < 4; nt++) {
                    mma_tf32(acc[mt][nt], alo[mt], bhi[nt]);
                    mma_tf32(acc[mt][nt], ahi[mt], blo[nt]);
                    mma_tf32(acc[mt][nt], ahi[mt], bhi[nt]);
                }
        }
        __syncthreads();
    }

    // ---- epilogue staging (reuse smem) ----
    // sm[0..127]=xq2 slice, [128..255]=yq2 slice, [256..1535]=YQ tile,
    // [1536..2815]=YP tile, [2816..2943]=yp2 slice
    if (tid < 128) {
        sm[tid]        = g_xq2[col0 + tid];
        sm[128 + tid]  = g_yq2[col0 + tid];
        sm[2816 + tid] = g_yp2[row0 + tid];
    }
    for (int i = tid; i < 128 * NCLS; i += 256) {
        sm[256 + i]  = YQ[(size_t)col0 * NCLS + i];
        sm[1536 + i] = YP[(size_t)row0 * NCLS + i];
    }
    __syncthreads();

    // CX epilogue + maxCX
    float maxcx = 0.f;
#pragma unroll
    for (int mt = 0; mt < 4; mt++) {
        const int r1 = warp_m * 64 + mt * 16 + g;
        const int r2 = r1 + 8;
        const float xp2a = g_xp2[row0 + r1];
        const float xp2b = g_xp2[row0 + r2];
#pragma unroll
        for (int nt = 0; nt < 4; nt++) {
            const int n0 = warp_n * 32 + nt * 8 + 2 * t4;
            const float xq0 = sm[n0], xq1 = sm[n0 + 1];
            float c00 = fmaxf(xp2a + xq0 - 2.f * acc[mt][nt][0], 0.f);
            float c01 = fmaxf(xp2a + xq1 - 2.f * acc[mt][nt][1], 0.f);
            float c10 = fmaxf(xp2b + xq0 - 2.f * acc[mt][nt][2], 0.f);
            float c11 = fmaxf(xp2b + xq1 - 2.f * acc[mt][nt][3], 0.f);
            maxcx = fmaxf(maxcx, fmaxf(fmaxf(c00, c01), fmaxf(c10, c11)));
            *reinterpret_cast<float2*>(&g_C[(size_t)(row0 + r1) * NN + col0 + n0]) = make_float2(c00, c01);
            *reinterpret_cast<float2*>(&g_C[(size_t)(row0 + r2) * NN + col0 + n0]) = make_float2(c10, c11);
        }
    }
#pragma unroll
    for (int o = 16; o > 0; o >>= 1) maxcx = fmaxf(maxcx, __shfl_xor_sync(0xffffffffu, maxcx, o));
    if (lane == 0) atomicMax(&g_max_cx, __float_as_uint(maxcx));

    // CY max over this 128x128 tile (K=10)
    {
        const int r = tid & 127;
        const int j0 = (tid >> 7) * 64;
        float ypv[NCLS];
#pragma unroll
        for (int d = 0; d < NCLS; d++) ypv[d] = sm[1536 + r * NCLS + d];
        const float yp2r = sm[2816 + r];
        float mx = 0.f;
        for (int j = j0; j < j0 + 64; j++) {
            float dot = 0.f;
#pragma unroll
            for (int d = 0; d < NCLS; d++) dot = fmaf(ypv[d], sm[256 + j * NCLS + d], dot);
            float cy = fmaxf(yp2r + sm[128 + j] - 2.f * dot, 0.f);
            mx = fmaxf(mx, cy);
        }
#pragma unroll
        for (int o = 16; o > 0; o >>= 1) mx = fmaxf(mx, __shfl_xor_sync(0xffffffffu, mx, o));
        if (lane == 0) atomicMax(&g_max_cy, __float_as_uint(mx));
    }
}

// ---------------- max(C) over all elements (C = CX + lw*CY on the fly) ----------------
__global__ void __launch_bounds__(256) k_maxc(const float* __restrict__ YP, const float* __restrict__ YQ) {
    __shared__ float YPs[16][NCLS];
    __shared__ float yp2s[16];
    const int i0 = blockIdx.x * 16;
    const int tid = threadIdx.x;
    if (tid < 16 * NCLS) { int r = tid / NCLS, c = tid - r * NCLS; YPs[r][c] = YP[(size_t)(i0 + r) * NCLS + c]; }
    if (tid < 16) yp2s[tid] = g_yp2[i0 + tid];
    __syncthreads();
    float cxm = __uint_as_float(g_max_cx);
    float cym = __uint_as_float(g_max_cy);
    float lw = (cym == 0.f) ? 0.f : cxm / cym;
    float localmax = 0.f;
    for (int j0 = tid * 4; j0 < NN; j0 += 1024) {
        float yq[4][NCLS], yq2[4];
#pragma unroll
        for (int c = 0; c < 4; c++) {
#pragma unroll
            for (int d = 0; d < NCLS; d += 2) {
                float2 t = __ldg(reinterpret_cast<const float2*>(&YQ[(size_t)(j0 + c) * NCLS + d]));
                yq[c][d] = t.x; yq[c][d + 1] = t.y;
            }
            yq2[c] = g_yq2[j0 + c];
        }
#pragma unroll
        for (int r = 0; r < 16; r++) {
            float4 cx = *reinterpret_cast<const float4*>(&g_C[(size_t)(i0 + r) * NN + j0]);
            float cxa[4] = {cx.x, cx.y, cx.z, cx.w};
#pragma unroll
            for (int c = 0; c < 4; c++) {
                float dot = 0.f;
#pragma unroll
                for (int d = 0; d < NCLS; d++) dot = fmaf(YPs[r][d], yq[c][d], dot);
                float cy = fmaxf(yp2s[r] + yq2[c] - 2.f * dot, 0.f);
                localmax = fmaxf(localmax, cxa[c] + lw * cy);
            }
        }
    }
#pragma unroll
    for (int o = 16; o > 0; o >>= 1)
        localmax = fmaxf(localmax, __shfl_xor_sync(0xffffffffu, localmax, o));
    if ((tid & 31) == 0) atomicMax(&g_max_c, __float_as_uint(localmax));
}

// ---------------- P' = 2^SHIFT * exp(-C/(reg*cmax)) as fp16 ----------------
__global__ void __launch_bounds__(256) k_exp(const float* __restrict__ YP, const float* __restrict__ YQ) {
    __shared__ float YPs[16][NCLS];
    __shared__ float yp2s[16];
    const int i0 = blockIdx.x * 16;
    const int tid = threadIdx.x;
    if (tid < 16 * NCLS) { int r = tid / NCLS, c = tid - r * NCLS; YPs[r][c] = YP[(size_t)(i0 + r) * NCLS + c]; }
    if (tid < 16) yp2s[tid] = g_yp2[i0 + tid];
    __syncthreads();
    float cxm = __uint_as_float(g_max_cx);
    float cym = __uint_as_float(g_max_cy);
    float lw = (cym == 0.f) ? 0.f : cxm / cym;
    float cmax = __uint_as_float(g_max_c);
    float sc = 1.4426950408889634f / (REG_E * cmax);
    for (int j0 = tid * 4; j0 < NN; j0 += 1024) {
        float yq[4][NCLS], yq2[4];
#pragma unroll
        for (int c = 0; c < 4; c++) {
#pragma unroll
            for (int d = 0; d < NCLS; d += 2) {
                float2 t = __ldg(reinterpret_cast<const float2*>(&YQ[(size_t)(j0 + c) * NCLS + d]));
                yq[c][d] = t.x; yq[c][d + 1] = t.y;
            }
            yq2[c] = g_yq2[j0 + c];
        }
#pragma unroll
        for (int r = 0; r < 16; r++) {
            float4 cx = *reinterpret_cast<const float4*>(&g_C[(size_t)(i0 + r) * NN + j0]);
            float cxa[4] = {cx.x, cx.y, cx.z, cx.w};
            float pv[4];
#pragma unroll
            for (int c = 0; c < 4; c++) {
                float dot = 0.f;
#pragma unroll
                for (int d = 0; d < NCLS; d++) dot = fmaf(YPs[r][d], yq[c][d], dot);
                float cy = fmaxf(yp2s[r] + yq2[c] - 2.f * dot, 0.f);
                float v = cxa[c] + lw * cy;
                pv[c] = fexp2(fmaf(-v, sc, SHIFT));
            }
            union { __half2 h[2]; uint2 u; } pk;
            pk.h[0] = __floats2half2_rn(pv[0], pv[1]);
            pk.h[1] = __floats2half2_rn(pv[2], pv[3]);
            *reinterpret_cast<uint2*>(&g_Ph[(size_t)(i0 + r) * NN + j0]) = pk.u;
        }
    }
}

// ---------------- Sinkhorn passes ----------------
__global__ void __launch_bounds__(256) k_row() {
    __shared__ float ws[NN];
    const int tid = threadIdx.x;
    const int i0 = blockIdx.x * 8;
    const int wid = tid >> 5, lane = tid & 31;
    {
        const float4* W4 = reinterpret_cast<const float4*>(g_w);
        float4* S4 = reinterpret_cast<float4*>(ws);
#pragma unroll
        for (int k = 0; k < 8; k++) S4[tid + k * 256] = W4[tid + k * 256];
    }
    __syncthreads();
    const uint4* Pr = reinterpret_cast<const uint4*>(g_Ph + (size_t)(i0 + wid) * NN);
    float acc = 0.f;
#pragma unroll 4
    for (int c = lane; c < 1024; c += 32) {
        uint4 pv = Pr[c];
        float2 f0 = __half22float2(*reinterpret_cast<__half2*>(&pv.x));
        float2 f1 = __half22float2(*reinterpret_cast<__half2*>(&pv.y));
        float2 f2 = __half22float2(*reinterpret_cast<__half2*>(&pv.z));
        float2 f3 = __half22float2(*reinterpret_cast<__half2*>(&pv.w));
        float4 w0 = *reinterpret_cast<const float4*>(&ws[c * 8]);
        float4 w1 = *reinterpret_cast<const float4*>(&ws[c * 8 + 4]);
        acc = fmaf(f0.x, w0.x, acc); acc = fmaf(f0.y, w0.y, acc);
        acc = fmaf(f1.x, w0.z, acc); acc = fmaf(f1.y, w0.w, acc);
        acc = fmaf(f2.x, w1.x, acc); acc = fmaf(f2.y, w1.y, acc);
        acc = fmaf(f3.x, w1.z, acc); acc = fmaf(f3.y, w1.w, acc);
    }
#pragma unroll
    for (int o = 16; o > 0; o >>= 1) acc += __shfl_down_sync(0xffffffffu, acc, o);
    if (lane == 0) g_z[i0 + wid] = (1.0f / NN) / acc;
}

// partial column sums of P'^T @ z' : grid (4, 64), 128 rows per y-block
__global__ void __launch_bounds__(256) k_colpart() {
    __shared__ float zs[128];
    const int tid = threadIdx.x;
    const int c8 = blockIdx.x * 256 + tid;      // uint4 (8-col) chunk index 0..1023
    const int r0 = blockIdx.y * 128;
    if (tid < 128) zs[tid] = g_z[r0 + tid];
    __syncthreads();
    const uint4* P4 = reinterpret_cast<const uint4*>(g_Ph);
    float a0 = 0.f, a1 = 0.f, a2 = 0.f, a3 = 0.f, a4 = 0.f, a5 = 0.f, a6 = 0.f, a7 = 0.f;
#pragma unroll 4
    for (int r = 0; r < 128; r++) {
        float zz = zs[r];
        uint4 pv = P4[(size_t)(r0 + r) * 1024 + c8];
        float2 f0 = __half22float2(*reinterpret_cast<__half2*>(&pv.x));
        float2 f1 = __half22float2(*reinterpret_cast<__half2*>(&pv.y));
        float2 f2 = __half22float2(*reinterpret_cast<__half2*>(&pv.z));
        float2 f3 = __half22float2(*reinterpret_cast<__half2*>(&pv.w));
        a0 = fmaf(f0.x, zz, a0); a1 = fmaf(f0.y, zz, a1);
        a2 = fmaf(f1.x, zz, a2); a3 = fmaf(f1.y, zz, a3);
        a4 = fmaf(f2.x, zz, a4); a5 = fmaf(f2.y, zz, a5);
        a6 = fmaf(f3.x, zz, a6); a7 = fmaf(f3.y, zz, a7);
    }
    float4* G = reinterpret_cast<float4*>(g_part);
    G[(size_t)blockIdx.y * 2048 + c8 * 2]     = make_float4(a0, a1, a2, a3);
    G[(size_t)blockIdx.y * 2048 + c8 * 2 + 1] = make_float4(a4, a5, a6, a7);
}

// w = (1/M) / colsum  -- grid 32 (8192 threads, one per column), chunk-ordered
__global__ void __launch_bounds__(256) k_colred() {
    int j = blockIdx.x * 256 + threadIdx.x;   // column 0..8191
    float s = 0.f;
#pragma unroll 4
    for (int ch = 0; ch < 64; ch++) s += g_part[(size_t)ch * NN + j];
    g_w[j] = (1.0f / NN) / s;
}

// ---------------- final objective ----------------
__global__ void __launch_bounds__(256) k_final(const float* __restrict__ YP, const float* __restrict__ YQ) {
    __shared__ float YPs[16][NCLS];
    __shared__ float yp2s[16];
    __shared__ float zs[16];
    const int i0 = blockIdx.x * 16;
    const int tid = threadIdx.x;
    if (tid < 16 * NCLS) { int r = tid / NCLS, c = tid - r * NCLS; YPs[r][c] = YP[(size_t)(i0 + r) * NCLS + c]; }
    if (tid < 16) { yp2s[tid] = g_yp2[i0 + tid]; zs[tid] = g_z[i0 + tid] * SHIFT_MUL; }
    __syncthreads();
    float cxm = __uint_as_float(g_max_cx);
    float cym = __uint_as_float(g_max_cy);
    float lw = (cym == 0.f) ? 0.f : cxm / cym;
    float cmax = __uint_as_float(g_max_c);
    float sc = 1.4426950408889634f / (REG_E * cmax);
    float acc = 0.f;
    for (int j0 = tid * 4; j0 < NN; j0 += 1024) {
        float yq[4][NCLS], yq2[4];
#pragma unroll
        for (int c = 0; c < 4; c++) {
#pragma unroll
            for (int d = 0; d < NCLS; d += 2) {
                float2 t = __ldg(reinterpret_cast<const float2*>(&YQ[(size_t)(j0 + c) * NCLS + d]));
                yq[c][d] = t.x; yq[c][d + 1] = t.y;
            }
            yq2[c] = g_yq2[j0 + c];
        }
        float4 wv = *reinterpret_cast<const float4*>(&g_w[j0]);
        float wa[4] = {wv.x, wv.y, wv.z, wv.w};
#pragma unroll
        for (int r = 0; r < 16; r++) {
            float4 cx = *reinterpret_cast<const float4*>(&g_C[(size_t)(i0 + r) * NN + j0]);
            float cxa[4] = {cx.x, cx.y, cx.z, cx.w};
            float zi = zs[r];
#pragma unroll
            for (int c = 0; c < 4; c++) {
                float dot = 0.f;
#pragma unroll
                for (int d = 0; d < NCLS; d++) dot = fmaf(YPs[r][d], yq[c][d], dot);
                float cy = fmaxf(yp2s[r] + yq2[c] - 2.f * dot, 0.f);
                float v = cxa[c] + lw * cy;
                float p = fexp2(-v * sc);
                acc = fmaf(v * p, zi * wa[c], acc);
            }
        }
    }
    acc = blockReduceSum(acc);
    if (tid == 0) g_bpart[blockIdx.x] = acc;
}

__global__ void __launch_bounds__(256) k_finalred(float* out) {
    double s = 0.0;
    for (int t = threadIdx.x; t < 512; t += 256) s += (double)g_bpart[t];
    s = blockReduceSumD(s);
    if (threadIdx.x == 0) out[0] = (float)s;
}

// ---------------- launch ----------------
extern "C" void kernel_launch(void* const* d_in, const int* in_sizes, int n_in,
                              void* d_out, int out_size) {
    const float* XQ = (const float*)d_in[0];   // (8192, 512)
    const float* YQ = (const float*)d_in[1];   // (8192, 10)
    const float* XP = (const float*)d_in[2];   // (8192, 512)
    const float* YP = (const float*)d_in[3];   // (8192, 10)
    float* out = (float*)d_out;

    cudaFuncSetAttribute(k_gemm_mma, cudaFuncAttributeMaxDynamicSharedMemorySize, SMEM_GEMM);

    k_init<<<32, 256>>>();
    k_norm512<<<dim3(NN, 2), 128>>>(XP, XQ);
    k_norm10<<<32, 256>>>(YP, YQ);

    k_gemm_mma<<<dim3(64, 64), 256, SMEM_GEMM>>>(XP, XQ, YP, YQ);   // launch #4: ncu target
    k_maxc<<<NN / 16, 256>>>(YP, YQ);
    k_exp<<<NN / 16, 256>>>(YP, YQ);

    for (int it = 0; it < NIT; it++) {
        k_row<<<NN / 8, 256>>>();
        k_colpart<<<dim3(4, 64), 256>>>();
        k_colred<<<32, 256>>>();
    }

    k_final<<<NN / 16, 256>>>(YP, YQ);
    k_finalred<<<1, 256>>>(out);
}

// round 7
// speedup vs baseline: 1.6644x; 1.2132x over previous
#include <cuda_runtime.h>
#include <cuda_fp16.h>
#include <cstdint>

// Problem constants
#define NN   8192
#define DD   512
#define NCLS 10
#define REG_E 0.05f
#define NIT  20
#define SHIFT 15.0f          // exp2 shift for fp16 P storage
#define SHIFT_MUL 32768.0f   // 2^15

static constexpr size_t NN2 = (size_t)NN * (size_t)NN;

// ---------------- scratch (device globals; no allocation) ----------------
static __device__ float  g_C[NN2];            // 256 MiB: CX only
static __device__ __half g_Ph[NN2];           // 128 MiB: P' = 2^15 * exp(-C/(reg*cmax))
static __device__ __half g_Ah[NN * DD], g_Al[NN * DD];   // XP hi/lo fp16 planes (8 MB each)
static __device__ __half g_Bh[NN * DD], g_Bl[NN * DD];   // XQ hi/lo fp16 planes
static __device__ float g_xp2[NN], g_xq2[NN], g_yp2[NN], g_yq2[NN];
static __device__ float g_z[NN], g_w[NN];
static __device__ float g_part[64 * NN];      // column-pass partials (2 MB)
static __device__ float g_bpart[512];         // final reduction partials
static __device__ unsigned g_max_cx, g_max_cy, g_max_c;

// ---------------- generic helpers ----------------
__device__ __forceinline__ float blockReduceSum(float v) {
    __shared__ float red[32];
    unsigned lane = threadIdx.x & 31u, wid = threadIdx.x >> 5;
#pragma unroll
    for (int o = 16; o > 0; o >>= 1) v += __shfl_down_sync(0xffffffffu, v, o);
    if (lane == 0) red[wid] = v;
    __syncthreads();
    int nw = (blockDim.x + 31) >> 5;
    v = (threadIdx.x < (unsigned)nw) ? red[threadIdx.x] : 0.f;
    if (wid == 0) {
#pragma unroll
        for (int o = 16; o > 0; o >>= 1) v += __shfl_down_sync(0xffffffffu, v, o);
    }
    return v;  // valid in thread 0
}

__device__ __forceinline__ double blockReduceSumD(double v) {
    __shared__ double redd[32];
    unsigned lane = threadIdx.x & 31u, wid = threadIdx.x >> 5;
#pragma unroll
    for (int o = 16; o > 0; o >>= 1) v += __shfl_down_sync(0xffffffffu, v, o);
    if (lane == 0) redd[wid] = v;
    __syncthreads();
    int nw = (blockDim.x + 31) >> 5;
    v = (threadIdx.x < (unsigned)nw) ? redd[threadIdx.x] : 0.0;
    if (wid == 0) {
#pragma unroll
        for (int o = 16; o > 0; o >>= 1) v += __shfl_down_sync(0xffffffffu, v, o);
    }
    return v;
}

// fast exp2 for y in [-30, 16]; FMA-only (no MUFU). rel err ~1e-7.
__device__ __forceinline__ float fexp2(float y) {
    float fk = y + 12582912.0f;
    int   k  = __float_as_int(fk) - 0x4B400000;
    float r  = y - (fk - 12582912.0f);
    float p  = 1.5403530e-4f;
    p = fmaf(p, r, 1.3333558e-3f);
    p = fmaf(p, r, 9.6181291e-3f);
    p = fmaf(p, r, 5.5504109e-2f);
    p = fmaf(p, r, 2.4022651e-1f);
    p = fmaf(p, r, 6.9314718e-1f);
    p = fmaf(p, r, 1.0f);
    return p * __int_as_float((k + 127) << 23);
}

// ---------------- mma / cp.async helpers (sm_80+ PTX, works on plain sm_100) ----
__device__ __forceinline__ void mma_f16(float* d, const uint32_t* a, const uint32_t* b) {
    asm volatile(
        "mma.sync.aligned.m16n8k16.row.col.f32.f16.f16.f32 "
        "{%0,%1,%2,%3}, {%4,%5,%6,%7}, {%8,%9}, {%0,%1,%2,%3};"
        : "+f"(d[0]), "+f"(d[1]), "+f"(d[2]), "+f"(d[3])
        : "r"(a[0]), "r"(a[1]), "r"(a[2]), "r"(a[3]), "r"(b[0]), "r"(b[1]));
}
__device__ __forceinline__ uint32_t smem_u32(const void* p) {
    uint32_t a;
    asm("{ .reg .u64 t; cvta.to.shared.u64 t, %1; cvt.u32.u64 %0, t; }" : "=r"(a) : "l"(p));
    return a;
}
#define CP_ASYNC16(dst, src) \
    asm volatile("cp.async.cg.shared.global [%0], [%1], 16;" :: "r"(dst), "l"(src) : "memory")
#define CP_COMMIT() asm volatile("cp.async.commit_group;" ::: "memory")
#define CP_WAIT0()  asm volatile("cp.async.wait_group 0;" ::: "memory")

// ---------------- small kernels ----------------
__global__ void k_init() {
    int t = blockIdx.x * blockDim.x + threadIdx.x;
    if (t == 0) { g_max_cx = 0u; g_max_cy = 0u; g_max_c = 0u; }
    if (t < NN) g_w[t] = 1.0f;
}

__global__ void k_norm512(const float* __restrict__ XP, const float* __restrict__ XQ) {
    int i = blockIdx.x;
    const float* X = blockIdx.y ? XQ : XP;
    float4 v = reinterpret_cast<const float4*>(X)[(size_t)i * (DD / 4) + threadIdx.x];
    float s = v.x * v.x + v.y * v.y + v.z * v.z + v.w * v.w;
    s = blockReduceSum(s);
    if (threadIdx.x == 0) (blockIdx.y ? g_xq2 : g_xp2)[i] = s;
}

__global__ void k_norm10(const float* __restrict__ YP, const float* __restrict__ YQ) {
    int i = blockIdx.x * blockDim.x + threadIdx.x;
    if (i < NN) {
        float sp = 0.f, sq = 0.f;
#pragma unroll
        for (int c = 0; c < NCLS; c++) {
            float tp = YP[(size_t)i * NCLS + c];
            float tq = YQ[(size_t)i * NCLS + c];
            sp += tp * tp; sq += tq * tq;
        }
        g_yp2[i] = sp; g_yq2[i] = sq;
    }
}

// split X into fp16 hi/lo planes: x = hi + lo (lo residual <= 2^-24 |x|)
__global__ void __launch_bounds__(256) k_split(const float* __restrict__ XP, const float* __restrict__ XQ) {
    const float4* src = reinterpret_cast<const float4*>(blockIdx.y ? XQ : XP);
    __half* Hh = blockIdx.y ? g_Bh : g_Ah;
    __half* Hl = blockIdx.y ? g_Bl : g_Al;
    int n4 = NN * DD / 4;
    for (int i = blockIdx.x * 256 + threadIdx.x; i < n4; i += gridDim.x * 256) {
        float4 v = src[i];
        __half hx = __float2half_rn(v.x), hy = __float2half_rn(v.y);
        __half hz = __float2half_rn(v.z), hw = __float2half_rn(v.w);
        __half lx = __float2half_rn(v.x - __half2float(hx));
        __half ly = __float2half_rn(v.y - __half2float(hy));
        __half lz = __float2half_rn(v.z - __half2float(hz));
        __half lw = __float2half_rn(v.w - __half2float(hw));
        union { __half2 h[2]; uint2 u; } ph, pl;
        ph.h[0] = __halves2half2(hx, hy); ph.h[1] = __halves2half2(hz, hw);
        pl.h[0] = __halves2half2(lx, ly); pl.h[1] = __halves2half2(lz, lw);
        reinterpret_cast<uint2*>(Hh)[i] = ph.u;
        reinterpret_cast<uint2*>(Hl)[i] = pl.u;
    }
}

// ---------------- 3xFP16 mma.sync GEMM: CX tile + maxCX/maxCY ----------------
// CTA tile 128x128, 8 warps (2x4), warp tile 64x32 (4x4 m16n8k16 tiles).
// BK=32, cp.async double-buffered fp16 hi/lo planes.
// Plane row: 32 halves + 8 pad = 40 halves (80 B); row stride 20 words.
#define ROWW 20                           // words per row
#define PLANE_B (128 * ROWW * 4)          // bytes per plane: 10240
#define BUF_B (4 * PLANE_B)               // 4 planes (Ah,Al,Bh,Bl): 40960
#define SMEM_GEMM (2 * BUF_B)             // 81920

__global__ void __launch_bounds__(256, 1)
k_gemm_mma(const float* __restrict__ YPg, const float* __restrict__ YQg) {
    extern __shared__ float sm[];
    const int tid = threadIdx.x;
    const int wid = tid >> 5, lane = tid & 31;
    const int warp_m = wid >> 2, warp_n = wid & 3;
    const int g = lane >> 2, t4 = lane & 3;
    const int row0 = blockIdx.y * 128;
    const int col0 = blockIdx.x * 128;

    const uint32_t smb = smem_u32(sm);

    float acc[4][4][4];
#pragma unroll
    for (int mt = 0; mt < 4; mt++)
#pragma unroll
        for (int nt = 0; nt < 4; nt++)
#pragma unroll
            for (int q = 0; q < 4; q++) acc[mt][nt][q] = 0.f;

    // cp.async chunk ch into buffer buf (2048 16B-chunks, 8 per thread)
    auto issue = [&](int ch, int buf) {
        const uint32_t base = smb + (uint32_t)buf * BUF_B;
#pragma unroll
        for (int q = 0; q < 8; q++) {
            int idx = tid + q * 256;          // 0..2047
            int plane = idx >> 9;             // 0=Ah,1=Al,2=Bh,3=Bl
            int r = (idx >> 2) & 127;
            int c16 = idx & 3;
            uint32_t dst = base + (uint32_t)plane * PLANE_B + (uint32_t)(r * 80 + c16 * 16);
            const __half* gp = (plane == 0) ? g_Ah : (plane == 1) ? g_Al : (plane == 2) ? g_Bh : g_Bl;
            int rg = ((plane < 2) ? row0 : col0) + r;
            const __half* src = gp + (size_t)rg * DD + ch * 32 + c16 * 8;
            CP_ASYNC16(dst, src);
        }
        CP_COMMIT();
    };

    issue(0, 0);
    for (int ch = 0; ch < 16; ch++) {
        const int buf = ch & 1;
        CP_WAIT0();
        __syncthreads();
        if (ch < 15) issue(ch + 1, buf ^ 1);
        const uint32_t* Ah = reinterpret_cast<const uint32_t*>(sm) + buf * (BUF_B / 4);
        const uint32_t* Al = Ah + PLANE_B / 4;
        const uint32_t* Bh = Al + PLANE_B / 4;
        const uint32_t* Bl = Bh + PLANE_B / 4;
#pragma unroll
        for (int kk = 0; kk < 2; kk++) {
            const int kbw = kk * 8;           // word offset of this k16 block
            uint32_t ah[4][4], al[4][4];
#pragma unroll
            for (int mt = 0; mt < 4; mt++) {
                int base = (warp_m * 64 + mt * 16 + g) * ROWW + kbw + t4;
                ah[mt][0] = Ah[base];       ah[mt][1] = Ah[base + 8 * ROWW];
                ah[mt][2] = Ah[base + 4];   ah[mt][3] = Ah[base + 8 * ROWW + 4];
                al[mt][0] = Al[base];       al[mt][1] = Al[base + 8 * ROWW];
                al[mt][2] = Al[base + 4];   al[mt][3] = Al[base + 8 * ROWW + 4];
            }
            uint32_t bh[4][2], bl[4][2];
#pragma unroll
            for (int nt = 0; nt < 4; nt++) {
                int base = (warp_n * 32 + nt * 8 + g) * ROWW + kbw + t4;
                bh[nt][0] = Bh[base];  bh[nt][1] = Bh[base + 4];
                bl[nt][0] = Bl[base];  bl[nt][1] = Bl[base + 4];
            }
#pragma unroll
            for (int mt = 0; mt < 4; mt++)
#pragma unroll
                for (int nt = 0; nt < 4; nt++) {
                    mma_f16(acc[mt][nt], al[mt], bh[nt]);
                    mma_f16(acc[mt][nt], ah[mt], bl[nt]);
                    mma_f16(acc[mt][nt], ah[mt], bh[nt]);
                }
        }
        __syncthreads();
    }

    // ---- epilogue staging (reuse smem) ----
    // sm[0..127]=xq2 slice, [128..255]=yq2 slice, [256..1535]=YQ tile,
    // [1536..2815]=YP tile, [2816..2943]=yp2 slice
    if (tid < 128) {
        sm[tid]        = g_xq2[col0 + tid];
        sm[128 + tid]  = g_yq2[col0 + tid];
        sm[2816 + tid] = g_yp2[row0 + tid];
    }
    for (int i = tid; i < 128 * NCLS; i += 256) {
        sm[256 + i]  = YQg[(size_t)col0 * NCLS + i];
        sm[1536 + i] = YPg[(size_t)row0 * NCLS + i];
    }
    __syncthreads();

    // CX epilogue + maxCX
    float maxcx = 0.f;
#pragma unroll
    for (int mt = 0; mt < 4; mt++) {
        const int r1 = warp_m * 64 + mt * 16 + g;
        const int r2 = r1 + 8;
        const float xp2a = g_xp2[row0 + r1];
        const float xp2b = g_xp2[row0 + r2];
#pragma unroll
        for (int nt = 0; nt < 4; nt++) {
            const int n0 = warp_n * 32 + nt * 8 + 2 * t4;
            const float xq0 = sm[n0], xq1 = sm[n0 + 1];
            float c00 = fmaxf(xp2a + xq0 - 2.f * acc[mt][nt][0], 0.f);
            float c01 = fmaxf(xp2a + xq1 - 2.f * acc[mt][nt][1], 0.f);
            float c10 = fmaxf(xp2b + xq0 - 2.f * acc[mt][nt][2], 0.f);
            float c11 = fmaxf(xp2b + xq1 - 2.f * acc[mt][nt][3], 0.f);
            maxcx = fmaxf(maxcx, fmaxf(fmaxf(c00, c01), fmaxf(c10, c11)));
            *reinterpret_cast<float2*>(&g_C[(size_t)(row0 + r1) * NN + col0 + n0]) = make_float2(c00, c01);
            *reinterpret_cast<float2*>(&g_C[(size_t)(row0 + r2) * NN + col0 + n0]) = make_float2(c10, c11);
        }
    }
#pragma unroll
    for (int o = 16; o > 0; o >>= 1) maxcx = fmaxf(maxcx, __shfl_xor_sync(0xffffffffu, maxcx, o));
    if (lane == 0) atomicMax(&g_max_cx, __float_as_uint(maxcx));

    // CY max over this 128x128 tile (K=10)
    {
        const int r = tid & 127;
        const int j0 = (tid >> 7) * 64;
        float ypv[NCLS];
#pragma unroll
        for (int d = 0; d < NCLS; d++) ypv[d] = sm[1536 + r * NCLS + d];
        const float yp2r = sm[2816 + r];
        float mx = 0.f;
        for (int j = j0; j < j0 + 64; j++) {
            float dot = 0.f;
#pragma unroll
            for (int d = 0; d < NCLS; d++) dot = fmaf(ypv[d], sm[256 + j * NCLS + d], dot);
            float cy = fmaxf(yp2r + sm[128 + j] - 2.f * dot, 0.f);
            mx = fmaxf(mx, cy);
        }
#pragma unroll
        for (int o = 16; o > 0; o >>= 1) mx = fmaxf(mx, __shfl_xor_sync(0xffffffffu, mx, o));
        if (lane == 0) atomicMax(&g_max_cy, __float_as_uint(mx));
    }
}

// ---------------- max(C) over all elements (C = CX + lw*CY on the fly) ----------------
__global__ void __launch_bounds__(256) k_maxc(const float* __restrict__ YP, const float* __restrict__ YQ) {
    __shared__ float YPs[16][NCLS];
    __shared__ float yp2s[16];
    const int i0 = blockIdx.x * 16;
    const int tid = threadIdx.x;
    if (tid < 16 * NCLS) { int r = tid / NCLS, c = tid - r * NCLS; YPs[r][c] = YP[(size_t)(i0 + r) * NCLS + c]; }
    if (tid < 16) yp2s[tid] = g_yp2[i0 + tid];
    __syncthreads();
    float cxm = __uint_as_float(g_max_cx);
    float cym = __uint_as_float(g_max_cy);
    float lw = (cym == 0.f) ? 0.f : cxm / cym;
    float localmax = 0.f;
    for (int j0 = tid * 4; j0 < NN; j0 += 1024) {
        float yq[4][NCLS], yq2[4];
#pragma unroll
        for (int c = 0; c < 4; c++) {
#pragma unroll
            for (int d = 0; d < NCLS; d += 2) {
                float2 t = __ldg(reinterpret_cast<const float2*>(&YQ[(size_t)(j0 + c) * NCLS + d]));
                yq[c][d] = t.x; yq[c][d + 1] = t.y;
            }
            yq2[c] = g_yq2[j0 + c];
        }
#pragma unroll
        for (int r = 0; r < 16; r++) {
            float4 cx = *reinterpret_cast<const float4*>(&g_C[(size_t)(i0 + r) * NN + j0]);
            float cxa[4] = {cx.x, cx.y, cx.z, cx.w};
#pragma unroll
            for (int c = 0; c < 4; c++) {
                float dot = 0.f;
#pragma unroll
                for (int d = 0; d < NCLS; d++) dot = fmaf(YPs[r][d], yq[c][d], dot);
                float cy = fmaxf(yp2s[r] + yq2[c] - 2.f * dot, 0.f);
                localmax = fmaxf(localmax, cxa[c] + lw * cy);
            }
        }
    }
#pragma unroll
    for (int o = 16; o > 0; o >>= 1)
        localmax = fmaxf(localmax, __shfl_xor_sync(0xffffffffu, localmax, o));
    if ((tid & 31) == 0) atomicMax(&g_max_c, __float_as_uint(localmax));
}

// ---------------- P' = 2^SHIFT * exp(-C/(reg*cmax)) as fp16 ----------------
__global__ void __launch_bounds__(256) k_exp(const float* __restrict__ YP, const float* __restrict__ YQ) {
    __shared__ float YPs[16][NCLS];
    __shared__ float yp2s[16];
    const int i0 = blockIdx.x * 16;
    const int tid = threadIdx.x;
    if (tid < 16 * NCLS) { int r = tid / NCLS, c = tid - r * NCLS; YPs[r][c] = YP[(size_t)(i0 + r) * NCLS + c]; }
    if (tid < 16) yp2s[tid] = g_yp2[i0 + tid];
    __syncthreads();
    float cxm = __uint_as_float(g_max_cx);
    float cym = __uint_as_float(g_max_cy);
    float lw = (cym == 0.f) ? 0.f : cxm / cym;
    float cmax = __uint_as_float(g_max_c);
    float sc = 1.4426950408889634f / (REG_E * cmax);
    for (int j0 = tid * 4; j0 < NN; j0 += 1024) {
        float yq[4][NCLS], yq2[4];
#pragma unroll
        for (int c = 0; c < 4; c++) {
#pragma unroll
            for (int d = 0; d < NCLS; d += 2) {
                float2 t = __ldg(reinterpret_cast<const float2*>(&YQ[(size_t)(j0 + c) * NCLS + d]));
                yq[c][d] = t.x; yq[c][d + 1] = t.y;
            }
            yq2[c] = g_yq2[j0 + c];
        }
#pragma unroll
        for (int r = 0; r < 16; r++) {
            float4 cx = *reinterpret_cast<const float4*>(&g_C[(size_t)(i0 + r) * NN + j0]);
            float cxa[4] = {cx.x, cx.y, cx.z, cx.w};
            float pv[4];
#pragma unroll
            for (int c = 0; c < 4; c++) {
                float dot = 0.f;
#pragma unroll
                for (int d = 0; d < NCLS; d++) dot = fmaf(YPs[r][d], yq[c][d], dot);
                float cy = fmaxf(yp2s[r] + yq2[c] - 2.f * dot, 0.f);
                float v = cxa[c] + lw * cy;
                pv[c] = fexp2(fmaf(-v, sc, SHIFT));
            }
            union { __half2 h[2]; uint2 u; } pk;
            pk.h[0] = __floats2half2_rn(pv[0], pv[1]);
            pk.h[1] = __floats2half2_rn(pv[2], pv[3]);
            *reinterpret_cast<uint2*>(&g_Ph[(size_t)(i0 + r) * NN + j0]) = pk.u;
        }
    }
}

// ---------------- Sinkhorn passes ----------------
__global__ void __launch_bounds__(256) k_row() {
    __shared__ float ws[NN];
    const int tid = threadIdx.x;
    const int i0 = blockIdx.x * 8;
    const int wid = tid >> 5, lane = tid & 31;
    {
        const float4* W4 = reinterpret_cast<const float4*>(g_w);
        float4* S4 = reinterpret_cast<float4*>(ws);
#pragma unroll
        for (int k = 0; k < 8; k++) S4[tid + k * 256] = W4[tid + k * 256];
    }
    __syncthreads();
    const uint4* Pr = reinterpret_cast<const uint4*>(g_Ph + (size_t)(i0 + wid) * NN);
    float acc = 0.f;
#pragma unroll 4
    for (int c = lane; c < 1024; c += 32) {
        uint4 pv = Pr[c];
        float2 f0 = __half22float2(*reinterpret_cast<__half2*>(&pv.x));
        float2 f1 = __half22float2(*reinterpret_cast<__half2*>(&pv.y));
        float2 f2 = __half22float2(*reinterpret_cast<__half2*>(&pv.z));
        float2 f3 = __half22float2(*reinterpret_cast<__half2*>(&pv.w));
        float4 w0 = *reinterpret_cast<const float4*>(&ws[c * 8]);
        float4 w1 = *reinterpret_cast<const float4*>(&ws[c * 8 + 4]);
        acc = fmaf(f0.x, w0.x, acc); acc = fmaf(f0.y, w0.y, acc);
        acc = fmaf(f1.x, w0.z, acc); acc = fmaf(f1.y, w0.w, acc);
        acc = fmaf(f2.x, w1.x, acc); acc = fmaf(f2.y, w1.y, acc);
        acc = fmaf(f3.x, w1.z, acc); acc = fmaf(f3.y, w1.w, acc);
    }
#pragma unroll
    for (int o = 16; o > 0; o >>= 1) acc += __shfl_down_sync(0xffffffffu, acc, o);
    if (lane == 0) g_z[i0 + wid] = (1.0f / NN) / acc;
}

// partial column sums of P'^T @ z' : grid (4, 64), 128 rows per y-block
__global__ void __launch_bounds__(256) k_colpart() {
    __shared__ float zs[128];
    const int tid = threadIdx.x;
    const int c8 = blockIdx.x * 256 + tid;      // uint4 (8-col) chunk index 0..1023
    const int r0 = blockIdx.y * 128;
    if (tid < 128) zs[tid] = g_z[r0 + tid];
    __syncthreads();
    const uint4* P4 = reinterpret_cast<const uint4*>(g_Ph);
    float a0 = 0.f, a1 = 0.f, a2 = 0.f, a3 = 0.f, a4 = 0.f, a5 = 0.f, a6 = 0.f, a7 = 0.f;
#pragma unroll 4
    for (int r = 0; r < 128; r++) {
        float zz = zs[r];
        uint4 pv = P4[(size_t)(r0 + r) * 1024 + c8];
        float2 f0 = __half22float2(*reinterpret_cast<__half2*>(&pv.x));
        float2 f1 = __half22float2(*reinterpret_cast<__half2*>(&pv.y));
        float2 f2 = __half22float2(*reinterpret_cast<__half2*>(&pv.z));
        float2 f3 = __half22float2(*reinterpret_cast<__half2*>(&pv.w));
        a0 = fmaf(f0.x, zz, a0); a1 = fmaf(f0.y, zz, a1);
        a2 = fmaf(f1.x, zz, a2); a3 = fmaf(f1.y, zz, a3);
        a4 = fmaf(f2.x, zz, a4); a5 = fmaf(f2.y, zz, a5);
        a6 = fmaf(f3.x, zz, a6); a7 = fmaf(f3.y, zz, a7);
    }
    float4* G = reinterpret_cast<float4*>(g_part);
    G[(size_t)blockIdx.y * 2048 + c8 * 2]     = make_float4(a0, a1, a2, a3);
    G[(size_t)blockIdx.y * 2048 + c8 * 2 + 1] = make_float4(a4, a5, a6, a7);
}

// w = (1/M) / colsum  -- grid 32 (8192 threads, one per column), chunk-ordered
__global__ void __launch_bounds__(256) k_colred() {
    int j = blockIdx.x * 256 + threadIdx.x;   // column 0..8191
    float s = 0.f;
#pragma unroll 4
    for (int ch = 0; ch < 64; ch++) s += g_part[(size_t)ch * NN + j];
    g_w[j] = (1.0f / NN) / s;
}

// ---------------- final objective ----------------
__global__ void __launch_bounds__(256) k_final(const float* __restrict__ YP, const float* __restrict__ YQ) {
    __shared__ float YPs[16][NCLS];
    __shared__ float yp2s[16];
    __shared__ float zs[16];
    const int i0 = blockIdx.x * 16;
    const int tid = threadIdx.x;
    if (tid < 16 * NCLS) { int r = tid / NCLS, c = tid - r * NCLS; YPs[r][c] = YP[(size_t)(i0 + r) * NCLS + c]; }
    if (tid < 16) { yp2s[tid] = g_yp2[i0 + tid]; zs[tid] = g_z[i0 + tid] * SHIFT_MUL; }
    __syncthreads();
    float cxm = __uint_as_float(g_max_cx);
    float cym = __uint_as_float(g_max_cy);
    float lw = (cym == 0.f) ? 0.f : cxm / cym;
    float cmax = __uint_as_float(g_max_c);
    float sc = 1.4426950408889634f / (REG_E * cmax);
    float acc = 0.f;
    for (int j0 = tid * 4; j0 < NN; j0 += 1024) {
        float yq[4][NCLS], yq2[4];
#pragma unroll
        for (int c = 0; c < 4; c++) {
#pragma unroll
            for (int d = 0; d < NCLS; d += 2) {
                float2 t = __ldg(reinterpret_cast<const float2*>(&YQ[(size_t)(j0 + c) * NCLS + d]));
                yq[c][d] = t.x; yq[c][d + 1] = t.y;
            }
            yq2[c] = g_yq2[j0 + c];
        }
        float4 wv = *reinterpret_cast<const float4*>(&g_w[j0]);
        float wa[4] = {wv.x, wv.y, wv.z, wv.w};
#pragma unroll
        for (int r = 0; r < 16; r++) {
            float4 cx = *reinterpret_cast<const float4*>(&g_C[(size_t)(i0 + r) * NN + j0]);
            float cxa[4] = {cx.x, cx.y, cx.z, cx.w};
            float zi = zs[r];
#pragma unroll
            for (int c = 0; c < 4; c++) {
                float dot = 0.f;
#pragma unroll
                for (int d = 0; d < NCLS; d++) dot = fmaf(YPs[r][d], yq[c][d], dot);
                float cy = fmaxf(yp2s[r] + yq2[c] - 2.f * dot, 0.f);
                float v = cxa[c] + lw * cy;
                float p = fexp2(-v * sc);
                acc = fmaf(v * p, zi * wa[c], acc);
            }
        }
    }
    acc = blockReduceSum(acc);
    if (tid == 0) g_bpart[blockIdx.x] = acc;
}

__global__ void __launch_bounds__(256) k_finalred(float* out) {
    double s = 0.0;
    for (int t = threadIdx.x; t < 512; t += 256) s += (double)g_bpart[t];
    s = blockReduceSumD(s);
    if (threadIdx.x == 0) out[0] = (float)s;
}

// ---------------- launch ----------------
extern "C" void kernel_launch(void* const* d_in, const int* in_sizes, int n_in,
                              void* d_out, int out_size) {
    const float* XQ = (const float*)d_in[0];   // (8192, 512)
    const float* YQ = (const float*)d_in[1];   // (8192, 10)
    const float* XP = (const float*)d_in[2];   // (8192, 512)
    const float* YP = (const float*)d_in[3];   // (8192, 10)
    float* out = (float*)d_out;

    cudaFuncSetAttribute(k_gemm_mma, cudaFuncAttributeMaxDynamicSharedMemorySize, SMEM_GEMM);

    k_init<<<32, 256>>>();
    k_norm512<<<dim3(NN, 2), 128>>>(XP, XQ);
    k_norm10<<<32, 256>>>(YP, YQ);
    k_split<<<dim3(512, 2), 256>>>(XP, XQ);

    k_gemm_mma<<<dim3(64, 64), 256, SMEM_GEMM>>>(YP, YQ);   // launch #5: ncu target
    k_maxc<<<NN / 16, 256>>>(YP, YQ);
    k_exp<<<NN / 16, 256>>>(YP, YQ);

    for (int it = 0; it < NIT; it++) {
        k_row<<<NN / 8, 256>>>();
        k_colpart<<<dim3(4, 64), 256>>>();
        k_colred<<<32, 256>>>();
    }

    k_final<<<NN / 16, 256>>>(YP, YQ);
    k_finalred<<<1, 256>>>(out);
}

// round 10
// speedup vs baseline: 1.7851x; 1.0725x over previous
#include <cuda_runtime.h>
#include <cuda_fp16.h>
#include <cstdint>

// Problem constants
#define NN   8192
#define DD   512
#define NCLS 10
#define REG_E 0.05f
#define NIT  20
#define SHIFT 15.0f          // exp2 shift for fp16 P storage
#define SHIFT_MUL 32768.0f   // 2^15

static constexpr size_t NN2 = (size_t)NN * (size_t)NN;

// ---------------- scratch (device globals; no allocation) ----------------
static __device__ float  g_C[NN2];            // 256 MiB: CX only
static __device__ __half g_Ph[NN2];           // 128 MiB: P' = 2^15 * exp(-C/(reg*cmax))
static __device__ __half g_Ah[NN * DD], g_Al[NN * DD];   // XP hi/lo fp16 planes
static __device__ __half g_Bh[NN * DD];                  // XQ hi plane
static __device__ float g_xp2[NN], g_xq2[NN], g_yp2[NN], g_yq2[NN];
static __device__ float g_z[NN], g_w[NN];
static __device__ float g_part[64 * NN];      // column-pass partials (2 MB)
static __device__ float g_bpart[512];         // final reduction partials
static __device__ unsigned g_max_cx, g_max_cy, g_max_c;

// ---------------- generic helpers ----------------
__device__ __forceinline__ float blockReduceSum(float v) {
    __shared__ float red[32];
    unsigned lane = threadIdx.x & 31u, wid = threadIdx.x >> 5;
#pragma unroll
    for (int o = 16; o > 0; o >>= 1) v += __shfl_down_sync(0xffffffffu, v, o);
    if (lane == 0) red[wid] = v;
    __syncthreads();
    int nw = (blockDim.x + 31) >> 5;
    v = (threadIdx.x < (unsigned)nw) ? red[threadIdx.x] : 0.f;
    if (wid == 0) {
#pragma unroll
        for (int o = 16; o > 0; o >>= 1) v += __shfl_down_sync(0xffffffffu, v, o);
    }
    return v;  // valid in thread 0
}

__device__ __forceinline__ double blockReduceSumD(double v) {
    __shared__ double redd[32];
    unsigned lane = threadIdx.x & 31u, wid = threadIdx.x >> 5;
#pragma unroll
    for (int o = 16; o > 0; o >>= 1) v += __shfl_down_sync(0xffffffffu, v, o);
    if (lane == 0) redd[wid] = v;
    __syncthreads();
    int nw = (blockDim.x + 31) >> 5;
    v = (threadIdx.x < (unsigned)nw) ? redd[threadIdx.x] : 0.0;
    if (wid == 0) {
#pragma unroll
        for (int o = 16; o > 0; o >>= 1) v += __shfl_down_sync(0xffffffffu, v, o);
    }
    return v;
}

// fast exp2 for y in [-30, 16]; FMA-only (no MUFU). rel err ~1e-7.
__device__ __forceinline__ float fexp2(float y) {
    float fk = y + 12582912.0f;
    int   k  = __float_as_int(fk) - 0x4B400000;
    float r  = y - (fk - 12582912.0f);
    float p  = 1.5403530e-4f;
    p = fmaf(p, r, 1.3333558e-3f);
    p = fmaf(p, r, 9.6181291e-3f);
    p = fmaf(p, r, 5.5504109e-2f);
    p = fmaf(p, r, 2.4022651e-1f);
    p = fmaf(p, r, 6.9314718e-1f);
    p = fmaf(p, r, 1.0f);
    return p * __int_as_float((k + 127) << 23);
}

// ---------------- mma / cp.async helpers (sm_80+ PTX, works on plain sm_100) ----
__device__ __forceinline__ void mma_f16(float* d, const uint32_t* a, const uint32_t* b) {
    asm volatile(
        "mma.sync.aligned.m16n8k16.row.col.f32.f16.f16.f32 "
        "{%0,%1,%2,%3}, {%4,%5,%6,%7}, {%8,%9}, {%0,%1,%2,%3};"
        : "+f"(d[0]), "+f"(d[1]), "+f"(d[2]), "+f"(d[3])
        : "r"(a[0]), "r"(a[1]), "r"(a[2]), "r"(a[3]), "r"(b[0]), "r"(b[1]));
}
__device__ __forceinline__ uint32_t smem_u32(const void* p) {
    uint32_t a;
    asm("{ .reg .u64 t; cvta.to.shared.u64 t, %1; cvt.u32.u64 %0, t; }" : "=r"(a) : "l"(p));
    return a;
}
#define CP_ASYNC16(dst, src) \
    asm volatile("cp.async.cg.shared.global [%0], [%1], 16;" :: "r"(dst), "l"(src) : "memory")
#define CP_COMMIT() asm volatile("cp.async.commit_group;" ::: "memory")
#define CP_WAIT0()  asm volatile("cp.async.wait_group 0;" ::: "memory")

// ---------------- small kernels ----------------
__global__ void k_init() {
    int t = blockIdx.x * blockDim.x + threadIdx.x;
    if (t == 0) { g_max_cx = 0u; g_max_cy = 0u; g_max_c = 0u; }
    if (t < NN) g_w[t] = 1.0f;
}

__global__ void k_norm512(const float* __restrict__ XP, const float* __restrict__ XQ) {
    int i = blockIdx.x;
    const float* X = blockIdx.y ? XQ : XP;
    float4 v = reinterpret_cast<const float4*>(X)[(size_t)i * (DD / 4) + threadIdx.x];
    float s = v.x * v.x + v.y * v.y + v.z * v.z + v.w * v.w;
    s = blockReduceSum(s);
    if (threadIdx.x == 0) (blockIdx.y ? g_xq2 : g_xp2)[i] = s;
}

__global__ void k_norm10(const float* __restrict__ YP, const float* __restrict__ YQ) {
    int i = blockIdx.x * blockDim.x + threadIdx.x;
    if (i < NN) {
        float sp = 0.f, sq = 0.f;
#pragma unroll
        for (int c = 0; c < NCLS; c++) {
            float tp = YP[(size_t)i * NCLS + c];
            float tq = YQ[(size_t)i * NCLS + c];
            sp += tp * tp; sq += tq * tq;
        }
        g_yp2[i] = sp; g_yq2[i] = sq;
    }
}

// split: XP -> (hi, lo) fp16 planes; XQ -> hi plane only
__global__ void __launch_bounds__(256) k_split(const float* __restrict__ XP, const float* __restrict__ XQ) {
    const float4* src = reinterpret_cast<const float4*>(blockIdx.y ? XQ : XP);
    __half* Hh = blockIdx.y ? g_Bh : g_Ah;
    int n4 = NN * DD / 4;
    for (int i = blockIdx.x * 256 + threadIdx.x; i < n4; i += gridDim.x * 256) {
        float4 v = src[i];
        __half hx = __float2half_rn(v.x), hy = __float2half_rn(v.y);
        __half hz = __float2half_rn(v.z), hw = __float2half_rn(v.w);
        union { __half2 h[2]; uint2 u; } ph;
        ph.h[0] = __halves2half2(hx, hy); ph.h[1] = __halves2half2(hz, hw);
        reinterpret_cast<uint2*>(Hh)[i] = ph.u;
        if (!blockIdx.y) {
            __half lx = __float2half_rn(v.x - __half2float(hx));
            __half ly = __float2half_rn(v.y - __half2float(hy));
            __half lz = __float2half_rn(v.z - __half2float(hz));
            __half lw = __float2half_rn(v.w - __half2float(hw));
            union { __half2 h[2]; uint2 u; } pl;
            pl.h[0] = __halves2half2(lx, ly); pl.h[1] = __halves2half2(lz, lw);
            reinterpret_cast<uint2*>(g_Al)[i] = pl.u;
        }
    }
}

// ---------------- 2xFP16 mma.sync GEMM: CX tile + maxCX/maxCY ----------------
// CTA tile 128x128, 8 warps (2x4), warp tile 64x32 (4x4 m16n8k16 tiles).
// D = (Ah + Al) * Bh  (drops Ah*Bl term, ~0.007 abs error on CX~1000).
#define ROWW 20                           // words per row (32 halves + pad)
#define PLANE_B (128 * ROWW * 4)          // bytes per plane: 10240
#define BUF_B (3 * PLANE_B)               // planes Ah, Al, Bh: 30720
#define SMEM_GEMM (2 * BUF_B)             // 61440

__global__ void __launch_bounds__(256, 1)
k_gemm_mma(const float* __restrict__ YPg, const float* __restrict__ YQg) {
    extern __shared__ float sm[];
    const int tid = threadIdx.x;
    const int wid = tid >> 5, lane = tid & 31;
    const int warp_m = wid >> 2, warp_n = wid & 3;
    const int g = lane >> 2, t4 = lane & 3;
    const int row0 = blockIdx.y * 128;
    const int col0 = blockIdx.x * 128;

    const uint32_t smb = smem_u32(sm);

    float acc[4][4][4];
#pragma unroll
    for (int mt = 0; mt < 4; mt++)
#pragma unroll
        for (int nt = 0; nt < 4; nt++)
#pragma unroll
            for (int q = 0; q < 4; q++) acc[mt][nt][q] = 0.f;

    // cp.async chunk ch into buffer buf (1536 16B-chunks, 6 per thread)
    auto issue = [&](int ch, int buf) {
        const uint32_t base = smb + (uint32_t)buf * BUF_B;
#pragma unroll
        for (int q = 0; q < 6; q++) {
            int idx = tid + q * 256;          // 0..1535
            int plane = idx >> 9;             // 0=Ah,1=Al,2=Bh
            int r = (idx >> 2) & 127;
            int c16 = idx & 3;
            uint32_t dst = base + (uint32_t)plane * PLANE_B + (uint32_t)(r * 80 + c16 * 16);
            const __half* gp = (plane == 0) ? g_Ah : (plane == 1) ? g_Al : g_Bh;
            int rg = ((plane < 2) ? row0 : col0) + r;
            const __half* src = gp + (size_t)rg * DD + ch * 32 + c16 * 8;
            CP_ASYNC16(dst, src);
        }
        CP_COMMIT();
    };

    issue(0, 0);
    for (int ch = 0; ch < 16; ch++) {
        const int buf = ch & 1;
        CP_WAIT0();
        __syncthreads();
        if (ch < 15) issue(ch + 1, buf ^ 1);
        const uint32_t* Ah = reinterpret_cast<const uint32_t*>(sm) + buf * (BUF_B / 4);
        const uint32_t* Al = Ah + PLANE_B / 4;
        const uint32_t* Bh = Al + PLANE_B / 4;
#pragma unroll
        for (int kk = 0; kk < 2; kk++) {
            const int kbw = kk * 8;           // word offset of this k16 block
            uint32_t ah[4][4], al[4][4];
#pragma unroll
            for (int mt = 0; mt < 4; mt++) {
                int base = (warp_m * 64 + mt * 16 + g) * ROWW + kbw + t4;
                ah[mt][0] = Ah[base];       ah[mt][1] = Ah[base + 8 * ROWW];
                ah[mt][2] = Ah[base + 4];   ah[mt][3] = Ah[base + 8 * ROWW + 4];
                al[mt][0] = Al[base];       al[mt][1] = Al[base + 8 * ROWW];
                al[mt][2] = Al[base + 4];   al[mt][3] = Al[base + 8 * ROWW + 4];
            }
            uint32_t bh[4][2];
#pragma unroll
            for (int nt = 0; nt < 4; nt++) {
                int base = (warp_n * 32 + nt * 8 + g) * ROWW + kbw + t4;
                bh[nt][0] = Bh[base];  bh[nt][1] = Bh[base + 4];
            }
#pragma unroll
            for (int mt = 0; mt < 4; mt++)
#pragma unroll
                for (int nt = 0; nt < 4; nt++) {
                    mma_f16(acc[mt][nt], al[mt], bh[nt]);
                    mma_f16(acc[mt][nt], ah[mt], bh[nt]);
                }
        }
        __syncthreads();
    }

    // ---- epilogue staging (reuse smem) ----
    if (tid < 128) {
        sm[tid]        = g_xq2[col0 + tid];
        sm[128 + tid]  = g_yq2[col0 + tid];
        sm[2816 + tid] = g_yp2[row0 + tid];
    }
    for (int i = tid; i < 128 * NCLS; i += 256) {
        sm[256 + i]  = YQg[(size_t)col0 * NCLS + i];
        sm[1536 + i] = YPg[(size_t)row0 * NCLS + i];
    }
    __syncthreads();

    // CX epilogue + maxCX
    float maxcx = 0.f;
#pragma unroll
    for (int mt = 0; mt < 4; mt++) {
        const int r1 = warp_m * 64 + mt * 16 + g;
        const int r2 = r1 + 8;
        const float xp2a = g_xp2[row0 + r1];
        const float xp2b = g_xp2[row0 + r2];
#pragma unroll
        for (int nt = 0; nt < 4; nt++) {
            const int n0 = warp_n * 32 + nt * 8 + 2 * t4;
            const float xq0 = sm[n0], xq1 = sm[n0 + 1];
            float c00 = fmaxf(xp2a + xq0 - 2.f * acc[mt][nt][0], 0.f);
            float c01 = fmaxf(xp2a + xq1 - 2.f * acc[mt][nt][1], 0.f);
            float c10 = fmaxf(xp2b + xq0 - 2.f * acc[mt][nt][2], 0.f);
            float c11 = fmaxf(xp2b + xq1 - 2.f * acc[mt][nt][3], 0.f);
            maxcx = fmaxf(maxcx, fmaxf(fmaxf(c00, c01), fmaxf(c10, c11)));
            *reinterpret_cast<float2*>(&g_C[(size_t)(row0 + r1) * NN + col0 + n0]) = make_float2(c00, c01);
            *reinterpret_cast<float2*>(&g_C[(size_t)(row0 + r2) * NN + col0 + n0]) = make_float2(c10, c11);
        }
    }
#pragma unroll
    for (int o = 16; o > 0; o >>= 1) maxcx = fmaxf(maxcx, __shfl_xor_sync(0xffffffffu, maxcx, o));
    if (lane == 0) atomicMax(&g_max_cx, __float_as_uint(maxcx));

    // CY max over this 128x128 tile (K=10)
    {
        const int r = tid & 127;
        const int j0 = (tid >> 7) * 64;
        float ypv[NCLS];
#pragma unroll
        for (int d = 0; d < NCLS; d++) ypv[d] = sm[1536 + r * NCLS + d];
        const float yp2r = sm[2816 + r];
        float mx = 0.f;
        for (int j = j0; j < j0 + 64; j++) {
            float dot = 0.f;
#pragma unroll
            for (int d = 0; d < NCLS; d++) dot = fmaf(ypv[d], sm[256 + j * NCLS + d], dot);
            float cy = fmaxf(yp2r + sm[128 + j] - 2.f * dot, 0.f);
            mx = fmaxf(mx, cy);
        }
#pragma unroll
        for (int o = 16; o > 0; o >>= 1) mx = fmaxf(mx, __shfl_xor_sync(0xffffffffu, mx, o));
        if (lane == 0) atomicMax(&g_max_cy, __float_as_uint(mx));
    }
}

// ---------------- max(C) over all elements (C = CX + lw*CY on the fly) ----------------
__global__ void __launch_bounds__(256) k_maxc(const float* __restrict__ YP, const float* __restrict__ YQ) {
    __shared__ float YPs[16][NCLS];
    __shared__ float yp2s[16];
    const int i0 = blockIdx.x * 16;
    const int tid = threadIdx.x;
    if (tid < 16 * NCLS) { int r = tid / NCLS, c = tid - r * NCLS; YPs[r][c] = YP[(size_t)(i0 + r) * NCLS + c]; }
    if (tid < 16) yp2s[tid] = g_yp2[i0 + tid];
    __syncthreads();
    float cxm = __uint_as_float(g_max_cx);
    float cym = __uint_as_float(g_max_cy);
    float lw = (cym == 0.f) ? 0.f : cxm / cym;
    float localmax = 0.f;
    for (int j0 = tid * 4; j0 < NN; j0 += 1024) {
        float yq[4][NCLS], yq2[4];
#pragma unroll
        for (int c = 0; c < 4; c++) {
#pragma unroll
            for (int d = 0; d < NCLS; d += 2) {
                float2 t = __ldg(reinterpret_cast<const float2*>(&YQ[(size_t)(j0 + c) * NCLS + d]));
                yq[c][d] = t.x; yq[c][d + 1] = t.y;
            }
            yq2[c] = g_yq2[j0 + c];
        }
#pragma unroll
        for (int r = 0; r < 16; r++) {
            float4 cx = *reinterpret_cast<const float4*>(&g_C[(size_t)(i0 + r) * NN + j0]);
            float cxa[4] = {cx.x, cx.y, cx.z, cx.w};
#pragma unroll
            for (int c = 0; c < 4; c++) {
                float dot = 0.f;
#pragma unroll
                for (int d = 0; d < NCLS; d++) dot = fmaf(YPs[r][d], yq[c][d], dot);
                float cy = fmaxf(yp2s[r] + yq2[c] - 2.f * dot, 0.f);
                localmax = fmaxf(localmax, cxa[c] + lw * cy);
            }
        }
    }
#pragma unroll
    for (int o = 16; o > 0; o >>= 1)
        localmax = fmaxf(localmax, __shfl_xor_sync(0xffffffffu, localmax, o));
    if ((tid & 31) == 0) atomicMax(&g_max_c, __float_as_uint(localmax));
}

// ---------------- P' = 2^SHIFT * exp(-C/(reg*cmax)) as fp16 ----------------
__global__ void __launch_bounds__(256) k_exp(const float* __restrict__ YP, const float* __restrict__ YQ) {
    __shared__ float YPs[16][NCLS];
    __shared__ float yp2s[16];
    const int i0 = blockIdx.x * 16;
    const int tid = threadIdx.x;
    if (tid < 16 * NCLS) { int r = tid / NCLS, c = tid - r * NCLS; YPs[r][c] = YP[(size_t)(i0 + r) * NCLS + c]; }
    if (tid < 16) yp2s[tid] = g_yp2[i0 + tid];
    __syncthreads();
    float cxm = __uint_as_float(g_max_cx);
    float cym = __uint_as_float(g_max_cy);
    float lw = (cym == 0.f) ? 0.f : cxm / cym;
    float cmax = __uint_as_float(g_max_c);
    float sc = 1.4426950408889634f / (REG_E * cmax);
    for (int j0 = tid * 4; j0 < NN; j0 += 1024) {
        float yq[4][NCLS], yq2[4];
#pragma unroll
        for (int c = 0; c < 4; c++) {
#pragma unroll
            for (int d = 0; d < NCLS; d += 2) {
                float2 t = __ldg(reinterpret_cast<const float2*>(&YQ[(size_t)(j0 + c) * NCLS + d]));
                yq[c][d] = t.x; yq[c][d + 1] = t.y;
            }
            yq2[c] = g_yq2[j0 + c];
        }
#pragma unroll
        for (int r = 0; r < 16; r++) {
            float4 cx = *reinterpret_cast<const float4*>(&g_C[(size_t)(i0 + r) * NN + j0]);
            float cxa[4] = {cx.x, cx.y, cx.z, cx.w};
            float pv[4];
#pragma unroll
            for (int c = 0; c < 4; c++) {
                float dot = 0.f;
#pragma unroll
                for (int d = 0; d < NCLS; d++) dot = fmaf(YPs[r][d], yq[c][d], dot);
                float cy = fmaxf(yp2s[r] + yq2[c] - 2.f * dot, 0.f);
                float v = cxa[c] + lw * cy;
                pv[c] = fexp2(fmaf(-v, sc, SHIFT));
            }
            union { __half2 h[2]; uint2 u; } pk;
            pk.h[0] = __floats2half2_rn(pv[0], pv[1]);
            pk.h[1] = __floats2half2_rn(pv[2], pv[3]);
            *reinterpret_cast<uint2*>(&g_Ph[(size_t)(i0 + r) * NN + j0]) = pk.u;
        }
    }
}

// ---------------- Sinkhorn passes (fp16 P) ----------------
__global__ void __launch_bounds__(256) k_row() {
    __shared__ float ws[NN];
    const int tid = threadIdx.x;
    const int i0 = blockIdx.x * 8;
    const int wid = tid >> 5, lane = tid & 31;
    {
        const float4* W4 = reinterpret_cast<const float4*>(g_w);
        float4* S4 = reinterpret_cast<float4*>(ws);
#pragma unroll
        for (int k = 0; k < 8; k++) S4[tid + k * 256] = W4[tid + k * 256];
    }
    __syncthreads();
    const uint4* Pr = reinterpret_cast<const uint4*>(g_Ph + (size_t)(i0 + wid) * NN);
    float acc = 0.f;
#pragma unroll 4
    for (int c = lane; c < 1024; c += 32) {
        uint4 pv = Pr[c];
        float2 f0 = __half22float2(*reinterpret_cast<__half2*>(&pv.x));
        float2 f1 = __half22float2(*reinterpret_cast<__half2*>(&pv.y));
        float2 f2 = __half22float2(*reinterpret_cast<__half2*>(&pv.z));
        float2 f3 = __half22float2(*reinterpret_cast<__half2*>(&pv.w));
        float4 w0 = *reinterpret_cast<const float4*>(&ws[c * 8]);
        float4 w1 = *reinterpret_cast<const float4*>(&ws[c * 8 + 4]);
        acc = fmaf(f0.x, w0.x, acc); acc = fmaf(f0.y, w0.y, acc);
        acc = fmaf(f1.x, w0.z, acc); acc = fmaf(f1.y, w0.w, acc);
        acc = fmaf(f2.x, w1.x, acc); acc = fmaf(f2.y, w1.y, acc);
        acc = fmaf(f3.x, w1.z, acc); acc = fmaf(f3.y, w1.w, acc);
    }
#pragma unroll
    for (int o = 16; o > 0; o >>= 1) acc += __shfl_down_sync(0xffffffffu, acc, o);
    if (lane == 0) g_z[i0 + wid] = (1.0f / NN) / acc;
}

// partial column sums of P'^T @ z' : grid (4, 64), 128 rows per y-block
__global__ void __launch_bounds__(256) k_colpart() {
    __shared__ float zs[128];
    const int tid = threadIdx.x;
    const int c8 = blockIdx.x * 256 + tid;      // uint4 (8-col) chunk index 0..1023
    const int r0 = blockIdx.y * 128;
    if (tid < 128) zs[tid] = g_z[r0 + tid];
    __syncthreads();
    const uint4* P4 = reinterpret_cast<const uint4*>(g_Ph);
    float a0 = 0.f, a1 = 0.f, a2 = 0.f, a3 = 0.f, a4 = 0.f, a5 = 0.f, a6 = 0.f, a7 = 0.f;
#pragma unroll 4
    for (int r = 0; r < 128; r++) {
        float zz = zs[r];
        uint4 pv = P4[(size_t)(r0 + r) * 1024 + c8];
        float2 f0 = __half22float2(*reinterpret_cast<__half2*>(&pv.x));
        float2 f1 = __half22float2(*reinterpret_cast<__half2*>(&pv.y));
        float2 f2 = __half22float2(*reinterpret_cast<__half2*>(&pv.z));
        float2 f3 = __half22float2(*reinterpret_cast<__half2*>(&pv.w));
        a0 = fmaf(f0.x, zz, a0); a1 = fmaf(f0.y, zz, a1);
        a2 = fmaf(f1.x, zz, a2); a3 = fmaf(f1.y, zz, a3);
        a4 = fmaf(f2.x, zz, a4); a5 = fmaf(f2.y, zz, a5);
        a6 = fmaf(f3.x, zz, a6); a7 = fmaf(f3.y, zz, a7);
    }
    float4* G = reinterpret_cast<float4*>(g_part);
    G[(size_t)blockIdx.y * 2048 + c8 * 2]     = make_float4(a0, a1, a2, a3);
    G[(size_t)blockIdx.y * 2048 + c8 * 2 + 1] = make_float4(a4, a5, a6, a7);
}

// w = (1/M) / colsum  -- grid 32 (8192 threads, one per column), chunk-ordered
__global__ void __launch_bounds__(256) k_colred() {
    int j = blockIdx.x * 256 + threadIdx.x;   // column 0..8191
    float s = 0.f;
#pragma unroll 4
    for (int ch = 0; ch < 64; ch++) s += g_part[(size_t)ch * NN + j];
    g_w[j] = (1.0f / NN) / s;
}

// ---------------- final objective ----------------
__global__ void __launch_bounds__(256) k_final(const float* __restrict__ YP, const float* __restrict__ YQ) {
    __shared__ float YPs[16][NCLS];
    __shared__ float yp2s[16];
    __shared__ float zs[16];
    const int i0 = blockIdx.x * 16;
    const int tid = threadIdx.x;
    if (tid < 16 * NCLS) { int r = tid / NCLS, c = tid - r * NCLS; YPs[r][c] = YP[(size_t)(i0 + r) * NCLS + c]; }
    if (tid < 16) { yp2s[tid] = g_yp2[i0 + tid]; zs[tid] = g_z[i0 + tid] * SHIFT_MUL; }
    __syncthreads();
    float cxm = __uint_as_float(g_max_cx);
    float cym = __uint_as_float(g_max_cy);
    float lw = (cym == 0.f) ? 0.f : cxm / cym;
    float cmax = __uint_as_float(g_max_c);
    float sc = 1.4426950408889634f / (REG_E * cmax);
    float acc = 0.f;
    for (int j0 = tid * 4; j0 < NN; j0 += 1024) {
        float yq[4][NCLS], yq2[4];
#pragma unroll
        for (int c = 0; c < 4; c++) {
#pragma unroll
            for (int d = 0; d < NCLS; d += 2) {
                float2 t = __ldg(reinterpret_cast<const float2*>(&YQ[(size_t)(j0 + c) * NCLS + d]));
                yq[c][d] = t.x; yq[c][d + 1] = t.y;
            }
            yq2[c] = g_yq2[j0 + c];
        }
        float4 wv = *reinterpret_cast<const float4*>(&g_w[j0]);
        float wa[4] = {wv.x, wv.y, wv.z, wv.w};
#pragma unroll
        for (int r = 0; r < 16; r++) {
            float4 cx = *reinterpret_cast<const float4*>(&g_C[(size_t)(i0 + r) * NN + j0]);
            float cxa[4] = {cx.x, cx.y, cx.z, cx.w};
            float zi = zs[r];
#pragma unroll
            for (int c = 0; c < 4; c++) {
                float dot = 0.f;
#pragma unroll
                for (int d = 0; d < NCLS; d++) dot = fmaf(YPs[r][d], yq[c][d], dot);
                float cy = fmaxf(yp2s[r] + yq2[c] - 2.f * dot, 0.f);
                float v = cxa[c] + lw * cy;
                float p = fexp2(-v * sc);
                acc = fmaf(v * p, zi * wa[c], acc);
            }
        }
    }
    acc = blockReduceSum(acc);
    if (tid == 0) g_bpart[blockIdx.x] = acc;
}

__global__ void __launch_bounds__(256) k_finalred(float* out) {
    double s = 0.0;
    for (int t = threadIdx.x; t < 512; t += 256) s += (double)g_bpart[t];
    s = blockReduceSumD(s);
    if (threadIdx.x == 0) out[0] = (float)s;
}

// ---------------- launch ----------------
extern "C" void kernel_launch(void* const* d_in, const int* in_sizes, int n_in,
                              void* d_out, int out_size) {
    const float* XQ = (const float*)d_in[0];   // (8192, 512)
    const float* YQ = (const float*)d_in[1];   // (8192, 10)
    const float* XP = (const float*)d_in[2];   // (8192, 512)
    const float* YP = (const float*)d_in[3];   // (8192, 10)
    float* out = (float*)d_out;

    cudaFuncSetAttribute(k_gemm_mma, cudaFuncAttributeMaxDynamicSharedMemorySize, SMEM_GEMM);

    k_init<<<32, 256>>>();
    k_norm512<<<dim3(NN, 2), 128>>>(XP, XQ);
    k_norm10<<<32, 256>>>(YP, YQ);
    k_split<<<dim3(512, 2), 256>>>(XP, XQ);

    k_gemm_mma<<<dim3(64, 64), 256, SMEM_GEMM>>>(YP, YQ);
    k_maxc<<<NN / 16, 256>>>(YP, YQ);
    k_exp<<<NN / 16, 256>>>(YP, YQ);

    for (int it = 0; it < NIT; it++) {
        k_row<<<NN / 8, 256>>>();
        k_colpart<<<dim3(4, 64), 256>>>();
        k_colred<<<32, 256>>>();
    }

    k_final<<<NN / 16, 256>>>(YP, YQ);
    k_finalred<<<1, 256>>>(out);
}

// round 11
// speedup vs baseline: 2.0528x; 1.1500x over previous
#include <cuda_runtime.h>
#include <cuda_fp16.h>
#include <cstdint>

// Problem constants
#define NN   8192
#define DD   512
#define NCLS 10
#define REG_E 0.05f
#define NIT  20
#define SHIFT 15.0f          // exp2 shift for fp16 P storage
#define SHIFT_MUL 32768.0f   // 2^15

static constexpr size_t NN2 = (size_t)NN * (size_t)NN;

// ---------------- scratch (device globals; no allocation) ----------------
static __device__ __half g_Ch[NN2];           // 128 MiB: CX (fp16)
static __device__ __half g_Ph[NN2];           // 128 MiB: P' = 2^15 * exp(-C/(reg*cmax))
static __device__ __half g_Ah[NN * DD];       // XP fp16 (hi)
static __device__ __half g_Bh[NN * DD];       // XQ fp16 (hi)
static __device__ float g_xp2[NN], g_xq2[NN], g_yp2[NN], g_yq2[NN];
static __device__ float g_z[NN], g_w[NN];
static __device__ float g_part[64 * NN];      // column-pass partials (2 MB)
static __device__ float g_bpart[512];         // final reduction partials
static __device__ unsigned g_max_cx, g_max_cy, g_max_c;

// ---------------- generic helpers ----------------
__device__ __forceinline__ float blockReduceSum(float v) {
    __shared__ float red[32];
    unsigned lane = threadIdx.x & 31u, wid = threadIdx.x >> 5;
#pragma unroll
    for (int o = 16; o > 0; o >>= 1) v += __shfl_down_sync(0xffffffffu, v, o);
    if (lane == 0) red[wid] = v;
    __syncthreads();
    int nw = (blockDim.x + 31) >> 5;
    v = (threadIdx.x < (unsigned)nw) ? red[threadIdx.x] : 0.f;
    if (wid == 0) {
#pragma unroll
        for (int o = 16; o > 0; o >>= 1) v += __shfl_down_sync(0xffffffffu, v, o);
    }
    return v;  // valid in thread 0
}

__device__ __forceinline__ double blockReduceSumD(double v) {
    __shared__ double redd[32];
    unsigned lane = threadIdx.x & 31u, wid = threadIdx.x >> 5;
#pragma unroll
    for (int o = 16; o > 0; o >>= 1) v += __shfl_down_sync(0xffffffffu, v, o);
    if (lane == 0) redd[wid] = v;
    __syncthreads();
    int nw = (blockDim.x + 31) >> 5;
    v = (threadIdx.x < (unsigned)nw) ? redd[threadIdx.x] : 0.0;
    if (wid == 0) {
#pragma unroll
        for (int o = 16; o > 0; o >>= 1) v += __shfl_down_sync(0xffffffffu, v, o);
    }
    return v;
}

// fast exp2 for y in [-30, 16]; FMA-only (no MUFU). rel err ~1e-7.
__device__ __forceinline__ float fexp2(float y) {
    float fk = y + 12582912.0f;
    int   k  = __float_as_int(fk) - 0x4B400000;
    float r  = y - (fk - 12582912.0f);
    float p  = 1.5403530e-4f;
    p = fmaf(p, r, 1.3333558e-3f);
    p = fmaf(p, r, 9.6181291e-3f);
    p = fmaf(p, r, 5.5504109e-2f);
    p = fmaf(p, r, 2.4022651e-1f);
    p = fmaf(p, r, 6.9314718e-1f);
    p = fmaf(p, r, 1.0f);
    return p * __int_as_float((k + 127) << 23);
}

// ---------------- mma / cp.async helpers (sm_80+ PTX, works on plain sm_100) ----
__device__ __forceinline__ void mma_f16(float* d, const uint32_t* a, const uint32_t* b) {
    asm volatile(
        "mma.sync.aligned.m16n8k16.row.col.f32.f16.f16.f32 "
        "{%0,%1,%2,%3}, {%4,%5,%6,%7}, {%8,%9}, {%0,%1,%2,%3};"
        : "+f"(d[0]), "+f"(d[1]), "+f"(d[2]), "+f"(d[3])
        : "r"(a[0]), "r"(a[1]), "r"(a[2]), "r"(a[3]), "r"(b[0]), "r"(b[1]));
}
__device__ __forceinline__ uint32_t smem_u32(const void* p) {
    uint32_t a;
    asm("{ .reg .u64 t; cvta.to.shared.u64 t, %1; cvt.u32.u64 %0, t; }" : "=r"(a) : "l"(p));
    return a;
}
#define CP_ASYNC16(dst, src) \
    asm volatile("cp.async.cg.shared.global [%0], [%1], 16;" :: "r"(dst), "l"(src) : "memory")
#define CP_COMMIT() asm volatile("cp.async.commit_group;" ::: "memory")
#define CP_WAIT0()  asm volatile("cp.async.wait_group 0;" ::: "memory")

// fp16 C decode: 4 cols from a uint2
__device__ __forceinline__ void dec_c4(uint2 cu, float* c) {
    float2 a = __half22float2(*reinterpret_cast<__half2*>(&cu.x));
    float2 b = __half22float2(*reinterpret_cast<__half2*>(&cu.y));
    c[0] = a.x; c[1] = a.y; c[2] = b.x; c[3] = b.y;
}

// ---------------- small kernels ----------------
__global__ void k_init() {
    int t = blockIdx.x * blockDim.x + threadIdx.x;
    if (t == 0) { g_max_cx = 0u; g_max_cy = 0u; g_max_c = 0u; }
    if (t < NN) g_w[t] = 1.0f;
}

__global__ void k_norm512(const float* __restrict__ XP, const float* __restrict__ XQ) {
    int i = blockIdx.x;
    const float* X = blockIdx.y ? XQ : XP;
    float4 v = reinterpret_cast<const float4*>(X)[(size_t)i * (DD / 4) + threadIdx.x];
    float s = v.x * v.x + v.y * v.y + v.z * v.z + v.w * v.w;
    s = blockReduceSum(s);
    if (threadIdx.x == 0) (blockIdx.y ? g_xq2 : g_xp2)[i] = s;
}

__global__ void k_norm10(const float* __restrict__ YP, const float* __restrict__ YQ) {
    int i = blockIdx.x * blockDim.x + threadIdx.x;
    if (i < NN) {
        float sp = 0.f, sq = 0.f;
#pragma unroll
        for (int c = 0; c < NCLS; c++) {
            float tp = YP[(size_t)i * NCLS + c];
            float tq = YQ[(size_t)i * NCLS + c];
            sp += tp * tp; sq += tq * tq;
        }
        g_yp2[i] = sp; g_yq2[i] = sq;
    }
}

// convert X to fp16 planes (rn)
__global__ void __launch_bounds__(256) k_split(const float* __restrict__ XP, const float* __restrict__ XQ) {
    const float4* src = reinterpret_cast<const float4*>(blockIdx.y ? XQ : XP);
    __half* Hh = blockIdx.y ? g_Bh : g_Ah;
    int n4 = NN * DD / 4;
    for (int i = blockIdx.x * 256 + threadIdx.x; i < n4; i += gridDim.x * 256) {
        float4 v = src[i];
        union { __half2 h[2]; uint2 u; } ph;
        ph.h[0] = __floats2half2_rn(v.x, v.y);
        ph.h[1] = __floats2half2_rn(v.z, v.w);
        reinterpret_cast<uint2*>(Hh)[i] = ph.u;
    }
}

// ---------------- single-pass FP16 mma.sync GEMM: CX tile + maxCX/maxCY ----------
// CTA tile 128x128, 8 warps (2x4), warp tile 64x32 (4x4 m16n8k16 tiles).
// D = Ah * Bh (cross terms dropped; dCX sigma ~0.013 abs on CX~1000 -> negligible).
#define ROWW 20                           // words per row (32 halves + pad)
#define PLANE_B (128 * ROWW * 4)          // bytes per plane: 10240
#define BUF_B (2 * PLANE_B)               // planes Ah, Bh: 20480
#define SMEM_GEMM (2 * BUF_B)             // 40960

__global__ void __launch_bounds__(256, 2)
k_gemm_mma(const float* __restrict__ YPg, const float* __restrict__ YQg) {
    extern __shared__ float sm[];
    const int tid = threadIdx.x;
    const int wid = tid >> 5, lane = tid & 31;
    const int warp_m = wid >> 2, warp_n = wid & 3;
    const int g = lane >> 2, t4 = lane & 3;
    const int row0 = blockIdx.y * 128;
    const int col0 = blockIdx.x * 128;

    const uint32_t smb = smem_u32(sm);

    float acc[4][4][4];
#pragma unroll
    for (int mt = 0; mt < 4; mt++)
#pragma unroll
        for (int nt = 0; nt < 4; nt++)
#pragma unroll
            for (int q = 0; q < 4; q++) acc[mt][nt][q] = 0.f;

    // cp.async chunk ch into buffer buf (1024 16B-chunks, 4 per thread)
    auto issue = [&](int ch, int buf) {
        const uint32_t base = smb + (uint32_t)buf * BUF_B;
#pragma unroll
        for (int q = 0; q < 4; q++) {
            int idx = tid + q * 256;          // 0..1023
            int plane = idx >> 9;             // 0=Ah,1=Bh
            int r = (idx >> 2) & 127;
            int c16 = idx & 3;
            uint32_t dst = base + (uint32_t)plane * PLANE_B + (uint32_t)(r * 80 + c16 * 16);
            const __half* gp = plane ? g_Bh : g_Ah;
            int rg = (plane ? col0 : row0) + r;
            const __half* src = gp + (size_t)rg * DD + ch * 32 + c16 * 8;
            CP_ASYNC16(dst, src);
        }
        CP_COMMIT();
    };

    issue(0, 0);
    for (int ch = 0; ch < 16; ch++) {
        const int buf = ch & 1;
        CP_WAIT0();
        __syncthreads();
        if (ch < 15) issue(ch + 1, buf ^ 1);
        const uint32_t* Ah = reinterpret_cast<const uint32_t*>(sm) + buf * (BUF_B / 4);
        const uint32_t* Bh = Ah + PLANE_B / 4;
#pragma unroll
        for (int kk = 0; kk < 2; kk++) {
            const int kbw = kk * 8;           // word offset of this k16 block
            uint32_t ah[4][4];
#pragma unroll
            for (int mt = 0; mt < 4; mt++) {
                int base = (warp_m * 64 + mt * 16 + g) * ROWW + kbw + t4;
                ah[mt][0] = Ah[base];       ah[mt][1] = Ah[base + 8 * ROWW];
                ah[mt][2] = Ah[base + 4];   ah[mt][3] = Ah[base + 8 * ROWW + 4];
            }
            uint32_t bh[4][2];
#pragma unroll
            for (int nt = 0; nt < 4; nt++) {
                int base = (warp_n * 32 + nt * 8 + g) * ROWW + kbw + t4;
                bh[nt][0] = Bh[base];  bh[nt][1] = Bh[base + 4];
            }
#pragma unroll
            for (int mt = 0; mt < 4; mt++)
#pragma unroll
                for (int nt = 0; nt < 4; nt++)
                    mma_f16(acc[mt][nt], ah[mt], bh[nt]);
        }
        __syncthreads();
    }

    // ---- epilogue staging (reuse smem) ----
    if (tid < 128) {
        sm[tid]        = g_xq2[col0 + tid];
        sm[128 + tid]  = g_yq2[col0 + tid];
        sm[2816 + tid] = g_yp2[row0 + tid];
    }
    for (int i = tid; i < 128 * NCLS; i += 256) {
        sm[256 + i]  = YQg[(size_t)col0 * NCLS + i];
        sm[1536 + i] = YPg[(size_t)row0 * NCLS + i];
    }
    __syncthreads();

    // CX epilogue (fp16 store) + maxCX on quantized values
    float maxcx = 0.f;
#pragma unroll
    for (int mt = 0; mt < 4; mt++) {
        const int r1 = warp_m * 64 + mt * 16 + g;
        const int r2 = r1 + 8;
        const float xp2a = g_xp2[row0 + r1];
        const float xp2b = g_xp2[row0 + r2];
#pragma unroll
        for (int nt = 0; nt < 4; nt++) {
            const int n0 = warp_n * 32 + nt * 8 + 2 * t4;
            const float xq0 = sm[n0], xq1 = sm[n0 + 1];
            float c00 = fmaxf(xp2a + xq0 - 2.f * acc[mt][nt][0], 0.f);
            float c01 = fmaxf(xp2a + xq1 - 2.f * acc[mt][nt][1], 0.f);
            float c10 = fmaxf(xp2b + xq0 - 2.f * acc[mt][nt][2], 0.f);
            float c11 = fmaxf(xp2b + xq1 - 2.f * acc[mt][nt][3], 0.f);
            __half2 h0 = __floats2half2_rn(c00, c01);
            __half2 h1 = __floats2half2_rn(c10, c11);
            *reinterpret_cast<__half2*>(&g_Ch[(size_t)(row0 + r1) * NN + col0 + n0]) = h0;
            *reinterpret_cast<__half2*>(&g_Ch[(size_t)(row0 + r2) * NN + col0 + n0]) = h1;
            float2 q0 = __half22float2(h0);
            float2 q1 = __half22float2(h1);
            maxcx = fmaxf(maxcx, fmaxf(fmaxf(q0.x, q0.y), fmaxf(q1.x, q1.y)));
        }
    }
#pragma unroll
    for (int o = 16; o > 0; o >>= 1) maxcx = fmaxf(maxcx, __shfl_xor_sync(0xffffffffu, maxcx, o));
    if (lane == 0) atomicMax(&g_max_cx, __float_as_uint(maxcx));

    // CY max over this 128x128 tile (K=10)
    {
        const int r = tid & 127;
        const int j0 = (tid >> 7) * 64;
        float ypv[NCLS];
#pragma unroll
        for (int d = 0; d < NCLS; d++) ypv[d] = sm[1536 + r * NCLS + d];
        const float yp2r = sm[2816 + r];
        float mx = 0.f;
        for (int j = j0; j < j0 + 64; j++) {
            float dot = 0.f;
#pragma unroll
            for (int d = 0; d < NCLS; d++) dot = fmaf(ypv[d], sm[256 + j * NCLS + d], dot);
            float cy = fmaxf(yp2r + sm[128 + j] - 2.f * dot, 0.f);
            mx = fmaxf(mx, cy);
        }
#pragma unroll
        for (int o = 16; o > 0; o >>= 1) mx = fmaxf(mx, __shfl_xor_sync(0xffffffffu, mx, o));
        if (lane == 0) atomicMax(&g_max_cy, __float_as_uint(mx));
    }
}

// ---------------- max(C) over all elements (C = CX + lw*CY on the fly) ----------------
__global__ void __launch_bounds__(256) k_maxc(const float* __restrict__ YP, const float* __restrict__ YQ) {
    __shared__ float YPs[16][NCLS];
    __shared__ float yp2s[16];
    const int i0 = blockIdx.x * 16;
    const int tid = threadIdx.x;
    if (tid < 16 * NCLS) { int r = tid / NCLS, c = tid - r * NCLS; YPs[r][c] = YP[(size_t)(i0 + r) * NCLS + c]; }
    if (tid < 16) yp2s[tid] = g_yp2[i0 + tid];
    __syncthreads();
    float cxm = __uint_as_float(g_max_cx);
    float cym = __uint_as_float(g_max_cy);
    float lw = (cym == 0.f) ? 0.f : cxm / cym;
    float localmax = 0.f;
    for (int j0 = tid * 4; j0 < NN; j0 += 1024) {
        float yq[4][NCLS], yq2[4];
#pragma unroll
        for (int c = 0; c < 4; c++) {
#pragma unroll
            for (int d = 0; d < NCLS; d += 2) {
                float2 t = __ldg(reinterpret_cast<const float2*>(&YQ[(size_t)(j0 + c) * NCLS + d]));
                yq[c][d] = t.x; yq[c][d + 1] = t.y;
            }
            yq2[c] = g_yq2[j0 + c];
        }
#pragma unroll
        for (int r = 0; r < 16; r++) {
            uint2 cu = *reinterpret_cast<const uint2*>(&g_Ch[(size_t)(i0 + r) * NN + j0]);
            float cxa[4]; dec_c4(cu, cxa);
#pragma unroll
            for (int c = 0; c < 4; c++) {
                float dot = 0.f;
#pragma unroll
                for (int d = 0; d < NCLS; d++) dot = fmaf(YPs[r][d], yq[c][d], dot);
                float cy = fmaxf(yp2s[r] + yq2[c] - 2.f * dot, 0.f);
                localmax = fmaxf(localmax, cxa[c] + lw * cy);
            }
        }
    }
#pragma unroll
    for (int o = 16; o > 0; o >>= 1)
        localmax = fmaxf(localmax, __shfl_xor_sync(0xffffffffu, localmax, o));
    if ((tid & 31) == 0) atomicMax(&g_max_c, __float_as_uint(localmax));
}

// ---------------- P' = 2^SHIFT * exp(-C/(reg*cmax)) as fp16 ----------------
__global__ void __launch_bounds__(256) k_exp(const float* __restrict__ YP, const float* __restrict__ YQ) {
    __shared__ float YPs[16][NCLS];
    __shared__ float yp2s[16];
    const int i0 = blockIdx.x * 16;
    const int tid = threadIdx.x;
    if (tid < 16 * NCLS) { int r = tid / NCLS, c = tid - r * NCLS; YPs[r][c] = YP[(size_t)(i0 + r) * NCLS + c]; }
    if (tid < 16) yp2s[tid] = g_yp2[i0 + tid];
    __syncthreads();
    float cxm = __uint_as_float(g_max_cx);
    float cym = __uint_as_float(g_max_cy);
    float lw = (cym == 0.f) ? 0.f : cxm / cym;
    float cmax = __uint_as_float(g_max_c);
    float sc = 1.4426950408889634f / (REG_E * cmax);
    for (int j0 = tid * 4; j0 < NN; j0 += 1024) {
        float yq[4][NCLS], yq2[4];
#pragma unroll
        for (int c = 0; c < 4; c++) {
#pragma unroll
            for (int d = 0; d < NCLS; d += 2) {
                float2 t = __ldg(reinterpret_cast<const float2*>(&YQ[(size_t)(j0 + c) * NCLS + d]));
                yq[c][d] = t.x; yq[c][d + 1] = t.y;
            }
            yq2[c] = g_yq2[j0 + c];
        }
#pragma unroll
        for (int r = 0; r < 16; r++) {
            uint2 cu = *reinterpret_cast<const uint2*>(&g_Ch[(size_t)(i0 + r) * NN + j0]);
            float cxa[4]; dec_c4(cu, cxa);
            float pv[4];
#pragma unroll
            for (int c = 0; c < 4; c++) {
                float dot = 0.f;
#pragma unroll
                for (int d = 0; d < NCLS; d++) dot = fmaf(YPs[r][d], yq[c][d], dot);
                float cy = fmaxf(yp2s[r] + yq2[c] - 2.f * dot, 0.f);
                float v = cxa[c] + lw * cy;
                pv[c] = fexp2(fmaf(-v, sc, SHIFT));
            }
            union { __half2 h[2]; uint2 u; } pk;
            pk.h[0] = __floats2half2_rn(pv[0], pv[1]);
            pk.h[1] = __floats2half2_rn(pv[2], pv[3]);
            *reinterpret_cast<uint2*>(&g_Ph[(size_t)(i0 + r) * NN + j0]) = pk.u;
        }
    }
}

// ---------------- Sinkhorn passes (fp16 P) ----------------
__global__ void __launch_bounds__(256) k_row() {
    __shared__ float ws[NN];
    const int tid = threadIdx.x;
    const int i0 = blockIdx.x * 8;
    const int wid = tid >> 5, lane = tid & 31;
    {
        const float4* W4 = reinterpret_cast<const float4*>(g_w);
        float4* S4 = reinterpret_cast<float4*>(ws);
#pragma unroll
        for (int k = 0; k < 8; k++) S4[tid + k * 256] = W4[tid + k * 256];
    }
    __syncthreads();
    const uint4* Pr = reinterpret_cast<const uint4*>(g_Ph + (size_t)(i0 + wid) * NN);
    float acc0 = 0.f, acc1 = 0.f;
#pragma unroll 4
    for (int c = lane; c < 1024; c += 32) {
        uint4 pv = Pr[c];
        float2 f0 = __half22float2(*reinterpret_cast<__half2*>(&pv.x));
        float2 f1 = __half22float2(*reinterpret_cast<__half2*>(&pv.y));
        float2 f2 = __half22float2(*reinterpret_cast<__half2*>(&pv.z));
        float2 f3 = __half22float2(*reinterpret_cast<__half2*>(&pv.w));
        float4 w0 = *reinterpret_cast<const float4*>(&ws[c * 8]);
        float4 w1 = *reinterpret_cast<const float4*>(&ws[c * 8 + 4]);
        acc0 = fmaf(f0.x, w0.x, acc0); acc1 = fmaf(f0.y, w0.y, acc1);
        acc0 = fmaf(f1.x, w0.z, acc0); acc1 = fmaf(f1.y, w0.w, acc1);
        acc0 = fmaf(f2.x, w1.x, acc0); acc1 = fmaf(f2.y, w1.y, acc1);
        acc0 = fmaf(f3.x, w1.z, acc0); acc1 = fmaf(f3.y, w1.w, acc1);
    }
    float acc = acc0 + acc1;
#pragma unroll
    for (int o = 16; o > 0; o >>= 1) acc += __shfl_down_sync(0xffffffffu, acc, o);
    if (lane == 0) g_z[i0 + wid] = (1.0f / NN) / acc;
}

// partial column sums of P'^T @ z' : grid (4, 64), 128 rows per y-block
__global__ void __launch_bounds__(256) k_colpart() {
    __shared__ float zs[128];
    const int tid = threadIdx.x;
    const int c8 = blockIdx.x * 256 + tid;      // uint4 (8-col) chunk index 0..1023
    const int r0 = blockIdx.y * 128;
    if (tid < 128) zs[tid] = g_z[r0 + tid];
    __syncthreads();
    const uint4* P4 = reinterpret_cast<const uint4*>(g_Ph);
    float a0 = 0.f, a1 = 0.f, a2 = 0.f, a3 = 0.f, a4 = 0.f, a5 = 0.f, a6 = 0.f, a7 = 0.f;
#pragma unroll 4
    for (int r = 0; r < 128; r++) {
        float zz = zs[r];
        uint4 pv = P4[(size_t)(r0 + r) * 1024 + c8];
        float2 f0 = __half22float2(*reinterpret_cast<__half2*>(&pv.x));
        float2 f1 = __half22float2(*reinterpret_cast<__half2*>(&pv.y));
        float2 f2 = __half22float2(*reinterpret_cast<__half2*>(&pv.z));
        float2 f3 = __half22float2(*reinterpret_cast<__half2*>(&pv.w));
        a0 = fmaf(f0.x, zz, a0); a1 = fmaf(f0.y, zz, a1);
        a2 = fmaf(f1.x, zz, a2); a3 = fmaf(f1.y, zz, a3);
        a4 = fmaf(f2.x, zz, a4); a5 = fmaf(f2.y, zz, a5);
        a6 = fmaf(f3.x, zz, a6); a7 = fmaf(f3.y, zz, a7);
    }
    float4* G = reinterpret_cast<float4*>(g_part);
    G[(size_t)blockIdx.y * 2048 + c8 * 2]     = make_float4(a0, a1, a2, a3);
    G[(size_t)blockIdx.y * 2048 + c8 * 2 + 1] = make_float4(a4, a5, a6, a7);
}

// w = (1/M) / colsum  -- grid 32 (8192 threads, one per column), chunk-ordered
__global__ void __launch_bounds__(256) k_colred() {
    int j = blockIdx.x * 256 + threadIdx.x;   // column 0..8191
    float s = 0.f;
#pragma unroll 4
    for (int ch = 0; ch < 64; ch++) s += g_part[(size_t)ch * NN + j];
    g_w[j] = (1.0f / NN) / s;
}

// ---------------- final objective ----------------
__global__ void __launch_bounds__(256) k_final(const float* __restrict__ YP, const float* __restrict__ YQ) {
    __shared__ float YPs[16][NCLS];
    __shared__ float yp2s[16];
    __shared__ float zs[16];
    const int i0 = blockIdx.x * 16;
    const int tid = threadIdx.x;
    if (tid < 16 * NCLS) { int r = tid / NCLS, c = tid - r * NCLS; YPs[r][c] = YP[(size_t)(i0 + r) * NCLS + c]; }
    if (tid < 16) { yp2s[tid] = g_yp2[i0 + tid]; zs[tid] = g_z[i0 + tid] * SHIFT_MUL; }
    __syncthreads();
    float cxm = __uint_as_float(g_max_cx);
    float cym = __uint_as_float(g_max_cy);
    float lw = (cym == 0.f) ? 0.f : cxm / cym;
    float cmax = __uint_as_float(g_max_c);
    float sc = 1.4426950408889634f / (REG_E * cmax);
    float acc = 0.f;
    for (int j0 = tid * 4; j0 < NN; j0 += 1024) {
        float yq[4][NCLS], yq2[4];
#pragma unroll
        for (int c = 0; c < 4; c++) {
#pragma unroll
            for (int d = 0; d < NCLS; d += 2) {
                float2 t = __ldg(reinterpret_cast<const float2*>(&YQ[(size_t)(j0 + c) * NCLS + d]));
                yq[c][d] = t.x; yq[c][d + 1] = t.y;
            }
            yq2[c] = g_yq2[j0 + c];
        }
        float4 wv = *reinterpret_cast<const float4*>(&g_w[j0]);
        float wa[4] = {wv.x, wv.y, wv.z, wv.w};
#pragma unroll
        for (int r = 0; r < 16; r++) {
            uint2 cu = *reinterpret_cast<const uint2*>(&g_Ch[(size_t)(i0 + r) * NN + j0]);
            float cxa[4]; dec_c4(cu, cxa);
            float zi = zs[r];
#pragma unroll
            for (int c = 0; c < 4; c++) {
                float dot = 0.f;
#pragma unroll
                for (int d = 0; d < NCLS; d++) dot = fmaf(YPs[r][d], yq[c][d], dot);
                float cy = fmaxf(yp2s[r] + yq2[c] - 2.f * dot, 0.f);
                float v = cxa[c] + lw * cy;
                float p = fexp2(-v * sc);
                acc = fmaf(v * p, zi * wa[c], acc);
            }
        }
    }
    acc = blockReduceSum(acc);
    if (tid == 0) g_bpart[blockIdx.x] = acc;
}

__global__ void __launch_bounds__(256) k_finalred(float* out) {
    double s = 0.0;
    for (int t = threadIdx.x; t < 512; t += 256) s += (double)g_bpart[t];
    s = blockReduceSumD(s);
    if (threadIdx.x == 0) out[0] = (float)s;
}

// ---------------- launch ----------------
extern "C" void kernel_launch(void* const* d_in, const int* in_sizes, int n_in,
                              void* d_out, int out_size) {
    const float* XQ = (const float*)d_in[0];   // (8192, 512)
    const float* YQ = (const float*)d_in[1];   // (8192, 10)
    const float* XP = (const float*)d_in[2];   // (8192, 512)
    const float* YP = (const float*)d_in[3];   // (8192, 10)
    float* out = (float*)d_out;

    cudaFuncSetAttribute(k_gemm_mma, cudaFuncAttributeMaxDynamicSharedMemorySize, SMEM_GEMM);

    k_init<<<32, 256>>>();
    k_norm512<<<dim3(NN, 2), 128>>>(XP, XQ);
    k_norm10<<<32, 256>>>(YP, YQ);
    k_split<<<dim3(512, 2), 256>>>(XP, XQ);

    k_gemm_mma<<<dim3(64, 64), 256, SMEM_GEMM>>>(YP, YQ);
    k_maxc<<<NN / 16, 256>>>(YP, YQ);
    k_exp<<<NN / 16, 256>>>(YP, YQ);

    for (int it = 0; it < NIT; it++) {
        k_row<<<NN / 8, 256>>>();
        k_colpart<<<dim3(4, 64), 256>>>();
        k_colred<<<32, 256>>>();
    }

    k_final<<<NN / 16, 256>>>(YP, YQ);
    k_finalred<<<1, 256>>>(out);
}

// round 12
// speedup vs baseline: 2.4369x; 1.1871x over previous
#include <cuda_runtime.h>
#include <cuda_fp16.h>
#include <cstdint>

// Problem constants
#define NN   8192
#define DD   512
#define NCLS 10
#define REG_E 0.05f
#define NIT  20
#define SHIFT 15.0f          // exp2 shift for fp16 P storage
#define SHIFT_MUL 32768.0f   // 2^15

static constexpr size_t NN2 = (size_t)NN * (size_t)NN;

// ---------------- scratch (device globals; no allocation) ----------------
static __device__ __half g_Ch[NN2];           // 128 MiB: CX (fp16)
static __device__ __half g_Ph[NN2];           // 128 MiB: P' = 2^15 * exp(-C/(reg*cmax))
static __device__ __half g_Ah[NN * DD];       // XP fp16
static __device__ __half g_Bh[NN * DD];       // XQ fp16
static __device__ float g_xp2[NN], g_xq2[NN], g_yp2[NN], g_yq2[NN];
static __device__ float g_z[NN], g_w[NN];
static __device__ float g_part[256 * NN];     // column partials (8 MB)
static __device__ float g_bpart[512];         // final reduction partials
static __device__ unsigned g_max_cx, g_max_cy, g_max_c;

// ---------------- generic helpers ----------------
__device__ __forceinline__ float blockReduceSum(float v) {
    __shared__ float red[32];
    unsigned lane = threadIdx.x & 31u, wid = threadIdx.x >> 5;
#pragma unroll
    for (int o = 16; o > 0; o >>= 1) v += __shfl_down_sync(0xffffffffu, v, o);
    if (lane == 0) red[wid] = v;
    __syncthreads();
    int nw = (blockDim.x + 31) >> 5;
    v = (threadIdx.x < (unsigned)nw) ? red[threadIdx.x] : 0.f;
    if (wid == 0) {
#pragma unroll
        for (int o = 16; o > 0; o >>= 1) v += __shfl_down_sync(0xffffffffu, v, o);
    }
    return v;  // valid in thread 0
}

__device__ __forceinline__ double blockReduceSumD(double v) {
    __shared__ double redd[32];
    unsigned lane = threadIdx.x & 31u, wid = threadIdx.x >> 5;
#pragma unroll
    for (int o = 16; o > 0; o >>= 1) v += __shfl_down_sync(0xffffffffu, v, o);
    if (lane == 0) redd[wid] = v;
    __syncthreads();
    int nw = (blockDim.x + 31) >> 5;
    v = (threadIdx.x < (unsigned)nw) ? redd[threadIdx.x] : 0.0;
    if (wid == 0) {
#pragma unroll
        for (int o = 16; o > 0; o >>= 1) v += __shfl_down_sync(0xffffffffu, v, o);
    }
    return v;
}

// fast exp2 for y in [-30, 16]; FMA-only (no MUFU). rel err ~1e-7.
__device__ __forceinline__ float fexp2(float y) {
    float fk = y + 12582912.0f;
    int   k  = __float_as_int(fk) - 0x4B400000;
    float r  = y - (fk - 12582912.0f);
    float p  = 1.5403530e-4f;
    p = fmaf(p, r, 1.3333558e-3f);
    p = fmaf(p, r, 9.6181291e-3f);
    p = fmaf(p, r, 5.5504109e-2f);
    p = fmaf(p, r, 2.4022651e-1f);
    p = fmaf(p, r, 6.9314718e-1f);
    p = fmaf(p, r, 1.0f);
    return p * __int_as_float((k + 127) << 23);
}

// ---------------- mma / cp.async helpers (sm_80+ PTX, works on plain sm_100) ----
__device__ __forceinline__ void mma_f16(float* d, const uint32_t* a, const uint32_t* b) {
    asm volatile(
        "mma.sync.aligned.m16n8k16.row.col.f32.f16.f16.f32 "
        "{%0,%1,%2,%3}, {%4,%5,%6,%7}, {%8,%9}, {%0,%1,%2,%3};"
        : "+f"(d[0]), "+f"(d[1]), "+f"(d[2]), "+f"(d[3])
        : "r"(a[0]), "r"(a[1]), "r"(a[2]), "r"(a[3]), "r"(b[0]), "r"(b[1]));
}
__device__ __forceinline__ uint32_t smem_u32(const void* p) {
    uint32_t a;
    asm("{ .reg .u64 t; cvta.to.shared.u64 t, %1; cvt.u32.u64 %0, t; }" : "=r"(a) : "l"(p));
    return a;
}
#define CP_ASYNC16(dst, src) \
    asm volatile("cp.async.cg.shared.global [%0], [%1], 16;" :: "r"(dst), "l"(src) : "memory")
#define CP_COMMIT() asm volatile("cp.async.commit_group;" ::: "memory")
#define CP_WAIT0()  asm volatile("cp.async.wait_group 0;" ::: "memory")

// fp16 C decode: 4 cols from a uint2
__device__ __forceinline__ void dec_c4(uint2 cu, float* c) {
    float2 a = __half22float2(*reinterpret_cast<__half2*>(&cu.x));
    float2 b = __half22float2(*reinterpret_cast<__half2*>(&cu.y));
    c[0] = a.x; c[1] = a.y; c[2] = b.x; c[3] = b.y;
}
// 8 halves from uint4
__device__ __forceinline__ void dec8(uint4 pv, float* f) {
    float2 a = __half22float2(*reinterpret_cast<__half2*>(&pv.x));
    float2 b = __half22float2(*reinterpret_cast<__half2*>(&pv.y));
    float2 c = __half22float2(*reinterpret_cast<__half2*>(&pv.z));
    float2 d = __half22float2(*reinterpret_cast<__half2*>(&pv.w));
    f[0] = a.x; f[1] = a.y; f[2] = b.x; f[3] = b.y;
    f[4] = c.x; f[5] = c.y; f[6] = d.x; f[7] = d.y;
}

// ---------------- small kernels ----------------
__global__ void k_init() {
    int t = blockIdx.x * blockDim.x + threadIdx.x;
    if (t == 0) { g_max_cx = 0u; g_max_cy = 0u; g_max_c = 0u; }
    if (t < NN) g_w[t] = 1.0f;
}

__global__ void k_norm512(const float* __restrict__ XP, const float* __restrict__ XQ) {
    int i = blockIdx.x;
    const float* X = blockIdx.y ? XQ : XP;
    float4 v = reinterpret_cast<const float4*>(X)[(size_t)i * (DD / 4) + threadIdx.x];
    float s = v.x * v.x + v.y * v.y + v.z * v.z + v.w * v.w;
    s = blockReduceSum(s);
    if (threadIdx.x == 0) (blockIdx.y ? g_xq2 : g_xp2)[i] = s;
}

__global__ void k_norm10(const float* __restrict__ YP, const float* __restrict__ YQ) {
    int i = blockIdx.x * blockDim.x + threadIdx.x;
    if (i < NN) {
        float sp = 0.f, sq = 0.f;
#pragma unroll
        for (int c = 0; c < NCLS; c++) {
            float tp = YP[(size_t)i * NCLS + c];
            float tq = YQ[(size_t)i * NCLS + c];
            sp += tp * tp; sq += tq * tq;
        }
        g_yp2[i] = sp; g_yq2[i] = sq;
    }
}

// convert X to fp16 planes (rn)
__global__ void __launch_bounds__(256) k_split(const float* __restrict__ XP, const float* __restrict__ XQ) {
    const float4* src = reinterpret_cast<const float4*>(blockIdx.y ? XQ : XP);
    __half* Hh = blockIdx.y ? g_Bh : g_Ah;
    int n4 = NN * DD / 4;
    for (int i = blockIdx.x * 256 + threadIdx.x; i < n4; i += gridDim.x * 256) {
        float4 v = src[i];
        union { __half2 h[2]; uint2 u; } ph;
        ph.h[0] = __floats2half2_rn(v.x, v.y);
        ph.h[1] = __floats2half2_rn(v.z, v.w);
        reinterpret_cast<uint2*>(Hh)[i] = ph.u;
    }
}

// ---------------- single-pass FP16 mma.sync GEMM: CX tile + maxCX/maxCY ----------
#define ROWW 20                           // words per row (32 halves + pad)
#define PLANE_B (128 * ROWW * 4)          // bytes per plane: 10240
#define BUF_B (2 * PLANE_B)               // planes Ah, Bh: 20480
#define SMEM_GEMM (2 * BUF_B)             // 40960

__global__ void __launch_bounds__(256, 2)
k_gemm_mma(const float* __restrict__ YPg, const float* __restrict__ YQg) {
    extern __shared__ float sm[];
    const int tid = threadIdx.x;
    const int wid = tid >> 5, lane = tid & 31;
    const int warp_m = wid >> 2, warp_n = wid & 3;
    const int g = lane >> 2, t4 = lane & 3;
    const int row0 = blockIdx.y * 128;
    const int col0 = blockIdx.x * 128;

    const uint32_t smb = smem_u32(sm);

    float acc[4][4][4];
#pragma unroll
    for (int mt = 0; mt < 4; mt++)
#pragma unroll
        for (int nt = 0; nt < 4; nt++)
#pragma unroll
            for (int q = 0; q < 4; q++) acc[mt][nt][q] = 0.f;

    auto issue = [&](int ch, int buf) {
        const uint32_t base = smb + (uint32_t)buf * BUF_B;
#pragma unroll
        for (int q = 0; q < 4; q++) {
            int idx = tid + q * 256;          // 0..1023
            int plane = idx >> 9;             // 0=Ah,1=Bh
            int r = (idx >> 2) & 127;
            int c16 = idx & 3;
            uint32_t dst = base + (uint32_t)plane * PLANE_B + (uint32_t)(r * 80 + c16 * 16);
            const __half* gp = plane ? g_Bh : g_Ah;
            int rg = (plane ? col0 : row0) + r;
            const __half* src = gp + (size_t)rg * DD + ch * 32 + c16 * 8;
            CP_ASYNC16(dst, src);
        }
        CP_COMMIT();
    };

    issue(0, 0);
    for (int ch = 0; ch < 16; ch++) {
        const int buf = ch & 1;
        CP_WAIT0();
        __syncthreads();
        if (ch < 15) issue(ch + 1, buf ^ 1);
        const uint32_t* Ah = reinterpret_cast<const uint32_t*>(sm) + buf * (BUF_B / 4);
        const uint32_t* Bh = Ah + PLANE_B / 4;
#pragma unroll
        for (int kk = 0; kk < 2; kk++) {
            const int kbw = kk * 8;
            uint32_t ah[4][4];
#pragma unroll
            for (int mt = 0; mt < 4; mt++) {
                int base = (warp_m * 64 + mt * 16 + g) * ROWW + kbw + t4;
                ah[mt][0] = Ah[base];       ah[mt][1] = Ah[base + 8 * ROWW];
                ah[mt][2] = Ah[base + 4];   ah[mt][3] = Ah[base + 8 * ROWW + 4];
            }
            uint32_t bh[4][2];
#pragma unroll
            for (int nt = 0; nt < 4; nt++) {
                int base = (warp_n * 32 + nt * 8 + g) * ROWW + kbw + t4;
                bh[nt][0] = Bh[base];  bh[nt][1] = Bh[base + 4];
            }
#pragma unroll
            for (int mt = 0; mt < 4; mt++)
#pragma unroll
                for (int nt = 0; nt < 4; nt++)
                    mma_f16(acc[mt][nt], ah[mt], bh[nt]);
        }
        __syncthreads();
    }

    // ---- epilogue staging (reuse smem) ----
    if (tid < 128) {
        sm[tid]        = g_xq2[col0 + tid];
        sm[128 + tid]  = g_yq2[col0 + tid];
        sm[2816 + tid] = g_yp2[row0 + tid];
    }
    for (int i = tid; i < 128 * NCLS; i += 256) {
        sm[256 + i]  = YQg[(size_t)col0 * NCLS + i];
        sm[1536 + i] = YPg[(size_t)row0 * NCLS + i];
    }
    __syncthreads();

    float maxcx = 0.f;
#pragma unroll
    for (int mt = 0; mt < 4; mt++) {
        const int r1 = warp_m * 64 + mt * 16 + g;
        const int r2 = r1 + 8;
        const float xp2a = g_xp2[row0 + r1];
        const float xp2b = g_xp2[row0 + r2];
#pragma unroll
        for (int nt = 0; nt < 4; nt++) {
            const int n0 = warp_n * 32 + nt * 8 + 2 * t4;
            const float xq0 = sm[n0], xq1 = sm[n0 + 1];
            float c00 = fmaxf(xp2a + xq0 - 2.f * acc[mt][nt][0], 0.f);
            float c01 = fmaxf(xp2a + xq1 - 2.f * acc[mt][nt][1], 0.f);
            float c10 = fmaxf(xp2b + xq0 - 2.f * acc[mt][nt][2], 0.f);
            float c11 = fmaxf(xp2b + xq1 - 2.f * acc[mt][nt][3], 0.f);
            __half2 h0 = __floats2half2_rn(c00, c01);
            __half2 h1 = __floats2half2_rn(c10, c11);
            *reinterpret_cast<__half2*>(&g_Ch[(size_t)(row0 + r1) * NN + col0 + n0]) = h0;
            *reinterpret_cast<__half2*>(&g_Ch[(size_t)(row0 + r2) * NN + col0 + n0]) = h1;
            float2 q0 = __half22float2(h0);
            float2 q1 = __half22float2(h1);
            maxcx = fmaxf(maxcx, fmaxf(fmaxf(q0.x, q0.y), fmaxf(q1.x, q1.y)));
        }
    }
#pragma unroll
    for (int o = 16; o > 0; o >>= 1) maxcx = fmaxf(maxcx, __shfl_xor_sync(0xffffffffu, maxcx, o));
    if (lane == 0) atomicMax(&g_max_cx, __float_as_uint(maxcx));

    {
        const int r = tid & 127;
        const int j0 = (tid >> 7) * 64;
        float ypv[NCLS];
#pragma unroll
        for (int d = 0; d < NCLS; d++) ypv[d] = sm[1536 + r * NCLS + d];
        const float yp2r = sm[2816 + r];
        float mx = 0.f;
        for (int j = j0; j < j0 + 64; j++) {
            float dot = 0.f;
#pragma unroll
            for (int d = 0; d < NCLS; d++) dot = fmaf(ypv[d], sm[256 + j * NCLS + d], dot);
            float cy = fmaxf(yp2r + sm[128 + j] - 2.f * dot, 0.f);
            mx = fmaxf(mx, cy);
        }
#pragma unroll
        for (int o = 16; o > 0; o >>= 1) mx = fmaxf(mx, __shfl_xor_sync(0xffffffffu, mx, o));
        if (lane == 0) atomicMax(&g_max_cy, __float_as_uint(mx));
    }
}

// ---------------- max(C) over all elements (C = CX + lw*CY on the fly) ----------------
__global__ void __launch_bounds__(256) k_maxc(const float* __restrict__ YP, const float* __restrict__ YQ) {
    __shared__ float YPs[16][NCLS];
    __shared__ float yp2s[16];
    const int i0 = blockIdx.x * 16;
    const int tid = threadIdx.x;
    if (tid < 16 * NCLS) { int r = tid / NCLS, c = tid - r * NCLS; YPs[r][c] = YP[(size_t)(i0 + r) * NCLS + c]; }
    if (tid < 16) yp2s[tid] = g_yp2[i0 + tid];
    __syncthreads();
    float cxm = __uint_as_float(g_max_cx);
    float cym = __uint_as_float(g_max_cy);
    float lw = (cym == 0.f) ? 0.f : cxm / cym;
    float localmax = 0.f;
    for (int j0 = tid * 4; j0 < NN; j0 += 1024) {
        float yq[4][NCLS], yq2[4];
#pragma unroll
        for (int c = 0; c < 4; c++) {
#pragma unroll
            for (int d = 0; d < NCLS; d += 2) {
                float2 t = __ldg(reinterpret_cast<const float2*>(&YQ[(size_t)(j0 + c) * NCLS + d]));
                yq[c][d] = t.x; yq[c][d + 1] = t.y;
            }
            yq2[c] = g_yq2[j0 + c];
        }
#pragma unroll
        for (int r = 0; r < 16; r++) {
            uint2 cu = *reinterpret_cast<const uint2*>(&g_Ch[(size_t)(i0 + r) * NN + j0]);
            float cxa[4]; dec_c4(cu, cxa);
#pragma unroll
            for (int c = 0; c < 4; c++) {
                float dot = 0.f;
#pragma unroll
                for (int d = 0; d < NCLS; d++) dot = fmaf(YPs[r][d], yq[c][d], dot);
                float cy = fmaxf(yp2s[r] + yq2[c] - 2.f * dot, 0.f);
                localmax = fmaxf(localmax, cxa[c] + lw * cy);
            }
        }
    }
#pragma unroll
    for (int o = 16; o > 0; o >>= 1)
        localmax = fmaxf(localmax, __shfl_xor_sync(0xffffffffu, localmax, o));
    if ((tid & 31) == 0) atomicMax(&g_max_c, __float_as_uint(localmax));
}

// ---------------- P' = 2^SHIFT * exp(-C/(reg*cmax)) as fp16 ----------------
__global__ void __launch_bounds__(256) k_exp(const float* __restrict__ YP, const float* __restrict__ YQ) {
    __shared__ float YPs[16][NCLS];
    __shared__ float yp2s[16];
    const int i0 = blockIdx.x * 16;
    const int tid = threadIdx.x;
    if (tid < 16 * NCLS) { int r = tid / NCLS, c = tid - r * NCLS; YPs[r][c] = YP[(size_t)(i0 + r) * NCLS + c]; }
    if (tid < 16) yp2s[tid] = g_yp2[i0 + tid];
    __syncthreads();
    float cxm = __uint_as_float(g_max_cx);
    float cym = __uint_as_float(g_max_cy);
    float lw = (cym == 0.f) ? 0.f : cxm / cym;
    float cmax = __uint_as_float(g_max_c);
    float sc = 1.4426950408889634f / (REG_E * cmax);
    for (int j0 = tid * 4; j0 < NN; j0 += 1024) {
        float yq[4][NCLS], yq2[4];
#pragma unroll
        for (int c = 0; c < 4; c++) {
#pragma unroll
            for (int d = 0; d < NCLS; d += 2) {
                float2 t = __ldg(reinterpret_cast<const float2*>(&YQ[(size_t)(j0 + c) * NCLS + d]));
                yq[c][d] = t.x; yq[c][d + 1] = t.y;
            }
            yq2[c] = g_yq2[j0 + c];
        }
#pragma unroll
        for (int r = 0; r < 16; r++) {
            uint2 cu = *reinterpret_cast<const uint2*>(&g_Ch[(size_t)(i0 + r) * NN + j0]);
            float cxa[4]; dec_c4(cu, cxa);
            float pv[4];
#pragma unroll
            for (int c = 0; c < 4; c++) {
                float dot = 0.f;
#pragma unroll
                for (int d = 0; d < NCLS; d++) dot = fmaf(YPs[r][d], yq[c][d], dot);
                float cy = fmaxf(yp2s[r] + yq2[c] - 2.f * dot, 0.f);
                float v = cxa[c] + lw * cy;
                pv[c] = fexp2(fmaf(-v, sc, SHIFT));
            }
            union { __half2 h[2]; uint2 u; } pk;
            pk.h[0] = __floats2half2_rn(pv[0], pv[1]);
            pk.h[1] = __floats2half2_rn(pv[2], pv[3]);
            *reinterpret_cast<uint2*>(&g_Ph[(size_t)(i0 + r) * NN + j0]) = pk.u;
        }
    }
}

// ---------------- fused Sinkhorn iteration: one DRAM pass over P ----------------
// Grid 256 blocks x 512 threads. Block owns 32 rows, processed as 8 strips of 4 rows.
// Strip staged in SMEM (cp.async, double-buffered 2x64KB). Per strip:
//   pass 1: row sums (w in registers) -> z for these rows (written to g_z + smem)
//   pass 2: column partials += P^T z from the SAME smem strip.
// Column partials (16 floats/thread = 8192/block) written to g_part[block].
#define IT_ROWS 32
#define STRIP 4
#define NSTRIP 8
#define STRIP_U4 (STRIP * (NN / 8))       // 4096 uint4
#define STRIP_B (STRIP_U4 * 16)           // 65536 bytes
#define SMEM_IT (2 * STRIP_B + 512)

__global__ void __launch_bounds__(512, 1) k_iter() {
    extern __shared__ char smc[];
    uint4* bufs = reinterpret_cast<uint4*>(smc);
    float* zsm = reinterpret_cast<float*>(smc + 2 * STRIP_B);   // [4]
    float* red = zsm + 4;                                        // [64]
    const int tid = threadIdx.x;
    const int wid = tid >> 5, lane = tid & 31;
    const int r0 = blockIdx.x * IT_ROWS;
    const uint32_t smb = smem_u32(smc);

    // w for this thread's two column chunks (cols (k*512+tid)*8 .. +7) in registers
    float wreg[2][8];
#pragma unroll
    for (int k = 0; k < 2; k++) {
        const float* wp = &g_w[(k * 512 + tid) * 8];
        float4 a = *reinterpret_cast<const float4*>(wp);
        float4 b = *reinterpret_cast<const float4*>(wp + 4);
        wreg[k][0] = a.x; wreg[k][1] = a.y; wreg[k][2] = a.z; wreg[k][3] = a.w;
        wreg[k][4] = b.x; wreg[k][5] = b.y; wreg[k][6] = b.z; wreg[k][7] = b.w;
    }
    float colacc[2][8];
#pragma unroll
    for (int k = 0; k < 2; k++)
#pragma unroll
        for (int i = 0; i < 8; i++) colacc[k][i] = 0.f;

    auto issue = [&](int s, int b) {
        const __half* base = g_Ph + (size_t)(r0 + s * STRIP) * NN;
#pragma unroll
        for (int q = 0; q < 8; q++) {
            int idx = tid + q * 512;                // 0..4095
            int rr = idx >> 10, c8 = idx & 1023;
            uint32_t dst = smb + (uint32_t)b * STRIP_B + (uint32_t)idx * 16;
            const __half* src = base + (size_t)rr * NN + c8 * 8;
            CP_ASYNC16(dst, src);
        }
        CP_COMMIT();
    };

    issue(0, 0);
    for (int s = 0; s < NSTRIP; s++) {
        const int b = s & 1;
        CP_WAIT0();
        __syncthreads();
        if (s < NSTRIP - 1) issue(s + 1, b ^ 1);
        const uint4* st = bufs + b * STRIP_U4;

        // pass 1: row sums
        float rp[STRIP] = {0.f, 0.f, 0.f, 0.f};
#pragma unroll
        for (int r = 0; r < STRIP; r++)
#pragma unroll
            for (int k = 0; k < 2; k++) {
                uint4 pv = st[r * 1024 + k * 512 + tid];
                float f[8]; dec8(pv, f);
                float s0 = fmaf(f[0], wreg[k][0], f[1] * wreg[k][1]);
                s0 = fmaf(f[2], wreg[k][2], s0); s0 = fmaf(f[3], wreg[k][3], s0);
                float s1 = fmaf(f[4], wreg[k][4], f[5] * wreg[k][5]);
                s1 = fmaf(f[6], wreg[k][6], s1); s1 = fmaf(f[7], wreg[k][7], s1);
                rp[r] += s0 + s1;
            }
#pragma unroll
        for (int r = 0; r < STRIP; r++) {
            float v = rp[r];
#pragma unroll
            for (int o = 16; o > 0; o >>= 1) v += __shfl_down_sync(0xffffffffu, v, o);
            if (lane == 0) red[r * 16 + wid] = v;
        }
        __syncthreads();
        if (tid < STRIP) {
            float sum = 0.f;
#pragma unroll
            for (int w2 = 0; w2 < 16; w2++) sum += red[tid * 16 + w2];
            float z = (1.0f / NN) / sum;
            zsm[tid] = z;
            g_z[r0 + s * STRIP + tid] = z;
        }
        __syncthreads();

        // pass 2: column partials
#pragma unroll
        for (int r = 0; r < STRIP; r++) {
            float zz = zsm[r];
#pragma unroll
            for (int k = 0; k < 2; k++) {
                uint4 pv = st[r * 1024 + k * 512 + tid];
                float f[8]; dec8(pv, f);
#pragma unroll
                for (int i = 0; i < 8; i++) colacc[k][i] = fmaf(f[i], zz, colacc[k][i]);
            }
        }
        // buffer b is reused only after the top-of-loop __syncthreads two iterations later
    }

#pragma unroll
    for (int k = 0; k < 2; k++) {
        float* dst = &g_part[(size_t)blockIdx.x * NN + (size_t)(k * 512 + tid) * 8];
        *reinterpret_cast<float4*>(dst)     = make_float4(colacc[k][0], colacc[k][1], colacc[k][2], colacc[k][3]);
        *reinterpret_cast<float4*>(dst + 4) = make_float4(colacc[k][4], colacc[k][5], colacc[k][6], colacc[k][7]);
    }
}

// w = (1/M) / colsum over 256 block partials -- chunk-ordered, deterministic
__global__ void __launch_bounds__(256) k_colred() {
    int j = blockIdx.x * 256 + threadIdx.x;   // column 0..8191
    float s = 0.f;
#pragma unroll 4
    for (int ch = 0; ch < 256; ch++) s += g_part[(size_t)ch * NN + j];
    g_w[j] = (1.0f / NN) / s;
}

// ---------------- final objective ----------------
__global__ void __launch_bounds__(256) k_final(const float* __restrict__ YP, const float* __restrict__ YQ) {
    __shared__ float YPs[16][NCLS];
    __shared__ float yp2s[16];
    __shared__ float zs[16];
    const int i0 = blockIdx.x * 16;
    const int tid = threadIdx.x;
    if (tid < 16 * NCLS) { int r = tid / NCLS, c = tid - r * NCLS; YPs[r][c] = YP[(size_t)(i0 + r) * NCLS + c]; }
    if (tid < 16) { yp2s[tid] = g_yp2[i0 + tid]; zs[tid] = g_z[i0 + tid] * SHIFT_MUL; }
    __syncthreads();
    float cxm = __uint_as_float(g_max_cx);
    float cym = __uint_as_float(g_max_cy);
    float lw = (cym == 0.f) ? 0.f : cxm / cym;
    float cmax = __uint_as_float(g_max_c);
    float sc = 1.4426950408889634f / (REG_E * cmax);
    float acc = 0.f;
    for (int j0 = tid * 4; j0 < NN; j0 += 1024) {
        float yq[4][NCLS], yq2[4];
#pragma unroll
        for (int c = 0; c < 4; c++) {
#pragma unroll
            for (int d = 0; d < NCLS; d += 2) {
                float2 t = __ldg(reinterpret_cast<const float2*>(&YQ[(size_t)(j0 + c) * NCLS + d]));
                yq[c][d] = t.x; yq[c][d + 1] = t.y;
            }
            yq2[c] = g_yq2[j0 + c];
        }
        float4 wv = *reinterpret_cast<const float4*>(&g_w[j0]);
        float wa[4] = {wv.x, wv.y, wv.z, wv.w};
#pragma unroll
        for (int r = 0; r < 16; r++) {
            uint2 cu = *reinterpret_cast<const uint2*>(&g_Ch[(size_t)(i0 + r) * NN + j0]);
            float cxa[4]; dec_c4(cu, cxa);
            float zi = zs[r];
#pragma unroll
            for (int c = 0; c < 4; c++) {
                float dot = 0.f;
#pragma unroll
                for (int d = 0; d < NCLS; d++) dot = fmaf(YPs[r][d], yq[c][d], dot);
                float cy = fmaxf(yp2s[r] + yq2[c] - 2.f * dot, 0.f);
                float v = cxa[c] + lw * cy;
                float p = fexp2(-v * sc);
                acc = fmaf(v * p, zi * wa[c], acc);
            }
        }
    }
    acc = blockReduceSum(acc);
    if (tid == 0) g_bpart[blockIdx.x] = acc;
}

__global__ void __launch_bounds__(256) k_finalred(float* out) {
    double s = 0.0;
    for (int t = threadIdx.x; t < 512; t += 256) s += (double)g_bpart[t];
    s = blockReduceSumD(s);
    if (threadIdx.x == 0) out[0] = (float)s;
}

// ---------------- launch ----------------
extern "C" void kernel_launch(void* const* d_in, const int* in_sizes, int n_in,
                              void* d_out, int out_size) {
    const float* XQ = (const float*)d_in[0];   // (8192, 512)
    const float* YQ = (const float*)d_in[1];   // (8192, 10)
    const float* XP = (const float*)d_in[2];   // (8192, 512)
    const float* YP = (const float*)d_in[3];   // (8192, 10)
    float* out = (float*)d_out;

    cudaFuncSetAttribute(k_gemm_mma, cudaFuncAttributeMaxDynamicSharedMemorySize, SMEM_GEMM);
    cudaFuncSetAttribute(k_iter, cudaFuncAttributeMaxDynamicSharedMemorySize, SMEM_IT);

    k_init<<<32, 256>>>();
    k_norm512<<<dim3(NN, 2), 128>>>(XP, XQ);
    k_norm10<<<32, 256>>>(YP, YQ);
    k_split<<<dim3(512, 2), 256>>>(XP, XQ);

    k_gemm_mma<<<dim3(64, 64), 256, SMEM_GEMM>>>(YP, YQ);
    k_maxc<<<NN / 16, 256>>>(YP, YQ);
    k_exp<<<NN / 16, 256>>>(YP, YQ);

    for (int it = 0; it < NIT; it++) {
        k_iter<<<256, 512, SMEM_IT>>>();
        k_colred<<<32, 256>>>();
    }

    k_final<<<NN / 16, 256>>>(YP, YQ);
    k_finalred<<<1, 256>>>(out);
}

// round 13
// speedup vs baseline: 2.4784x; 1.0171x over previous
#include <cuda_runtime.h>
#include <cuda_fp16.h>
#include <cstdint>

// Problem constants
#define NN   8192
#define DD   512
#define NCLS 10
#define REG_E 0.05f
#define NIT  20
#define SHIFT 15.0f          // exp2 shift for fp16 P storage
#define SHIFT_MUL 32768.0f   // 2^15

static constexpr size_t NN2 = (size_t)NN * (size_t)NN;

// ---------------- scratch (device globals; no allocation) ----------------
static __device__ __half g_Ch[NN2];           // 128 MiB: CX (fp16)
static __device__ __half g_Ph[NN2];           // 128 MiB: P' = 2^15 * exp(-C/(reg*cmax))
static __device__ __half g_Ah[NN * DD];       // XP fp16
static __device__ __half g_Bh[NN * DD];       // XQ fp16
static __device__ float g_xp2[NN], g_xq2[NN], g_yp2[NN], g_yq2[NN];
static __device__ float g_z[NN], g_w[NN];
static __device__ float g_part[256 * NN];     // column partials (8 MB)
static __device__ float g_bpart[512];         // final reduction partials
static __device__ unsigned g_max_cx, g_max_cy, g_max_c;

// ---------------- generic helpers ----------------
__device__ __forceinline__ float blockReduceSum(float v) {
    __shared__ float red[32];
    unsigned lane = threadIdx.x & 31u, wid = threadIdx.x >> 5;
#pragma unroll
    for (int o = 16; o > 0; o >>= 1) v += __shfl_down_sync(0xffffffffu, v, o);
    if (lane == 0) red[wid] = v;
    __syncthreads();
    int nw = (blockDim.x + 31) >> 5;
    v = (threadIdx.x < (unsigned)nw) ? red[threadIdx.x] : 0.f;
    if (wid == 0) {
#pragma unroll
        for (int o = 16; o > 0; o >>= 1) v += __shfl_down_sync(0xffffffffu, v, o);
    }
    return v;  // valid in thread 0
}

__device__ __forceinline__ double blockReduceSumD(double v) {
    __shared__ double redd[32];
    unsigned lane = threadIdx.x & 31u, wid = threadIdx.x >> 5;
#pragma unroll
    for (int o = 16; o > 0; o >>= 1) v += __shfl_down_sync(0xffffffffu, v, o);
    if (lane == 0) redd[wid] = v;
    __syncthreads();
    int nw = (blockDim.x + 31) >> 5;
    v = (threadIdx.x < (unsigned)nw) ? redd[threadIdx.x] : 0.0;
    if (wid == 0) {
#pragma unroll
        for (int o = 16; o > 0; o >>= 1) v += __shfl_down_sync(0xffffffffu, v, o);
    }
    return v;
}

// fast exp2 for y in [-30, 16]; FMA-only (no MUFU). rel err ~1e-7.
__device__ __forceinline__ float fexp2(float y) {
    float fk = y + 12582912.0f;
    int   k  = __float_as_int(fk) - 0x4B400000;
    float r  = y - (fk - 12582912.0f);
    float p  = 1.5403530e-4f;
    p = fmaf(p, r, 1.3333558e-3f);
    p = fmaf(p, r, 9.6181291e-3f);
    p = fmaf(p, r, 5.5504109e-2f);
    p = fmaf(p, r, 2.4022651e-1f);
    p = fmaf(p, r, 6.9314718e-1f);
    p = fmaf(p, r, 1.0f);
    return p * __int_as_float((k + 127) << 23);
}

// ---------------- mma / cp.async helpers (sm_80+ PTX, works on plain sm_100) ----
__device__ __forceinline__ void mma_f16(float* d, const uint32_t* a, const uint32_t* b) {
    asm volatile(
        "mma.sync.aligned.m16n8k16.row.col.f32.f16.f16.f32 "
        "{%0,%1,%2,%3}, {%4,%5,%6,%7}, {%8,%9}, {%0,%1,%2,%3};"
        : "+f"(d[0]), "+f"(d[1]), "+f"(d[2]), "+f"(d[3])
        : "r"(a[0]), "r"(a[1]), "r"(a[2]), "r"(a[3]), "r"(b[0]), "r"(b[1]));
}
__device__ __forceinline__ uint32_t smem_u32(const void* p) {
    uint32_t a;
    asm("{ .reg .u64 t; cvta.to.shared.u64 t, %1; cvt.u32.u64 %0, t; }" : "=r"(a) : "l"(p));
    return a;
}
#define CP_ASYNC16(dst, src) \
    asm volatile("cp.async.cg.shared.global [%0], [%1], 16;" :: "r"(dst), "l"(src) : "memory")
#define CP_COMMIT() asm volatile("cp.async.commit_group;" ::: "memory")
#define CP_WAIT0()  asm volatile("cp.async.wait_group 0;" ::: "memory")

// fp16 C decode: 4 cols from a uint2
__device__ __forceinline__ void dec_c4(uint2 cu, float* c) {
    float2 a = __half22float2(*reinterpret_cast<__half2*>(&cu.x));
    float2 b = __half22float2(*reinterpret_cast<__half2*>(&cu.y));
    c[0] = a.x; c[1] = a.y; c[2] = b.x; c[3] = b.y;
}
// 8 halves from uint4
__device__ __forceinline__ void dec8(uint4 pv, float* f) {
    float2 a = __half22float2(*reinterpret_cast<__half2*>(&pv.x));
    float2 b = __half22float2(*reinterpret_cast<__half2*>(&pv.y));
    float2 c = __half22float2(*reinterpret_cast<__half2*>(&pv.z));
    float2 d = __half22float2(*reinterpret_cast<__half2*>(&pv.w));
    f[0] = a.x; f[1] = a.y; f[2] = b.x; f[3] = b.y;
    f[4] = c.x; f[5] = c.y; f[6] = d.x; f[7] = d.y;
}

// ---------------- small kernels ----------------
__global__ void k_init() {
    int t = blockIdx.x * blockDim.x + threadIdx.x;
    if (t == 0) { g_max_cx = 0u; g_max_cy = 0u; g_max_c = 0u; }
    if (t < NN) g_w[t] = 1.0f;
}

__global__ void k_norm512(const float* __restrict__ XP, const float* __restrict__ XQ) {
    int i = blockIdx.x;
    const float* X = blockIdx.y ? XQ : XP;
    float4 v = reinterpret_cast<const float4*>(X)[(size_t)i * (DD / 4) + threadIdx.x];
    float s = v.x * v.x + v.y * v.y + v.z * v.z + v.w * v.w;
    s = blockReduceSum(s);
    if (threadIdx.x == 0) (blockIdx.y ? g_xq2 : g_xp2)[i] = s;
}

__global__ void k_norm10(const float* __restrict__ YP, const float* __restrict__ YQ) {
    int i = blockIdx.x * blockDim.x + threadIdx.x;
    if (i < NN) {
        float sp = 0.f, sq = 0.f;
#pragma unroll
        for (int c = 0; c < NCLS; c++) {
            float tp = YP[(size_t)i * NCLS + c];
            float tq = YQ[(size_t)i * NCLS + c];
            sp += tp * tp; sq += tq * tq;
        }
        g_yp2[i] = sp; g_yq2[i] = sq;
    }
}

// convert X to fp16 planes (rn)
__global__ void __launch_bounds__(256) k_split(const float* __restrict__ XP, const float* __restrict__ XQ) {
    const float4* src = reinterpret_cast<const float4*>(blockIdx.y ? XQ : XP);
    __half* Hh = blockIdx.y ? g_Bh : g_Ah;
    int n4 = NN * DD / 4;
    for (int i = blockIdx.x * 256 + threadIdx.x; i < n4; i += gridDim.x * 256) {
        float4 v = src[i];
        union { __half2 h[2]; uint2 u; } ph;
        ph.h[0] = __floats2half2_rn(v.x, v.y);
        ph.h[1] = __floats2half2_rn(v.z, v.w);
        reinterpret_cast<uint2*>(Hh)[i] = ph.u;
    }
}

// ---------------- single-pass FP16 mma.sync GEMM: CX tile + maxCX/maxCY ----------
#define ROWW 20                           // words per row (32 halves + pad)
#define PLANE_B (128 * ROWW * 4)          // bytes per plane: 10240
#define BUF_B (2 * PLANE_B)               // planes Ah, Bh: 20480
#define SMEM_GEMM (2 * BUF_B)             // 40960

__global__ void __launch_bounds__(256, 2)
k_gemm_mma(const float* __restrict__ YPg, const float* __restrict__ YQg) {
    extern __shared__ float sm[];
    const int tid = threadIdx.x;
    const int wid = tid >> 5, lane = tid & 31;
    const int warp_m = wid >> 2, warp_n = wid & 3;
    const int g = lane >> 2, t4 = lane & 3;
    const int row0 = blockIdx.y * 128;
    const int col0 = blockIdx.x * 128;

    const uint32_t smb = smem_u32(sm);

    float acc[4][4][4];
#pragma unroll
    for (int mt = 0; mt < 4; mt++)
#pragma unroll
        for (int nt = 0; nt < 4; nt++)
#pragma unroll
            for (int q = 0; q < 4; q++) acc[mt][nt][q] = 0.f;

    auto issue = [&](int ch, int buf) {
        const uint32_t base = smb + (uint32_t)buf * BUF_B;
#pragma unroll
        for (int q = 0; q < 4; q++) {
            int idx = tid + q * 256;          // 0..1023
            int plane = idx >> 9;             // 0=Ah,1=Bh
            int r = (idx >> 2) & 127;
            int c16 = idx & 3;
            uint32_t dst = base + (uint32_t)plane * PLANE_B + (uint32_t)(r * 80 + c16 * 16);
            const __half* gp = plane ? g_Bh : g_Ah;
            int rg = (plane ? col0 : row0) + r;
            const __half* src = gp + (size_t)rg * DD + ch * 32 + c16 * 8;
            CP_ASYNC16(dst, src);
        }
        CP_COMMIT();
    };

    issue(0, 0);
    for (int ch = 0; ch < 16; ch++) {
        const int buf = ch & 1;
        CP_WAIT0();
        __syncthreads();
        if (ch < 15) issue(ch + 1, buf ^ 1);
        const uint32_t* Ah = reinterpret_cast<const uint32_t*>(sm) + buf * (BUF_B / 4);
        const uint32_t* Bh = Ah + PLANE_B / 4;
#pragma unroll
        for (int kk = 0; kk < 2; kk++) {
            const int kbw = kk * 8;
            uint32_t ah[4][4];
#pragma unroll
            for (int mt = 0; mt < 4; mt++) {
                int base = (warp_m * 64 + mt * 16 + g) * ROWW + kbw + t4;
                ah[mt][0] = Ah[base];       ah[mt][1] = Ah[base + 8 * ROWW];
                ah[mt][2] = Ah[base + 4];   ah[mt][3] = Ah[base + 8 * ROWW + 4];
            }
            uint32_t bh[4][2];
#pragma unroll
            for (int nt = 0; nt < 4; nt++) {
                int base = (warp_n * 32 + nt * 8 + g) * ROWW + kbw + t4;
                bh[nt][0] = Bh[base];  bh[nt][1] = Bh[base + 4];
            }
#pragma unroll
            for (int mt = 0; mt < 4; mt++)
#pragma unroll
                for (int nt = 0; nt < 4; nt++)
                    mma_f16(acc[mt][nt], ah[mt], bh[nt]);
        }
        __syncthreads();
    }

    // ---- epilogue staging (reuse smem) ----
    if (tid < 128) {
        sm[tid]        = g_xq2[col0 + tid];
        sm[128 + tid]  = g_yq2[col0 + tid];
        sm[2816 + tid] = g_yp2[row0 + tid];
    }
    for (int i = tid; i < 128 * NCLS; i += 256) {
        sm[256 + i]  = YQg[(size_t)col0 * NCLS + i];
        sm[1536 + i] = YPg[(size_t)row0 * NCLS + i];
    }
    __syncthreads();

    float maxcx = 0.f;
#pragma unroll
    for (int mt = 0; mt < 4; mt++) {
        const int r1 = warp_m * 64 + mt * 16 + g;
        const int r2 = r1 + 8;
        const float xp2a = g_xp2[row0 + r1];
        const float xp2b = g_xp2[row0 + r2];
#pragma unroll
        for (int nt = 0; nt < 4; nt++) {
            const int n0 = warp_n * 32 + nt * 8 + 2 * t4;
            const float xq0 = sm[n0], xq1 = sm[n0 + 1];
            float c00 = fmaxf(xp2a + xq0 - 2.f * acc[mt][nt][0], 0.f);
            float c01 = fmaxf(xp2a + xq1 - 2.f * acc[mt][nt][1], 0.f);
            float c10 = fmaxf(xp2b + xq0 - 2.f * acc[mt][nt][2], 0.f);
            float c11 = fmaxf(xp2b + xq1 - 2.f * acc[mt][nt][3], 0.f);
            __half2 h0 = __floats2half2_rn(c00, c01);
            __half2 h1 = __floats2half2_rn(c10, c11);
            *reinterpret_cast<__half2*>(&g_Ch[(size_t)(row0 + r1) * NN + col0 + n0]) = h0;
            *reinterpret_cast<__half2*>(&g_Ch[(size_t)(row0 + r2) * NN + col0 + n0]) = h1;
            float2 q0 = __half22float2(h0);
            float2 q1 = __half22float2(h1);
            maxcx = fmaxf(maxcx, fmaxf(fmaxf(q0.x, q0.y), fmaxf(q1.x, q1.y)));
        }
    }
#pragma unroll
    for (int o = 16; o > 0; o >>= 1) maxcx = fmaxf(maxcx, __shfl_xor_sync(0xffffffffu, maxcx, o));
    if (lane == 0) atomicMax(&g_max_cx, __float_as_uint(maxcx));

    {
        const int r = tid & 127;
        const int j0 = (tid >> 7) * 64;
        float ypv[NCLS];
#pragma unroll
        for (int d = 0; d < NCLS; d++) ypv[d] = sm[1536 + r * NCLS + d];
        const float yp2r = sm[2816 + r];
        float mx = 0.f;
        for (int j = j0; j < j0 + 64; j++) {
            float dot = 0.f;
#pragma unroll
            for (int d = 0; d < NCLS; d++) dot = fmaf(ypv[d], sm[256 + j * NCLS + d], dot);
            float cy = fmaxf(yp2r + sm[128 + j] - 2.f * dot, 0.f);
            mx = fmaxf(mx, cy);
        }
#pragma unroll
        for (int o = 16; o > 0; o >>= 1) mx = fmaxf(mx, __shfl_xor_sync(0xffffffffu, mx, o));
        if (lane == 0) atomicMax(&g_max_cy, __float_as_uint(mx));
    }
}

// ---------------- max(C) over all elements (C = CX + lw*CY on the fly) ----------------
__global__ void __launch_bounds__(256) k_maxc(const float* __restrict__ YP, const float* __restrict__ YQ) {
    __shared__ float YPs[16][NCLS];
    __shared__ float yp2s[16];
    const int i0 = blockIdx.x * 16;
    const int tid = threadIdx.x;
    if (tid < 16 * NCLS) { int r = tid / NCLS, c = tid - r * NCLS; YPs[r][c] = YP[(size_t)(i0 + r) * NCLS + c]; }
    if (tid < 16) yp2s[tid] = g_yp2[i0 + tid];
    __syncthreads();
    float cxm = __uint_as_float(g_max_cx);
    float cym = __uint_as_float(g_max_cy);
    float lw = (cym == 0.f) ? 0.f : cxm / cym;
    float localmax = 0.f;
    for (int j0 = tid * 4; j0 < NN; j0 += 1024) {
        float yq[4][NCLS], yq2[4];
#pragma unroll
        for (int c = 0; c < 4; c++) {
#pragma unroll
            for (int d = 0; d < NCLS; d += 2) {
                float2 t = __ldg(reinterpret_cast<const float2*>(&YQ[(size_t)(j0 + c) * NCLS + d]));
                yq[c][d] = t.x; yq[c][d + 1] = t.y;
            }
            yq2[c] = g_yq2[j0 + c];
        }
#pragma unroll
        for (int r = 0; r < 16; r++) {
            uint2 cu = *reinterpret_cast<const uint2*>(&g_Ch[(size_t)(i0 + r) * NN + j0]);
            float cxa[4]; dec_c4(cu, cxa);
#pragma unroll
            for (int c = 0; c < 4; c++) {
                float dot = 0.f;
#pragma unroll
                for (int d = 0; d < NCLS; d++) dot = fmaf(YPs[r][d], yq[c][d], dot);
                float cy = fmaxf(yp2s[r] + yq2[c] - 2.f * dot, 0.f);
                localmax = fmaxf(localmax, cxa[c] + lw * cy);
            }
        }
    }
#pragma unroll
    for (int o = 16; o > 0; o >>= 1)
        localmax = fmaxf(localmax, __shfl_xor_sync(0xffffffffu, localmax, o));
    if ((tid & 31) == 0) atomicMax(&g_max_c, __float_as_uint(localmax));
}

// ---------------- P' = 2^SHIFT * exp(-C/(reg*cmax)) as fp16 ----------------
__global__ void __launch_bounds__(256) k_exp(const float* __restrict__ YP, const float* __restrict__ YQ) {
    __shared__ float YPs[16][NCLS];
    __shared__ float yp2s[16];
    const int i0 = blockIdx.x * 16;
    const int tid = threadIdx.x;
    if (tid < 16 * NCLS) { int r = tid / NCLS, c = tid - r * NCLS; YPs[r][c] = YP[(size_t)(i0 + r) * NCLS + c]; }
    if (tid < 16) yp2s[tid] = g_yp2[i0 + tid];
    __syncthreads();
    float cxm = __uint_as_float(g_max_cx);
    float cym = __uint_as_float(g_max_cy);
    float lw = (cym == 0.f) ? 0.f : cxm / cym;
    float cmax = __uint_as_float(g_max_c);
    float sc = 1.4426950408889634f / (REG_E * cmax);
    for (int j0 = tid * 4; j0 < NN; j0 += 1024) {
        float yq[4][NCLS], yq2[4];
#pragma unroll
        for (int c = 0; c < 4; c++) {
#pragma unroll
            for (int d = 0; d < NCLS; d += 2) {
                float2 t = __ldg(reinterpret_cast<const float2*>(&YQ[(size_t)(j0 + c) * NCLS + d]));
                yq[c][d] = t.x; yq[c][d + 1] = t.y;
            }
            yq2[c] = g_yq2[j0 + c];
        }
#pragma unroll
        for (int r = 0; r < 16; r++) {
            uint2 cu = *reinterpret_cast<const uint2*>(&g_Ch[(size_t)(i0 + r) * NN + j0]);
            float cxa[4]; dec_c4(cu, cxa);
            float pv[4];
#pragma unroll
            for (int c = 0; c < 4; c++) {
                float dot = 0.f;
#pragma unroll
                for (int d = 0; d < NCLS; d++) dot = fmaf(YPs[r][d], yq[c][d], dot);
                float cy = fmaxf(yp2s[r] + yq2[c] - 2.f * dot, 0.f);
                float v = cxa[c] + lw * cy;
                pv[c] = fexp2(fmaf(-v, sc, SHIFT));
            }
            union { __half2 h[2]; uint2 u; } pk;
            pk.h[0] = __floats2half2_rn(pv[0], pv[1]);
            pk.h[1] = __floats2half2_rn(pv[2], pv[3]);
            *reinterpret_cast<uint2*>(&g_Ph[(size_t)(i0 + r) * NN + j0]) = pk.u;
        }
    }
}

// ---------------- fused Sinkhorn iteration: one DRAM pass over P ----------------
// Grid 256 blocks x 512 threads, 2 blocks/SM (one full wave on 148 SMs).
// Block owns 32 rows, processed as 16 strips of 2 rows.
// Strip staged in SMEM (cp.async, double-buffered 2x32KB). Per strip:
//   pass 1: row sums (w in registers) -> z for these rows (written to g_z + smem)
//   pass 2: column partials += P^T z from the SAME smem strip.
#define IT_ROWS 32
#define STRIP 2
#define NSTRIP 16
#define STRIP_U4 (STRIP * (NN / 8))       // 2048 uint4
#define STRIP_B (STRIP_U4 * 16)           // 32768 bytes
#define SMEM_IT (2 * STRIP_B + 512)       // 66048

__global__ void __launch_bounds__(512, 2) k_iter() {
    extern __shared__ char smc[];
    uint4* bufs = reinterpret_cast<uint4*>(smc);
    float* zsm = reinterpret_cast<float*>(smc + 2 * STRIP_B);   // [2]
    float* red = zsm + 4;                                        // [32]
    const int tid = threadIdx.x;
    const int wid = tid >> 5, lane = tid & 31;
    const int r0 = blockIdx.x * IT_ROWS;
    const uint32_t smb = smem_u32(smc);

    // w for this thread's two column chunks (cols (k*512+tid)*8 .. +7) in registers
    float wreg[2][8];
#pragma unroll
    for (int k = 0; k < 2; k++) {
        const float* wp = &g_w[(k * 512 + tid) * 8];
        float4 a = *reinterpret_cast<const float4*>(wp);
        float4 b = *reinterpret_cast<const float4*>(wp + 4);
        wreg[k][0] = a.x; wreg[k][1] = a.y; wreg[k][2] = a.z; wreg[k][3] = a.w;
        wreg[k][4] = b.x; wreg[k][5] = b.y; wreg[k][6] = b.z; wreg[k][7] = b.w;
    }
    float colacc[2][8];
#pragma unroll
    for (int k = 0; k < 2; k++)
#pragma unroll
        for (int i = 0; i < 8; i++) colacc[k][i] = 0.f;

    auto issue = [&](int s, int b) {
        const __half* base = g_Ph + (size_t)(r0 + s * STRIP) * NN;
#pragma unroll
        for (int q = 0; q < 4; q++) {
            int idx = tid + q * 512;                // 0..2047
            int rr = idx >> 10, c8 = idx & 1023;
            uint32_t dst = smb + (uint32_t)b * STRIP_B + (uint32_t)idx * 16;
            const __half* src = base + (size_t)rr * NN + c8 * 8;
            CP_ASYNC16(dst, src);
        }
        CP_COMMIT();
    };

    issue(0, 0);
    for (int s = 0; s < NSTRIP; s++) {
        const int b = s & 1;
        CP_WAIT0();
        __syncthreads();
        if (s < NSTRIP - 1) issue(s + 1, b ^ 1);
        const uint4* st = bufs + b * STRIP_U4;

        // pass 1: row sums
        float rp[STRIP] = {0.f, 0.f};
#pragma unroll
        for (int r = 0; r < STRIP; r++)
#pragma unroll
            for (int k = 0; k < 2; k++) {
                uint4 pv = st[r * 1024 + k * 512 + tid];
                float f[8]; dec8(pv, f);
                float s0 = fmaf(f[0], wreg[k][0], f[1] * wreg[k][1]);
                s0 = fmaf(f[2], wreg[k][2], s0); s0 = fmaf(f[3], wreg[k][3], s0);
                float s1 = fmaf(f[4], wreg[k][4], f[5] * wreg[k][5]);
                s1 = fmaf(f[6], wreg[k][6], s1); s1 = fmaf(f[7], wreg[k][7], s1);
                rp[r] += s0 + s1;
            }
#pragma unroll
        for (int r = 0; r < STRIP; r++) {
            float v = rp[r];
#pragma unroll
            for (int o = 16; o > 0; o >>= 1) v += __shfl_down_sync(0xffffffffu, v, o);
            if (lane == 0) red[r * 16 + wid] = v;
        }
        __syncthreads();
        if (tid < STRIP) {
            float sum = 0.f;
#pragma unroll
            for (int w2 = 0; w2 < 16; w2++) sum += red[tid * 16 + w2];
            float z = (1.0f / NN) / sum;
            zsm[tid] = z;
            g_z[r0 + s * STRIP + tid] = z;
        }
        __syncthreads();

        // pass 2: column partials
#pragma unroll
        for (int r = 0; r < STRIP; r++) {
            float zz = zsm[r];
#pragma unroll
            for (int k = 0; k < 2; k++) {
                uint4 pv = st[r * 1024 + k * 512 + tid];
                float f[8]; dec8(pv, f);
#pragma unroll
                for (int i = 0; i < 8; i++) colacc[k][i] = fmaf(f[i], zz, colacc[k][i]);
            }
        }
    }

#pragma unroll
    for (int k = 0; k < 2; k++) {
        float* dst = &g_part[(size_t)blockIdx.x * NN + (size_t)(k * 512 + tid) * 8];
        *reinterpret_cast<float4*>(dst)     = make_float4(colacc[k][0], colacc[k][1], colacc[k][2], colacc[k][3]);
        *reinterpret_cast<float4*>(dst + 4) = make_float4(colacc[k][4], colacc[k][5], colacc[k][6], colacc[k][7]);
    }
}

// w = (1/M) / colsum over 256 block partials -- chunk-ordered, deterministic
__global__ void __launch_bounds__(256) k_colred() {
    int j = blockIdx.x * 256 + threadIdx.x;   // column 0..8191
    float s = 0.f;
#pragma unroll 4
    for (int ch = 0; ch < 256; ch++) s += g_part[(size_t)ch * NN + j];
    g_w[j] = (1.0f / NN) / s;
}

// ---------------- final objective ----------------
__global__ void __launch_bounds__(256) k_final(const float* __restrict__ YP, const float* __restrict__ YQ) {
    __shared__ float YPs[16][NCLS];
    __shared__ float yp2s[16];
    __shared__ float zs[16];
    const int i0 = blockIdx.x * 16;
    const int tid = threadIdx.x;
    if (tid < 16 * NCLS) { int r = tid / NCLS, c = tid - r * NCLS; YPs[r][c] = YP[(size_t)(i0 + r) * NCLS + c]; }
    if (tid < 16) { yp2s[tid] = g_yp2[i0 + tid]; zs[tid] = g_z[i0 + tid] * SHIFT_MUL; }
    __syncthreads();
    float cxm = __uint_as_float(g_max_cx);
    float cym = __uint_as_float(g_max_cy);
    float lw = (cym == 0.f) ? 0.f : cxm / cym;
    float cmax = __uint_as_float(g_max_c);
    float sc = 1.4426950408889634f / (REG_E * cmax);
    float acc = 0.f;
    for (int j0 = tid * 4; j0 < NN; j0 += 1024) {
        float yq[4][NCLS], yq2[4];
#pragma unroll
        for (int c = 0; c < 4; c++) {
#pragma unroll
            for (int d = 0; d < NCLS; d += 2) {
                float2 t = __ldg(reinterpret_cast<const float2*>(&YQ[(size_t)(j0 + c) * NCLS + d]));
                yq[c][d] = t.x; yq[c][d + 1] = t.y;
            }
            yq2[c] = g_yq2[j0 + c];
        }
        float4 wv = *reinterpret_cast<const float4*>(&g_w[j0]);
        float wa[4] = {wv.x, wv.y, wv.z, wv.w};
#pragma unroll
        for (int r = 0; r < 16; r++) {
            uint2 cu = *reinterpret_cast<const uint2*>(&g_Ch[(size_t)(i0 + r) * NN + j0]);
            float cxa[4]; dec_c4(cu, cxa);
            float zi = zs[r];
#pragma unroll
            for (int c = 0; c < 4; c++) {
                float dot = 0.f;
#pragma unroll
                for (int d = 0; d < NCLS; d++) dot = fmaf(YPs[r][d], yq[c][d], dot);
                float cy = fmaxf(yp2s[r] + yq2[c] - 2.f * dot, 0.f);
                float v = cxa[c] + lw * cy;
                float p = fexp2(-v * sc);
                acc = fmaf(v * p, zi * wa[c], acc);
            }
        }
    }
    acc = blockReduceSum(acc);
    if (tid == 0) g_bpart[blockIdx.x] = acc;
}

__global__ void __launch_bounds__(256) k_finalred(float* out) {
    double s = 0.0;
    for (int t = threadIdx.x; t < 512; t += 256) s += (double)g_bpart[t];
    s = blockReduceSumD(s);
    if (threadIdx.x == 0) out[0] = (float)s;
}

// ---------------- launch ----------------
extern "C" void kernel_launch(void* const* d_in, const int* in_sizes, int n_in,
                              void* d_out, int out_size) {
    const float* XQ = (const float*)d_in[0];   // (8192, 512)
    const float* YQ = (const float*)d_in[1];   // (8192, 10)
    const float* XP = (const float*)d_in[2];   // (8192, 512)
    const float* YP = (const float*)d_in[3];   // (8192, 10)
    float* out = (float*)d_out;

    cudaFuncSetAttribute(k_gemm_mma, cudaFuncAttributeMaxDynamicSharedMemorySize, SMEM_GEMM);
    cudaFuncSetAttribute(k_iter, cudaFuncAttributeMaxDynamicSharedMemorySize, SMEM_IT);

    k_init<<<32, 256>>>();
    k_norm512<<<dim3(NN, 2), 128>>>(XP, XQ);
    k_norm10<<<32, 256>>>(YP, YQ);
    k_split<<<dim3(512, 2), 256>>>(XP, XQ);

    k_gemm_mma<<<dim3(64, 64), 256, SMEM_GEMM>>>(YP, YQ);
    k_maxc<<<NN / 16, 256>>>(YP, YQ);
    k_exp<<<NN / 16, 256>>>(YP, YQ);

    for (int it = 0; it < NIT; it++) {
        k_iter<<<256, 512, SMEM_IT>>>();
        k_colred<<<32, 256>>>();
    }

    k_final<<<NN / 16, 256>>>(YP, YQ);
    k_finalred<<<1, 256>>>(out);
}